// round 1
// baseline (speedup 1.0000x reference)
#include <cuda_runtime.h>
#include <cuda_bf16.h>
#include <math.h>

// ---------------- problem constants ----------------
#define BATCH 4
#define TLEN  512
#define NTOK  (BATCH*TLEN)        // 2048
#define DIN   80
#define DOUT  4096
#define DMODEL 512
#define DHID  1024
#define NEXP  4
#define NLAYER 8
#define NHEAD 8
#define DH    64
#define MMEM  64
#define SFULL (TLEN+MMEM)         // 576

// ---------------- device scratch (static, no allocs) ----------------
__device__ float g_embed[NTOK*DMODEL];
__device__ float g_hid[NTOK*DHID];
__device__ float g_cur[NTOK*DMODEL];
__device__ float g_p[NTOK*DMODEL];
__device__ float g_q[NTOK*DMODEL];
__device__ float g_k[BATCH*SFULL*DMODEL];
__device__ float g_v[BATCH*SFULL*DMODEL];
__device__ float g_ao[NTOK*DMODEL];
__device__ float g_tmp[NTOK*DMODEL];
__device__ float g_gtok[NTOK];
__device__ float g_imp[NLAYER*NEXP];
__device__ int   g_cnt[NLAYER*NEXP];
__device__ int   g_lists[NEXP*NTOK];
__device__ int   g_kvmap[NTOK];

// ---------------- init ----------------
__global__ void init_kernel() {
    int t = threadIdx.x;
    if (t < NLAYER*NEXP) { g_cnt[t] = 0; g_imp[t] = 0.f; }
    for (int i = t; i < NTOK; i += blockDim.x)
        g_kvmap[i] = (i >> 9) * SFULL + (i & 511);
}

// ---------------- generic tiled SGEMM ----------------
// C[M,N] = op(A@B): optional bias, relu, A row gather, C row scatter,
// per-out-row scale, residual add, dynamic M from device.
#define BK 16
__global__ void gemm64(const float* __restrict__ A,
                       const float* __restrict__ Bm,
                       float* __restrict__ C,
                       int M, int N, int K,
                       const float* __restrict__ bias,
                       int doRelu,
                       const int* __restrict__ gatherA,
                       const int* __restrict__ scatterC,
                       const float* __restrict__ rowScale,
                       const float* __restrict__ residual,
                       const int* __restrict__ Mdev)
{
    __shared__ float As[BK][65];
    __shared__ float Bs[BK][64];
    int Ml = Mdev ? *Mdev : M;
    int row0 = blockIdx.y * 64;
    if (row0 >= Ml) return;
    int col0 = blockIdx.x * 64;
    int tid = threadIdx.x;
    int tx = tid & 15, ty = tid >> 4;
    float acc[4][4] = {};

    for (int k0 = 0; k0 < K; k0 += BK) {
        #pragma unroll
        for (int i = 0; i < 4; i++) {
            int idx = i * 256 + tid;
            int r = idx >> 4, kk = idx & 15;
            int gr = row0 + r;
            float v = 0.f;
            if (gr < Ml) {
                int ar = gatherA ? gatherA[gr] : gr;
                v = A[(size_t)ar * K + (k0 + kk)];
            }
            As[kk][r] = v;
        }
        #pragma unroll
        for (int i = 0; i < 4; i++) {
            int idx = i * 256 + tid;
            int kk = idx >> 6, n = idx & 63;
            Bs[kk][n] = Bm[(size_t)(k0 + kk) * N + col0 + n];
        }
        __syncthreads();
        #pragma unroll
        for (int kk = 0; kk < BK; kk++) {
            float a[4], b[4];
            #pragma unroll
            for (int i = 0; i < 4; i++) a[i] = As[kk][ty + 16 * i];
            #pragma unroll
            for (int j = 0; j < 4; j++) b[j] = Bs[kk][tx + 16 * j];
            #pragma unroll
            for (int i = 0; i < 4; i++)
                #pragma unroll
                for (int j = 0; j < 4; j++)
                    acc[i][j] += a[i] * b[j];
        }
        __syncthreads();
    }

    #pragma unroll
    for (int i = 0; i < 4; i++) {
        int r = row0 + ty + 16 * i;
        if (r >= Ml) continue;
        int orow = scatterC ? scatterC[r] : r;
        float sc = rowScale ? rowScale[orow] : 1.f;
        #pragma unroll
        for (int j = 0; j < 4; j++) {
            int n = col0 + tx + 16 * j;
            float v = acc[i][j] * sc;
            if (bias) v += bias[n];
            if (residual) v += residual[(size_t)orow * N + n];
            if (doRelu) v = fmaxf(v, 0.f);
            C[(size_t)orow * N + n] = v;
        }
    }
}

// ---------------- router: softmax over E=4, top-1 dispatch, importance ----------------
__global__ void router_kernel(const float* __restrict__ embed, const float* __restrict__ R,
                              const int* __restrict__ seqlen, float* __restrict__ gtok,
                              int* __restrict__ lists, int* __restrict__ cnt,
                              float* __restrict__ imp)
{
    int gw = (blockIdx.x * blockDim.x + threadIdx.x) >> 5;
    int lane = threadIdx.x & 31;
    if (gw >= NTOK) return;
    const float* xr = embed + (size_t)gw * DMODEL;
    float l0 = 0, l1 = 0, l2 = 0, l3 = 0;
    for (int d = lane; d < DMODEL; d += 32) {
        float v = xr[d];
        const float* rr = R + d * 4;
        l0 += v * rr[0]; l1 += v * rr[1]; l2 += v * rr[2]; l3 += v * rr[3];
    }
    for (int off = 16; off; off >>= 1) {
        l0 += __shfl_xor_sync(0xffffffffu, l0, off);
        l1 += __shfl_xor_sync(0xffffffffu, l1, off);
        l2 += __shfl_xor_sync(0xffffffffu, l2, off);
        l3 += __shfl_xor_sync(0xffffffffu, l3, off);
    }
    if (lane == 0) {
        float mx = fmaxf(fmaxf(l0, l1), fmaxf(l2, l3));
        float e0 = __expf(l0 - mx), e1 = __expf(l1 - mx);
        float e2 = __expf(l2 - mx), e3 = __expf(l3 - mx);
        float inv = 1.f / (e0 + e1 + e2 + e3);
        float s0 = e0 * inv, s1 = e1 * inv, s2 = e2 * inv, s3 = e3 * inv;
        int em = 0; float gm = s0;
        if (s1 > gm) { gm = s1; em = 1; }
        if (s2 > gm) { gm = s2; em = 2; }
        if (s3 > gm) { gm = s3; em = 3; }
        int b = gw >> 9, t = gw & 511;
        if (t < seqlen[b]) {
            atomicAdd(&imp[0], s0); atomicAdd(&imp[1], s1);
            atomicAdd(&imp[2], s2); atomicAdd(&imp[3], s3);
        }
        gtok[gw] = gm;
        int slot = atomicAdd(&cnt[em], 1);
        lists[em * NTOK + slot] = gw;
    }
}

// ---------------- FSMN depthwise memory ----------------
__global__ void fsmn_kernel(const float* __restrict__ P, const float* __restrict__ fb,
                            const float* __restrict__ fa, const float* __restrict__ skipin,
                            float* __restrict__ outp)
{
    int idx = blockIdx.x * 256 + threadIdx.x;
    if (idx >= NTOK * DMODEL) return;
    int d = idx & 511;
    int t = (idx >> 9) & 511;
    float v = P[idx];
    #pragma unroll
    for (int k = 0; k < 4; k++) {
        int off = (k + 1) * 2;               // SL=2
        if (t - off >= 0) v += fb[k * DMODEL + d] * P[idx - off * DMODEL];
    }
    if (t + 1 < TLEN) v += fa[d] * P[idx + DMODEL];   // SR=1, LA=1
    if (skipin) v += skipin[idx];
    outp[idx] = v;
}

// ---------------- positional encoding add ----------------
__global__ void pe_kernel(float* __restrict__ cur)
{
    int idx = blockIdx.x * 256 + threadIdx.x;
    if (idx >= NTOK * DMODEL) return;
    int d = idx & 511;
    int t = (idx >> 9) & 511;
    int i = d >> 1;
    float div = __expf(-(float)(2 * i) * (9.2103403719761836f / 512.f));
    float a = (float)t * div;
    cur[idx] += (d & 1) ? cosf(a) : sinf(a);
}

// ---------------- broadcast memory KV rows ----------------
__global__ void memrows_kernel(const float* __restrict__ mk, const float* __restrict__ mv,
                               float* __restrict__ Kb, float* __restrict__ Vb)
{
    int idx = blockIdx.x * 256 + threadIdx.x;
    if (idx >= BATCH * MMEM * DMODEL) return;
    int d = idx & 511;
    int r = idx >> 9;
    int m = r & 63;
    int b = r >> 6;
    size_t dst = ((size_t)(b * SFULL + TLEN + m)) * DMODEL + d;
    Kb[dst] = mk[m * DMODEL + d];
    Vb[dst] = mv[m * DMODEL + d];
}

// ---------------- flash attention (64q x 64s tiles) ----------------
#define ATTN_SMEM (4*64*65*4)
__global__ void attn_kernel(const float* __restrict__ Q, const float* __restrict__ Kb,
                            const float* __restrict__ Vb, const int* __restrict__ seqlen,
                            float* __restrict__ O)
{
    extern __shared__ float sm[];
    float* Qs = sm;
    float* Ks = sm + 64 * 65;
    float* Vs = sm + 2 * 64 * 65;
    float* Ps = sm + 3 * 64 * 65;
    int q0 = blockIdx.x * 64, h = blockIdx.y, b = blockIdx.z;
    int tid = threadIdx.x, tx = tid & 15, ty = tid >> 4;
    int slen = seqlen[b];

    #pragma unroll
    for (int i = 0; i < 16; i++) {
        int idx = i * 256 + tid;
        int r = idx >> 6, d = idx & 63;
        Qs[r * 65 + d] = Q[((size_t)(b * TLEN + q0 + r)) * DMODEL + h * DH + d];
    }
    float acc[4][4] = {};
    float m_i[4], l_i[4] = {};
    #pragma unroll
    for (int i = 0; i < 4; i++) m_i[i] = -1e30f;

    for (int s0 = 0; s0 < SFULL; s0 += 64) {
        __syncthreads();
        #pragma unroll
        for (int i = 0; i < 16; i++) {
            int idx = i * 256 + tid;
            int r = idx >> 6, d = idx & 63;
            size_t base = ((size_t)(b * SFULL + s0 + r)) * DMODEL + h * DH + d;
            Ks[r * 65 + d] = Kb[base];
            Vs[r * 65 + d] = Vb[base];
        }
        __syncthreads();
        float st[4][4] = {};
        #pragma unroll 8
        for (int d = 0; d < 64; d++) {
            float a[4], bb[4];
            #pragma unroll
            for (int i = 0; i < 4; i++) a[i] = Qs[(ty + 16 * i) * 65 + d];
            #pragma unroll
            for (int j = 0; j < 4; j++) bb[j] = Ks[(tx + 16 * j) * 65 + d];
            #pragma unroll
            for (int i = 0; i < 4; i++)
                #pragma unroll
                for (int j = 0; j < 4; j++)
                    st[i][j] += a[i] * bb[j];
        }
        #pragma unroll
        for (int i = 0; i < 4; i++) {
            #pragma unroll
            for (int j = 0; j < 4; j++) {
                st[i][j] *= 0.125f;
                int sg = s0 + tx + 16 * j;
                if (sg < TLEN && sg >= slen) st[i][j] = -1e9f;
            }
            float mr = fmaxf(fmaxf(st[i][0], st[i][1]), fmaxf(st[i][2], st[i][3]));
            mr = fmaxf(mr, __shfl_xor_sync(0xffffffffu, mr, 1));
            mr = fmaxf(mr, __shfl_xor_sync(0xffffffffu, mr, 2));
            mr = fmaxf(mr, __shfl_xor_sync(0xffffffffu, mr, 4));
            mr = fmaxf(mr, __shfl_xor_sync(0xffffffffu, mr, 8));
            float mn = fmaxf(m_i[i], mr);
            float lr = 0.f;
            #pragma unroll
            for (int j = 0; j < 4; j++) {
                float pv = __expf(st[i][j] - mn);
                Ps[(ty + 16 * i) * 65 + tx + 16 * j] = pv;
                lr += pv;
            }
            lr += __shfl_xor_sync(0xffffffffu, lr, 1);
            lr += __shfl_xor_sync(0xffffffffu, lr, 2);
            lr += __shfl_xor_sync(0xffffffffu, lr, 4);
            lr += __shfl_xor_sync(0xffffffffu, lr, 8);
            float scl = __expf(m_i[i] - mn);
            l_i[i] = l_i[i] * scl + lr;
            m_i[i] = mn;
            #pragma unroll
            for (int j = 0; j < 4; j++) acc[i][j] *= scl;
        }
        __syncthreads();
        #pragma unroll 8
        for (int s = 0; s < 64; s++) {
            float a[4], bb[4];
            #pragma unroll
            for (int i = 0; i < 4; i++) a[i] = Ps[(ty + 16 * i) * 65 + s];
            #pragma unroll
            for (int j = 0; j < 4; j++) bb[j] = Vs[s * 65 + tx + 16 * j];
            #pragma unroll
            for (int i = 0; i < 4; i++)
                #pragma unroll
                for (int j = 0; j < 4; j++)
                    acc[i][j] += a[i] * bb[j];
        }
    }
    #pragma unroll
    for (int i = 0; i < 4; i++) {
        float inv = 1.f / l_i[i];
        #pragma unroll
        for (int j = 0; j < 4; j++)
            O[((size_t)(b * TLEN + q0 + ty + 16 * i)) * DMODEL + h * DH + tx + 16 * j] =
                acc[i][j] * inv;
    }
}

// ---------------- layernorm ----------------
__global__ void ln_kernel(const float* __restrict__ X, float* __restrict__ Y,
                          const float* __restrict__ gw, const float* __restrict__ bw)
{
    __shared__ float red[128];
    int row = blockIdx.x, tid = threadIdx.x;
    const float* xr = X + (size_t)row * DMODEL;
    float v[4]; float s = 0.f;
    #pragma unroll
    for (int i = 0; i < 4; i++) { v[i] = xr[tid + 128 * i]; s += v[i]; }
    red[tid] = s; __syncthreads();
    for (int off = 64; off > 0; off >>= 1) {
        if (tid < off) red[tid] += red[tid + off];
        __syncthreads();
    }
    float mu = red[0] * (1.f / 512.f);
    __syncthreads();
    float s2 = 0.f;
    #pragma unroll
    for (int i = 0; i < 4; i++) { float d = v[i] - mu; s2 += d * d; }
    red[tid] = s2; __syncthreads();
    for (int off = 64; off > 0; off >>= 1) {
        if (tid < off) red[tid] += red[tid + off];
        __syncthreads();
    }
    float inv = rsqrtf(red[0] * (1.f / 512.f) + 1e-5f);
    #pragma unroll
    for (int i = 0; i < 4; i++) {
        int c = tid + 128 * i;
        Y[(size_t)row * DMODEL + c] = (v[i] - mu) * inv * gw[c] + bw[c];
    }
}

// ---------------- aux (importance cv^2 summed over layers) ----------------
__global__ void aux_kernel(float* __restrict__ dst)
{
    float tot = 0.f;
    for (int l = 0; l < NLAYER; l++) {
        float m = 0.f;
        for (int e = 0; e < NEXP; e++) m += g_imp[l * 4 + e];
        m *= 0.25f;
        float var = 0.f;
        for (int e = 0; e < NEXP; e++) { float d = g_imp[l * 4 + e] - m; var += d * d; }
        var *= 0.25f;
        tot += var / (m * m + 1e-9f);
    }
    dst[0] = tot;
}

// ---------------- launcher ----------------
extern "C" void kernel_launch(void* const* d_in, const int* in_sizes, int n_in,
                              void* d_out, int out_size)
{
    const float* x         = (const float*)d_in[0];
    const int*   seq       = (const int*)  d_in[1];
    const float* emb_w1    = (const float*)d_in[2];
    const float* emb_b1    = (const float*)d_in[3];
    const float* emb_w2    = (const float*)d_in[4];
    const float* emb_wo    = (const float*)d_in[5];
    const float* f0_w1     = (const float*)d_in[6];
    const float* f0_b1     = (const float*)d_in[7];
    const float* f0_w2     = (const float*)d_in[8];
    const float* f0_router = (const float*)d_in[9];
    const float* f0_fb     = (const float*)d_in[10];
    const float* f0_fa     = (const float*)d_in[11];
    const float* f_w1      = (const float*)d_in[12];
    const float* f_b1      = (const float*)d_in[13];
    const float* f_w2      = (const float*)d_in[14];
    const float* f_router  = (const float*)d_in[15];
    const float* f_fb      = (const float*)d_in[16];
    const float* f_fa      = (const float*)d_in[17];
    const float* wq        = (const float*)d_in[18];
    const float* wk        = (const float*)d_in[19];
    const float* wv        = (const float*)d_in[20];
    const float* wvo       = (const float*)d_in[21];
    const float* mk        = (const float*)d_in[22];
    const float* mv        = (const float*)d_in[23];
    const float* lng       = (const float*)d_in[24];
    const float* lnb       = (const float*)d_in[25];
    const float* out_w     = (const float*)d_in[26];
    const float* out_b     = (const float*)d_in[27];
    float* out = (float*)d_out;

    float *embed, *hid, *cur, *p, *q, *kb, *vb, *ao, *tmp, *gtok, *imp;
    int *cnt, *lists;
    cudaGetSymbolAddress((void**)&embed, g_embed);
    cudaGetSymbolAddress((void**)&hid,   g_hid);
    cudaGetSymbolAddress((void**)&cur,   g_cur);
    cudaGetSymbolAddress((void**)&p,     g_p);
    cudaGetSymbolAddress((void**)&q,     g_q);
    cudaGetSymbolAddress((void**)&kb,    g_k);
    cudaGetSymbolAddress((void**)&vb,    g_v);
    cudaGetSymbolAddress((void**)&ao,    g_ao);
    cudaGetSymbolAddress((void**)&tmp,   g_tmp);
    cudaGetSymbolAddress((void**)&gtok,  g_gtok);
    cudaGetSymbolAddress((void**)&imp,   g_imp);
    cudaGetSymbolAddress((void**)&cnt,   g_cnt);
    cudaGetSymbolAddress((void**)&lists, g_lists);
    int* kvmap;
    cudaGetSymbolAddress((void**)&kvmap, g_kvmap);

    cudaFuncSetAttribute(attn_kernel, cudaFuncAttributeMaxDynamicSharedMemorySize, ATTN_SMEM);

    auto GEMM = [](const float* A, const float* Bm, float* C, int M, int N, int K,
                   const float* bias, int relu, const int* ga, const int* sc,
                   const float* rs, const float* res, const int* Md) {
        dim3 grid(N / 64, (M + 63) / 64);
        gemm64<<<grid, 256>>>(A, Bm, C, M, N, K, bias, relu, ga, sc, rs, res, Md);
    };

    init_kernel<<<1, 1024>>>();

    // embed sub-network + embed_out
    GEMM(x, emb_w1, hid, NTOK, DHID, DIN, emb_b1, 1, 0, 0, 0, 0, 0);
    GEMM(hid, emb_w2, embed, NTOK, DMODEL, DHID, 0, 0, 0, 0, 0, 0, 0);
    GEMM(embed, emb_wo, out + (size_t)NTOK * DOUT, NTOK, DOUT, DMODEL, 0, 0, 0, 0, 0, 0, 0);

    for (int l = 0; l < NLAYER; l++) {
        const float* Rl  = (l == 0) ? f0_router : f_router + (size_t)(l - 1) * DMODEL * NEXP;
        router_kernel<<<NTOK / 8, 256>>>(embed, Rl, seq, gtok, lists, cnt + l * 4, imp + l * 4);

        const float* Ain = (l == 0) ? x : cur;
        int Kin = (l == 0) ? DIN : DMODEL;
        for (int e = 0; e < NEXP; e++) {
            const float* w1 = (l == 0) ? f0_w1 + (size_t)e * DIN * DHID
                                       : f_w1 + ((size_t)(l - 1) * NEXP + e) * DMODEL * DHID;
            const float* b1 = (l == 0) ? f0_b1 + e * DHID
                                       : f_b1 + ((size_t)(l - 1) * NEXP + e) * DHID;
            const float* w2 = (l == 0) ? f0_w2 + (size_t)e * DHID * DMODEL
                                       : f_w2 + ((size_t)(l - 1) * NEXP + e) * DHID * DMODEL;
            const int* lst = lists + e * NTOK;
            const int* Md  = cnt + l * 4 + e;
            GEMM(Ain, w1, hid, NTOK, DHID, Kin, b1, 1, lst, lst, 0, 0, Md);
            GEMM(hid, w2, p, NTOK, DMODEL, DHID, 0, 0, lst, lst, gtok, 0, Md);
        }
        const float* fbL = (l == 0) ? f0_fb : f_fb + (size_t)(l - 1) * 4 * DMODEL;
        const float* faL = (l == 0) ? f0_fa : f_fa + (size_t)(l - 1) * DMODEL;
        fsmn_kernel<<<NTOK * DMODEL / 256, 256>>>(p, fbL, faL, (l == 0) ? (const float*)0 : cur, cur);

        if (l == 3) pe_kernel<<<NTOK * DMODEL / 256, 256>>>(cur);

        if (l == 3 || l == 7) {
            int bi = l / 4;
            size_t wo = (size_t)bi * DMODEL * DMODEL;
            GEMM(cur, wq + wo, q, NTOK, DMODEL, DMODEL, 0, 0, 0, 0, 0, 0, 0);
            GEMM(cur, wk + wo, kb, NTOK, DMODEL, DMODEL, 0, 0, 0, kvmap, 0, 0, 0);
            GEMM(cur, wv + wo, vb, NTOK, DMODEL, DMODEL, 0, 0, 0, kvmap, 0, 0, 0);
            memrows_kernel<<<BATCH * MMEM * DMODEL / 256, 256>>>(
                mk + (size_t)bi * MMEM * DMODEL, mv + (size_t)bi * MMEM * DMODEL, kb, vb);
            attn_kernel<<<dim3(TLEN / 64, NHEAD, BATCH), 256, ATTN_SMEM>>>(q, kb, vb, seq, ao);
            GEMM(ao, wvo + wo, tmp, NTOK, DMODEL, DMODEL, 0, 0, 0, 0, 0, cur, 0);
            ln_kernel<<<NTOK, 128>>>(tmp, cur, lng + bi * DMODEL, lnb + bi * DMODEL);
        }
    }

    GEMM(cur, out_w, out, NTOK, DOUT, DMODEL, out_b, 0, 0, 0, 0, 0, 0);
    aux_kernel<<<1, 1>>>(out + 2 * (size_t)NTOK * DOUT);
}

// round 2
// speedup vs baseline: 1.5309x; 1.5309x over previous
#include <cuda_runtime.h>
#include <cuda_bf16.h>
#include <math.h>

// ---------------- problem constants ----------------
#define BATCH 4
#define TLEN  512
#define NTOK  (BATCH*TLEN)        // 2048
#define DIN   80
#define DOUT  4096
#define DMODEL 512
#define DHID  1024
#define NEXP  4
#define NLAYER 8
#define NHEAD 8
#define DH    64
#define MMEM  64
#define SFULL (TLEN+MMEM)         // 576

// ---------------- device scratch (static, no allocs) ----------------
__device__ float g_embed[NTOK*DMODEL];
__device__ float g_hid[NTOK*DHID];
__device__ float g_cur[NTOK*DMODEL];
__device__ float g_p[NTOK*DMODEL];
__device__ float g_q[NTOK*DMODEL];
__device__ float g_k[BATCH*SFULL*DMODEL];
__device__ float g_v[BATCH*SFULL*DMODEL];
__device__ float g_ao[NTOK*DMODEL];
__device__ float g_tmp[NTOK*DMODEL];
__device__ float g_gtok[NTOK];
__device__ float g_imp[NLAYER*NEXP];
__device__ int   g_cnt[NLAYER*NEXP];
__device__ int   g_lists[NEXP*NTOK];
__device__ int   g_kvmap[NTOK];

// ---------------- init ----------------
__global__ void init_kernel() {
    int t = threadIdx.x;
    if (t < NLAYER*NEXP) { g_cnt[t] = 0; g_imp[t] = 0.f; }
    for (int i = t; i < NTOK; i += blockDim.x)
        g_kvmap[i] = (i >> 9) * SFULL + (i & 511);
}

// ---------------- 128x128 tiled SGEMM, 8x8 microtile, double-buffered ----------------
// C[M,N] = op(A@B): optional bias, relu, A row gather, C row scatter,
// per-out-row scale, residual add, dynamic M from device, fused expert dim (z).
#define TK 8
__global__ __launch_bounds__(256, 2)
void gemm128(const float* __restrict__ A,
             const float* __restrict__ Bm,
             float* __restrict__ C,
             int N, int K, int Mstatic,
             const float* __restrict__ bias,
             int doRelu,
             const int* __restrict__ gatherA,
             const int* __restrict__ scatterC,
             const float* __restrict__ rowScale,
             const float* __restrict__ residual,
             const int* __restrict__ Mdev,
             int strideB, int strideBias, int strideList)
{
    __shared__ float As[2][TK][132];
    __shared__ float Bs[2][TK][132];

    int e = blockIdx.z;
    const float* Bz    = Bm + (size_t)e * strideB;
    const float* biasz = bias ? bias + (size_t)e * strideBias : (const float*)0;
    const int*   gA    = gatherA ? gatherA + (size_t)e * strideList : (const int*)0;
    const int*   sC    = scatterC ? scatterC + (size_t)e * strideList : (const int*)0;
    int Ml = Mdev ? Mdev[e] : Mstatic;
    int row0 = blockIdx.y * 128;
    if (row0 >= Ml) return;
    int col0 = blockIdx.x * 128;
    int tid = threadIdx.x;
    int tx = tid & 15, ty = tid >> 4;

    // global load assignments
    int ar_ = tid >> 1;          // 0..127 tile row
    int ah  = (tid & 1) * 4;     // k sub-offset 0 or 4
    int agr = row0 + ar_;
    int arow = -1;
    if (agr < Ml) arow = gA ? gA[agr] : agr;
    int bkr = tid >> 5;          // 0..7
    int bc  = (tid & 31) * 4;    // 0..124

    float4 av = make_float4(0.f, 0.f, 0.f, 0.f), bv;
    if (arow >= 0) av = *(const float4*)(A + (size_t)arow * K + ah);
    bv = *(const float4*)(Bz + (size_t)bkr * N + col0 + bc);
    As[0][ah + 0][ar_] = av.x; As[0][ah + 1][ar_] = av.y;
    As[0][ah + 2][ar_] = av.z; As[0][ah + 3][ar_] = av.w;
    *(float4*)&Bs[0][bkr][bc] = bv;
    __syncthreads();

    float acc[8][8] = {};
    int nk = K / TK;
    int ty8 = ty * 8, tx8 = tx * 8;

    for (int t = 0; t < nk; t++) {
        int cur = t & 1, nxt = cur ^ 1;
        if (t + 1 < nk) {
            int k0 = (t + 1) * TK;
            av = make_float4(0.f, 0.f, 0.f, 0.f);
            if (arow >= 0) av = *(const float4*)(A + (size_t)arow * K + k0 + ah);
            bv = *(const float4*)(Bz + (size_t)(k0 + bkr) * N + col0 + bc);
        }
        #pragma unroll
        for (int k = 0; k < TK; k++) {
            float4 a0 = *(const float4*)&As[cur][k][ty8];
            float4 a1 = *(const float4*)&As[cur][k][ty8 + 4];
            float4 b0 = *(const float4*)&Bs[cur][k][tx8];
            float4 b1 = *(const float4*)&Bs[cur][k][tx8 + 4];
            float aa[8] = {a0.x, a0.y, a0.z, a0.w, a1.x, a1.y, a1.z, a1.w};
            float bb[8] = {b0.x, b0.y, b0.z, b0.w, b1.x, b1.y, b1.z, b1.w};
            #pragma unroll
            for (int i = 0; i < 8; i++)
                #pragma unroll
                for (int j = 0; j < 8; j++)
                    acc[i][j] += aa[i] * bb[j];
        }
        if (t + 1 < nk) {
            As[nxt][ah + 0][ar_] = av.x; As[nxt][ah + 1][ar_] = av.y;
            As[nxt][ah + 2][ar_] = av.z; As[nxt][ah + 3][ar_] = av.w;
            *(float4*)&Bs[nxt][bkr][bc] = bv;
        }
        __syncthreads();
    }

    // epilogue
    float bb[8] = {};
    if (biasz) {
        #pragma unroll
        for (int j = 0; j < 8; j++) bb[j] = biasz[col0 + tx8 + j];
    }
    #pragma unroll
    for (int i = 0; i < 8; i++) {
        int r = row0 + ty8 + i;
        if (r >= Ml) continue;
        int orow = sC ? sC[r] : r;
        float sc = rowScale ? rowScale[orow] : 1.f;
        size_t cb = (size_t)orow * N + col0 + tx8;
        float v[8];
        #pragma unroll
        for (int j = 0; j < 8; j++) v[j] = acc[i][j] * sc + bb[j];
        if (residual) {
            float4 r0 = *(const float4*)(residual + cb);
            float4 r1 = *(const float4*)(residual + cb + 4);
            v[0] += r0.x; v[1] += r0.y; v[2] += r0.z; v[3] += r0.w;
            v[4] += r1.x; v[5] += r1.y; v[6] += r1.z; v[7] += r1.w;
        }
        if (doRelu) {
            #pragma unroll
            for (int j = 0; j < 8; j++) v[j] = fmaxf(v[j], 0.f);
        }
        *(float4*)(C + cb)     = make_float4(v[0], v[1], v[2], v[3]);
        *(float4*)(C + cb + 4) = make_float4(v[4], v[5], v[6], v[7]);
    }
}

// ---------------- router: softmax over E=4, top-1 dispatch, importance ----------------
__global__ void router_kernel(const float* __restrict__ embed, const float* __restrict__ R,
                              const int* __restrict__ seqlen, float* __restrict__ gtok,
                              int* __restrict__ lists, int* __restrict__ cnt,
                              float* __restrict__ imp)
{
    int gw = (blockIdx.x * blockDim.x + threadIdx.x) >> 5;
    int lane = threadIdx.x & 31;
    if (gw >= NTOK) return;
    const float* xr = embed + (size_t)gw * DMODEL;
    float l0 = 0, l1 = 0, l2 = 0, l3 = 0;
    for (int d = lane; d < DMODEL; d += 32) {
        float v = xr[d];
        const float* rr = R + d * 4;
        l0 += v * rr[0]; l1 += v * rr[1]; l2 += v * rr[2]; l3 += v * rr[3];
    }
    for (int off = 16; off; off >>= 1) {
        l0 += __shfl_xor_sync(0xffffffffu, l0, off);
        l1 += __shfl_xor_sync(0xffffffffu, l1, off);
        l2 += __shfl_xor_sync(0xffffffffu, l2, off);
        l3 += __shfl_xor_sync(0xffffffffu, l3, off);
    }
    if (lane == 0) {
        float mx = fmaxf(fmaxf(l0, l1), fmaxf(l2, l3));
        float e0 = __expf(l0 - mx), e1 = __expf(l1 - mx);
        float e2 = __expf(l2 - mx), e3 = __expf(l3 - mx);
        float inv = 1.f / (e0 + e1 + e2 + e3);
        float s0 = e0 * inv, s1 = e1 * inv, s2 = e2 * inv, s3 = e3 * inv;
        int em = 0; float gm = s0;
        if (s1 > gm) { gm = s1; em = 1; }
        if (s2 > gm) { gm = s2; em = 2; }
        if (s3 > gm) { gm = s3; em = 3; }
        int b = gw >> 9, t = gw & 511;
        if (t < seqlen[b]) {
            atomicAdd(&imp[0], s0); atomicAdd(&imp[1], s1);
            atomicAdd(&imp[2], s2); atomicAdd(&imp[3], s3);
        }
        gtok[gw] = gm;
        int slot = atomicAdd(&cnt[em], 1);
        lists[em * NTOK + slot] = gw;
    }
}

// ---------------- FSMN depthwise memory ----------------
__global__ void fsmn_kernel(const float* __restrict__ P, const float* __restrict__ fb,
                            const float* __restrict__ fa, const float* __restrict__ skipin,
                            float* __restrict__ outp)
{
    int idx = blockIdx.x * 256 + threadIdx.x;
    if (idx >= NTOK * DMODEL) return;
    int d = idx & 511;
    int t = (idx >> 9) & 511;
    float v = P[idx];
    #pragma unroll
    for (int k = 0; k < 4; k++) {
        int off = (k + 1) * 2;               // SL=2
        if (t - off >= 0) v += fb[k * DMODEL + d] * P[idx - off * DMODEL];
    }
    if (t + 1 < TLEN) v += fa[d] * P[idx + DMODEL];   // SR=1, LA=1
    if (skipin) v += skipin[idx];
    outp[idx] = v;
}

// ---------------- positional encoding add ----------------
__global__ void pe_kernel(float* __restrict__ cur)
{
    int idx = blockIdx.x * 256 + threadIdx.x;
    if (idx >= NTOK * DMODEL) return;
    int d = idx & 511;
    int t = (idx >> 9) & 511;
    int i = d >> 1;
    float div = __expf(-(float)(2 * i) * (9.2103403719761836f / 512.f));
    float a = (float)t * div;
    cur[idx] += (d & 1) ? cosf(a) : sinf(a);
}

// ---------------- broadcast memory KV rows ----------------
__global__ void memrows_kernel(const float* __restrict__ mk, const float* __restrict__ mv,
                               float* __restrict__ Kb, float* __restrict__ Vb)
{
    int idx = blockIdx.x * 256 + threadIdx.x;
    if (idx >= BATCH * MMEM * DMODEL) return;
    int d = idx & 511;
    int r = idx >> 9;
    int m = r & 63;
    int b = r >> 6;
    size_t dst = ((size_t)(b * SFULL + TLEN + m)) * DMODEL + d;
    Kb[dst] = mk[m * DMODEL + d];
    Vb[dst] = mv[m * DMODEL + d];
}

// ---------------- flash attention (64q x 64s tiles) ----------------
#define ATTN_SMEM (4*64*65*4)
__global__ void attn_kernel(const float* __restrict__ Q, const float* __restrict__ Kb,
                            const float* __restrict__ Vb, const int* __restrict__ seqlen,
                            float* __restrict__ O)
{
    extern __shared__ float sm[];
    float* Qs = sm;
    float* Ks = sm + 64 * 65;
    float* Vs = sm + 2 * 64 * 65;
    float* Ps = sm + 3 * 64 * 65;
    int q0 = blockIdx.x * 64, h = blockIdx.y, b = blockIdx.z;
    int tid = threadIdx.x, tx = tid & 15, ty = tid >> 4;
    int slen = seqlen[b];

    #pragma unroll
    for (int i = 0; i < 16; i++) {
        int idx = i * 256 + tid;
        int r = idx >> 6, d = idx & 63;
        Qs[r * 65 + d] = Q[((size_t)(b * TLEN + q0 + r)) * DMODEL + h * DH + d];
    }
    float acc[4][4] = {};
    float m_i[4], l_i[4] = {};
    #pragma unroll
    for (int i = 0; i < 4; i++) m_i[i] = -1e30f;

    for (int s0 = 0; s0 < SFULL; s0 += 64) {
        __syncthreads();
        #pragma unroll
        for (int i = 0; i < 16; i++) {
            int idx = i * 256 + tid;
            int r = idx >> 6, d = idx & 63;
            size_t base = ((size_t)(b * SFULL + s0 + r)) * DMODEL + h * DH + d;
            Ks[r * 65 + d] = Kb[base];
            Vs[r * 65 + d] = Vb[base];
        }
        __syncthreads();
        float st[4][4] = {};
        #pragma unroll 8
        for (int d = 0; d < 64; d++) {
            float a[4], bbv[4];
            #pragma unroll
            for (int i = 0; i < 4; i++) a[i] = Qs[(ty + 16 * i) * 65 + d];
            #pragma unroll
            for (int j = 0; j < 4; j++) bbv[j] = Ks[(tx + 16 * j) * 65 + d];
            #pragma unroll
            for (int i = 0; i < 4; i++)
                #pragma unroll
                for (int j = 0; j < 4; j++)
                    st[i][j] += a[i] * bbv[j];
        }
        #pragma unroll
        for (int i = 0; i < 4; i++) {
            #pragma unroll
            for (int j = 0; j < 4; j++) {
                st[i][j] *= 0.125f;
                int sg = s0 + tx + 16 * j;
                if (sg < TLEN && sg >= slen) st[i][j] = -1e9f;
            }
            float mr = fmaxf(fmaxf(st[i][0], st[i][1]), fmaxf(st[i][2], st[i][3]));
            mr = fmaxf(mr, __shfl_xor_sync(0xffffffffu, mr, 1));
            mr = fmaxf(mr, __shfl_xor_sync(0xffffffffu, mr, 2));
            mr = fmaxf(mr, __shfl_xor_sync(0xffffffffu, mr, 4));
            mr = fmaxf(mr, __shfl_xor_sync(0xffffffffu, mr, 8));
            float mn = fmaxf(m_i[i], mr);
            float lr = 0.f;
            #pragma unroll
            for (int j = 0; j < 4; j++) {
                float pv = __expf(st[i][j] - mn);
                Ps[(ty + 16 * i) * 65 + tx + 16 * j] = pv;
                lr += pv;
            }
            lr += __shfl_xor_sync(0xffffffffu, lr, 1);
            lr += __shfl_xor_sync(0xffffffffu, lr, 2);
            lr += __shfl_xor_sync(0xffffffffu, lr, 4);
            lr += __shfl_xor_sync(0xffffffffu, lr, 8);
            float scl = __expf(m_i[i] - mn);
            l_i[i] = l_i[i] * scl + lr;
            m_i[i] = mn;
            #pragma unroll
            for (int j = 0; j < 4; j++) acc[i][j] *= scl;
        }
        __syncthreads();
        #pragma unroll 8
        for (int s = 0; s < 64; s++) {
            float a[4], bbv[4];
            #pragma unroll
            for (int i = 0; i < 4; i++) a[i] = Ps[(ty + 16 * i) * 65 + s];
            #pragma unroll
            for (int j = 0; j < 4; j++) bbv[j] = Vs[s * 65 + tx + 16 * j];
            #pragma unroll
            for (int i = 0; i < 4; i++)
                #pragma unroll
                for (int j = 0; j < 4; j++)
                    acc[i][j] += a[i] * bbv[j];
        }
    }
    #pragma unroll
    for (int i = 0; i < 4; i++) {
        float inv = 1.f / l_i[i];
        #pragma unroll
        for (int j = 0; j < 4; j++)
            O[((size_t)(b * TLEN + q0 + ty + 16 * i)) * DMODEL + h * DH + tx + 16 * j] =
                acc[i][j] * inv;
    }
}

// ---------------- layernorm ----------------
__global__ void ln_kernel(const float* __restrict__ X, float* __restrict__ Y,
                          const float* __restrict__ gw, const float* __restrict__ bw)
{
    __shared__ float red[128];
    int row = blockIdx.x, tid = threadIdx.x;
    const float* xr = X + (size_t)row * DMODEL;
    float v[4]; float s = 0.f;
    #pragma unroll
    for (int i = 0; i < 4; i++) { v[i] = xr[tid + 128 * i]; s += v[i]; }
    red[tid] = s; __syncthreads();
    for (int off = 64; off > 0; off >>= 1) {
        if (tid < off) red[tid] += red[tid + off];
        __syncthreads();
    }
    float mu = red[0] * (1.f / 512.f);
    __syncthreads();
    float s2 = 0.f;
    #pragma unroll
    for (int i = 0; i < 4; i++) { float d = v[i] - mu; s2 += d * d; }
    red[tid] = s2; __syncthreads();
    for (int off = 64; off > 0; off >>= 1) {
        if (tid < off) red[tid] += red[tid + off];
        __syncthreads();
    }
    float inv = rsqrtf(red[0] * (1.f / 512.f) + 1e-5f);
    #pragma unroll
    for (int i = 0; i < 4; i++) {
        int c = tid + 128 * i;
        Y[(size_t)row * DMODEL + c] = (v[i] - mu) * inv * gw[c] + bw[c];
    }
}

// ---------------- aux (importance cv^2 summed over layers) ----------------
__global__ void aux_kernel(float* __restrict__ dst)
{
    float tot = 0.f;
    for (int l = 0; l < NLAYER; l++) {
        float m = 0.f;
        for (int e = 0; e < NEXP; e++) m += g_imp[l * 4 + e];
        m *= 0.25f;
        float var = 0.f;
        for (int e = 0; e < NEXP; e++) { float d = g_imp[l * 4 + e] - m; var += d * d; }
        var *= 0.25f;
        tot += var / (m * m + 1e-9f);
    }
    dst[0] = tot;
}

// ---------------- launcher ----------------
extern "C" void kernel_launch(void* const* d_in, const int* in_sizes, int n_in,
                              void* d_out, int out_size)
{
    const float* x         = (const float*)d_in[0];
    const int*   seq       = (const int*)  d_in[1];
    const float* emb_w1    = (const float*)d_in[2];
    const float* emb_b1    = (const float*)d_in[3];
    const float* emb_w2    = (const float*)d_in[4];
    const float* emb_wo    = (const float*)d_in[5];
    const float* f0_w1     = (const float*)d_in[6];
    const float* f0_b1     = (const float*)d_in[7];
    const float* f0_w2     = (const float*)d_in[8];
    const float* f0_router = (const float*)d_in[9];
    const float* f0_fb     = (const float*)d_in[10];
    const float* f0_fa     = (const float*)d_in[11];
    const float* f_w1      = (const float*)d_in[12];
    const float* f_b1      = (const float*)d_in[13];
    const float* f_w2      = (const float*)d_in[14];
    const float* f_router  = (const float*)d_in[15];
    const float* f_fb      = (const float*)d_in[16];
    const float* f_fa      = (const float*)d_in[17];
    const float* wq        = (const float*)d_in[18];
    const float* wk        = (const float*)d_in[19];
    const float* wv        = (const float*)d_in[20];
    const float* wvo       = (const float*)d_in[21];
    const float* mk        = (const float*)d_in[22];
    const float* mv        = (const float*)d_in[23];
    const float* lng       = (const float*)d_in[24];
    const float* lnb       = (const float*)d_in[25];
    const float* out_w     = (const float*)d_in[26];
    const float* out_b     = (const float*)d_in[27];
    float* out = (float*)d_out;

    float *embed, *hid, *cur, *p, *q, *kb, *vb, *ao, *tmp, *gtok, *imp;
    int *cnt, *lists, *kvmap;
    cudaGetSymbolAddress((void**)&embed, g_embed);
    cudaGetSymbolAddress((void**)&hid,   g_hid);
    cudaGetSymbolAddress((void**)&cur,   g_cur);
    cudaGetSymbolAddress((void**)&p,     g_p);
    cudaGetSymbolAddress((void**)&q,     g_q);
    cudaGetSymbolAddress((void**)&kb,    g_k);
    cudaGetSymbolAddress((void**)&vb,    g_v);
    cudaGetSymbolAddress((void**)&ao,    g_ao);
    cudaGetSymbolAddress((void**)&tmp,   g_tmp);
    cudaGetSymbolAddress((void**)&gtok,  g_gtok);
    cudaGetSymbolAddress((void**)&imp,   g_imp);
    cudaGetSymbolAddress((void**)&cnt,   g_cnt);
    cudaGetSymbolAddress((void**)&lists, g_lists);
    cudaGetSymbolAddress((void**)&kvmap, g_kvmap);

    cudaFuncSetAttribute(attn_kernel, cudaFuncAttributeMaxDynamicSharedMemorySize, ATTN_SMEM);

    auto GEMM = [](const float* A, const float* Bm, float* C, int M, int N, int K,
                   const float* bias, int relu, const int* ga, const int* sc,
                   const float* rs, const float* res, const int* Md,
                   int E = 1, int sB = 0, int sBias = 0, int sList = 0) {
        dim3 grid(N / 128, (M + 127) / 128, E);
        gemm128<<<grid, 256>>>(A, Bm, C, N, K, M, bias, relu, ga, sc, rs, res, Md,
                               sB, sBias, sList);
    };

    init_kernel<<<1, 1024>>>();

    // embed sub-network + embed_out
    GEMM(x, emb_w1, hid, NTOK, DHID, DIN, emb_b1, 1, 0, 0, 0, 0, 0);
    GEMM(hid, emb_w2, embed, NTOK, DMODEL, DHID, 0, 0, 0, 0, 0, 0, 0);
    GEMM(embed, emb_wo, out + (size_t)NTOK * DOUT, NTOK, DOUT, DMODEL, 0, 0, 0, 0, 0, 0, 0);

    for (int l = 0; l < NLAYER; l++) {
        const float* Rl  = (l == 0) ? f0_router : f_router + (size_t)(l - 1) * DMODEL * NEXP;
        router_kernel<<<NTOK / 8, 256>>>(embed, Rl, seq, gtok, lists, cnt + l * 4, imp + l * 4);

        const float* Ain = (l == 0) ? x : cur;
        int Kin = (l == 0) ? DIN : DMODEL;
        const float* w1b = (l == 0) ? f0_w1 : f_w1 + (size_t)(l - 1) * NEXP * DMODEL * DHID;
        const float* b1b = (l == 0) ? f0_b1 : f_b1 + (size_t)(l - 1) * NEXP * DHID;
        const float* w2b = (l == 0) ? f0_w2 : f_w2 + (size_t)(l - 1) * NEXP * DHID * DMODEL;

        // fused-over-experts launches (blockIdx.z = expert)
        GEMM(Ain, w1b, hid, NTOK, DHID, Kin, b1b, 1, lists, lists, 0, 0, cnt + l * 4,
             NEXP, Kin * DHID, DHID, NTOK);
        GEMM(hid, w2b, p, NTOK, DMODEL, DHID, 0, 0, lists, lists, gtok, 0, cnt + l * 4,
             NEXP, DHID * DMODEL, 0, NTOK);

        const float* fbL = (l == 0) ? f0_fb : f_fb + (size_t)(l - 1) * 4 * DMODEL;
        const float* faL = (l == 0) ? f0_fa : f_fa + (size_t)(l - 1) * DMODEL;
        fsmn_kernel<<<NTOK * DMODEL / 256, 256>>>(p, fbL, faL, (l == 0) ? (const float*)0 : cur, cur);

        if (l == 3) pe_kernel<<<NTOK * DMODEL / 256, 256>>>(cur);

        if (l == 3 || l == 7) {
            int bi = l / 4;
            size_t wo = (size_t)bi * DMODEL * DMODEL;
            GEMM(cur, wq + wo, q, NTOK, DMODEL, DMODEL, 0, 0, 0, 0, 0, 0, 0);
            GEMM(cur, wk + wo, kb, NTOK, DMODEL, DMODEL, 0, 0, 0, kvmap, 0, 0, 0);
            GEMM(cur, wv + wo, vb, NTOK, DMODEL, DMODEL, 0, 0, 0, kvmap, 0, 0, 0);
            memrows_kernel<<<BATCH * MMEM * DMODEL / 256, 256>>>(
                mk + (size_t)bi * MMEM * DMODEL, mv + (size_t)bi * MMEM * DMODEL, kb, vb);
            attn_kernel<<<dim3(TLEN / 64, NHEAD, BATCH), 256, ATTN_SMEM>>>(q, kb, vb, seq, ao);
            GEMM(ao, wvo + wo, tmp, NTOK, DMODEL, DMODEL, 0, 0, 0, 0, 0, cur, 0);
            ln_kernel<<<NTOK, 128>>>(tmp, cur, lng + bi * DMODEL, lnb + bi * DMODEL);
        }
    }

    GEMM(cur, out_w, out, NTOK, DOUT, DMODEL, out_b, 0, 0, 0, 0, 0, 0);
    aux_kernel<<<1, 1>>>(out + 2 * (size_t)NTOK * DOUT);
}

// round 4
// speedup vs baseline: 3.3026x; 2.1573x over previous
#include <cuda_runtime.h>
#include <cuda_bf16.h>
#include <math.h>
#include <stdint.h>

// ---------------- problem constants ----------------
#define BATCH 4
#define TLEN  512
#define NTOK  (BATCH*TLEN)        // 2048
#define DIN   80
#define DOUT  4096
#define DMODEL 512
#define DHID  1024
#define NEXP  4
#define NLAYER 8
#define NHEAD 8
#define DH    64
#define MMEM  64
#define SFULL (TLEN+MMEM)         // 576

// ---------------- device scratch (static, no allocs) ----------------
__device__ float g_embed[NTOK*DMODEL];
__device__ float g_hid[NTOK*DHID];
__device__ float g_cur[NTOK*DMODEL];
__device__ float g_p[NTOK*DMODEL];
__device__ float g_q[NTOK*DMODEL];
__device__ float g_k[BATCH*SFULL*DMODEL];
__device__ float g_v[BATCH*SFULL*DMODEL];
__device__ float g_ao[NTOK*DMODEL];
__device__ float g_tmp[NTOK*DMODEL];
__device__ float g_gtok[NTOK];
__device__ float g_imp[NLAYER*NEXP];
__device__ int   g_cnt[NLAYER*NEXP];
__device__ int   g_lists[NEXP*NTOK];
__device__ int   g_kvmap[NTOK];

// bf16 weight pools (transposed to [N,K]) and activation split buffers
#define WPOOL (40u*1024u*1024u)
__device__ __nv_bfloat16 g_whi[WPOOL];
__device__ __nv_bfloat16 g_wlo[WPOOL];
__device__ __nv_bfloat16 g_ahi[NTOK*DHID];
__device__ __nv_bfloat16 g_alo[NTOK*DHID];

// pool offsets (elements)
#define OFF_EMBW2 0u
#define OFF_EMBWO (OFF_EMBW2 + 512u*1024u)
#define OFF_F0W2  (OFF_EMBWO + 4096u*512u)
#define OFF_FW1   (OFF_F0W2 + 4u*512u*1024u)
#define OFF_FW2   (OFF_FW1 + 28u*1024u*512u)
#define OFF_WQ    (OFF_FW2 + 28u*512u*1024u)
#define OFF_WK    (OFF_WQ + 2u*512u*512u)
#define OFF_WV    (OFF_WK + 2u*512u*512u)
#define OFF_WO    (OFF_WV + 2u*512u*512u)
#define OFF_OUTW  (OFF_WO + 2u*512u*512u)

// ---------------- warp-MMA helpers (sm_80+ PTX, works on plain sm_103) ----------------
__device__ __forceinline__ uint32_t s2u(const void* p) {
    uint32_t a;
    asm("{ .reg .u64 t; cvta.to.shared.u64 t, %1; cvt.u32.u64 %0, t; }" : "=r"(a) : "l"(p));
    return a;
}
__device__ __forceinline__ void ldsm4(uint32_t* r, uint32_t addr) {
    asm volatile("ldmatrix.sync.aligned.m8n8.x4.shared.b16 {%0,%1,%2,%3}, [%4];"
        : "=r"(r[0]), "=r"(r[1]), "=r"(r[2]), "=r"(r[3]) : "r"(addr));
}
__device__ __forceinline__ void ldsm2(uint32_t* r, uint32_t addr) {
    asm volatile("ldmatrix.sync.aligned.m8n8.x2.shared.b16 {%0,%1}, [%2];"
        : "=r"(r[0]), "=r"(r[1]) : "r"(addr));
}
__device__ __forceinline__ void mma_bf16(float* c, const uint32_t* a, const uint32_t* b) {
    asm volatile("mma.sync.aligned.m16n8k16.row.col.f32.bf16.bf16.f32 "
        "{%0,%1,%2,%3}, {%4,%5,%6,%7}, {%8,%9}, {%0,%1,%2,%3};"
        : "+f"(c[0]), "+f"(c[1]), "+f"(c[2]), "+f"(c[3])
        : "r"(a[0]), "r"(a[1]), "r"(a[2]), "r"(a[3]), "r"(b[0]), "r"(b[1]));
}

// ---------------- init ----------------
__global__ void init_kernel() {
    int t = threadIdx.x;
    if (t < NLAYER*NEXP) { g_cnt[t] = 0; g_imp[t] = 0.f; }
    for (int i = t; i < NTOK; i += blockDim.x)
        g_kvmap[i] = (i >> 9) * SFULL + (i & 511);
}

// ---------------- weight transpose + bf16 hi/lo split: W[K,N] -> out[N,K] ----------------
__global__ void wsplitT(const float* __restrict__ W, __nv_bfloat16* __restrict__ hi,
                        __nv_bfloat16* __restrict__ lo, int K, int N)
{
    __shared__ float t[32][33];
    size_t zo = (size_t)blockIdx.z * K * N;
    const float* Wz = W + zo;
    __nv_bfloat16* hz = hi + zo;
    __nv_bfloat16* lz = lo + zo;
    int n0 = blockIdx.x * 32, k0 = blockIdx.y * 32;
    int tx = threadIdx.x, ty = threadIdx.y;
    #pragma unroll
    for (int i = 0; i < 4; i++)
        t[ty + 8 * i][tx] = Wz[(size_t)(k0 + ty + 8 * i) * N + n0 + tx];
    __syncthreads();
    #pragma unroll
    for (int i = 0; i < 4; i++) {
        float v = t[tx][ty + 8 * i];
        __nv_bfloat16 h = __float2bfloat16(v);
        size_t o = (size_t)(n0 + ty + 8 * i) * K + k0 + tx;
        hz[o] = h;
        lz[o] = __float2bfloat16(v - __bfloat162float(h));
    }
}

// ---------------- activation bf16 hi/lo split ----------------
__global__ void asplit(const float* __restrict__ X, __nv_bfloat16* __restrict__ hi,
                       __nv_bfloat16* __restrict__ lo, int n)
{
    int i = blockIdx.x * 256 + threadIdx.x;
    if (i >= n) return;
    float v = X[i];
    __nv_bfloat16 h = __float2bfloat16(v);
    hi[i] = h;
    lo[i] = __float2bfloat16(v - __bfloat162float(h));
}

// ---------------- bf16 tensor-core GEMM (128x128 tile, mma.sync, 3-pass hi/lo) ----------------
// C[M,N] = A @ W^T; W transposed [N,K] hi/lo. bias/relu/gather/scatter/rowScale/residual.
#define KC 32
#define APITCH 40   // bf16 elems per smem row (80 bytes) -> conflict-free ldmatrix
__global__ __launch_bounds__(256, 2)
void tgemm(const __nv_bfloat16* __restrict__ Ahi, const __nv_bfloat16* __restrict__ Alo,
           const __nv_bfloat16* __restrict__ Bhi, const __nv_bfloat16* __restrict__ Blo,
           float* __restrict__ C, int N, int K, int Mstatic,
           const float* __restrict__ bias, int doRelu,
           const int* __restrict__ gatherA, const int* __restrict__ scatterC,
           const float* __restrict__ rowScale, const float* __restrict__ residual,
           const int* __restrict__ Mdev, int strideB, int strideBias, int strideList)
{
    __shared__ __nv_bfloat16 sAh[128 * APITCH];
    __shared__ __nv_bfloat16 sAl[128 * APITCH];
    __shared__ __nv_bfloat16 sBh[128 * APITCH];
    __shared__ __nv_bfloat16 sBl[128 * APITCH];

    int e = blockIdx.z;
    const __nv_bfloat16* Bhz = Bhi + (size_t)e * strideB;
    const __nv_bfloat16* Blz = Blo + (size_t)e * strideB;
    const float* biasz = bias ? bias + (size_t)e * strideBias : (const float*)0;
    const int* gA = gatherA ? gatherA + (size_t)e * strideList : (const int*)0;
    const int* sC = scatterC ? scatterC + (size_t)e * strideList : (const int*)0;
    int Ml = Mdev ? Mdev[e] : Mstatic;
    int row0 = blockIdx.y * 128;
    if (row0 >= Ml) return;
    int col0 = blockIdx.x * 128;
    int tid = threadIdx.x, wid = tid >> 5, lane = tid & 31;

    // global load assignments: 512 units of 8 bf16; thread does units tid, tid+256
    int arow[2], brow[2], lr[2], lu[2];
    #pragma unroll
    for (int i = 0; i < 2; i++) {
        int unit = tid + i * 256;
        lr[i] = unit >> 2;          // tile row 0..127
        lu[i] = unit & 3;           // 8-elem group in K-chunk
        int gr = row0 + lr[i];
        arow[i] = (gr < Ml) ? (gA ? gA[gr] : gr) : -1;
        brow[i] = col0 + lr[i];
    }

    float acc[4][4][4] = {};
    int wm = wid >> 2, wn = wid & 3;
    int m_base = wm * 64, n_base = wn * 32;

    uint32_t sAhB = s2u(sAh), sAlB = s2u(sAl), sBhB = s2u(sBh), sBlB = s2u(sBl);
    int l8 = lane & 7, mat = lane >> 3;

    int nc = K / KC;
    for (int c = 0; c < nc; c++) {
        int k0 = c * KC;
        #pragma unroll
        for (int i = 0; i < 2; i++) {
            uint32_t soff = (uint32_t)(lr[i] * APITCH + lu[i] * 8);
            uint4 z = make_uint4(0, 0, 0, 0);
            size_t ab = (size_t)arow[i] * K + k0 + lu[i] * 8;
            *(uint4*)&sAh[soff] = (arow[i] >= 0) ? *(const uint4*)(Ahi + ab) : z;
            *(uint4*)&sAl[soff] = (arow[i] >= 0) ? *(const uint4*)(Alo + ab) : z;
            size_t bb = (size_t)brow[i] * K + k0 + lu[i] * 8;
            *(uint4*)&sBh[soff] = *(const uint4*)(Bhz + bb);
            *(uint4*)&sBl[soff] = *(const uint4*)(Blz + bb);
        }
        __syncthreads();

        #pragma unroll
        for (int pass = 0; pass < 3; pass++) {
            uint32_t aB = (pass == 2) ? sAlB : sAhB;
            uint32_t bB = (pass == 1) ? sBlB : sBhB;
            #pragma unroll
            for (int ks = 0; ks < KC / 16; ks++) {
                int kb = ks * 16;
                uint32_t af[4][4], bf[4][2];
                #pragma unroll
                for (int mf = 0; mf < 4; mf++) {
                    int r = m_base + mf * 16 + (mat & 1) * 8 + l8;
                    int cc = kb + (mat >> 1) * 8;
                    ldsm4(af[mf], aB + (uint32_t)(r * APITCH + cc) * 2);
                }
                #pragma unroll
                for (int nf = 0; nf < 4; nf++) {
                    int r = n_base + nf * 8 + l8;
                    int cc = kb + ((lane >> 3) & 1) * 8;
                    ldsm2(bf[nf], bB + (uint32_t)(r * APITCH + cc) * 2);
                }
                #pragma unroll
                for (int mf = 0; mf < 4; mf++)
                    #pragma unroll
                    for (int nf = 0; nf < 4; nf++)
                        mma_bf16(acc[mf][nf], af[mf], bf[nf]);
            }
        }
        __syncthreads();
    }

    // epilogue: c-frag mapping (g=lane>>2, t=lane&3): c0(g,2t) c1(g,2t+1) c2(g+8,2t) c3(g+8,2t+1)
    int g = lane >> 2, t2 = (lane & 3) * 2;
    #pragma unroll
    for (int mf = 0; mf < 4; mf++) {
        #pragma unroll
        for (int half = 0; half < 2; half++) {
            int r = row0 + m_base + mf * 16 + g + half * 8;
            if (r >= Ml) continue;
            int orow = sC ? sC[r] : r;
            float sc = rowScale ? rowScale[orow] : 1.f;
            size_t rb = (size_t)orow * N;
            #pragma unroll
            for (int nf = 0; nf < 4; nf++) {
                int cc = col0 + n_base + nf * 8 + t2;
                float v0 = acc[mf][nf][half * 2 + 0] * sc;
                float v1 = acc[mf][nf][half * 2 + 1] * sc;
                if (biasz) { v0 += biasz[cc]; v1 += biasz[cc + 1]; }
                if (residual) { v0 += residual[rb + cc]; v1 += residual[rb + cc + 1]; }
                if (doRelu) { v0 = fmaxf(v0, 0.f); v1 = fmaxf(v1, 0.f); }
                *(float2*)(C + rb + cc) = make_float2(v0, v1);
            }
        }
    }
}

// ---------------- SIMT GEMM (kept for K=80 cases) ----------------
#define TK 8
__global__ __launch_bounds__(256, 2)
void gemm128(const float* __restrict__ A, const float* __restrict__ Bm,
             float* __restrict__ C, int N, int K, int Mstatic,
             const float* __restrict__ bias, int doRelu,
             const int* __restrict__ gatherA, const int* __restrict__ scatterC,
             const float* __restrict__ rowScale, const float* __restrict__ residual,
             const int* __restrict__ Mdev, int strideB, int strideBias, int strideList)
{
    __shared__ float As[2][TK][132];
    __shared__ float Bs[2][TK][132];
    int e = blockIdx.z;
    const float* Bz = Bm + (size_t)e * strideB;
    const float* biasz = bias ? bias + (size_t)e * strideBias : (const float*)0;
    const int* gA = gatherA ? gatherA + (size_t)e * strideList : (const int*)0;
    const int* sC = scatterC ? scatterC + (size_t)e * strideList : (const int*)0;
    int Ml = Mdev ? Mdev[e] : Mstatic;
    int row0 = blockIdx.y * 128;
    if (row0 >= Ml) return;
    int col0 = blockIdx.x * 128;
    int tid = threadIdx.x;
    int tx = tid & 15, ty = tid >> 4;

    int ar_ = tid >> 1;
    int ah = (tid & 1) * 4;
    int agr = row0 + ar_;
    int arow = -1;
    if (agr < Ml) arow = gA ? gA[agr] : agr;
    int bkr = tid >> 5;
    int bc = (tid & 31) * 4;
    int nk = (K + TK - 1) / TK;

    auto ldA = [&](int k0) {
        float4 v = make_float4(0.f, 0.f, 0.f, 0.f);
        if (arow >= 0) {
            if (k0 + ah + 3 < K) v = *(const float4*)(A + (size_t)arow * K + k0 + ah);
            else {
                const float* p = A + (size_t)arow * K;
                float t[4];
                #pragma unroll
                for (int q = 0; q < 4; q++) t[q] = (k0 + ah + q < K) ? p[k0 + ah + q] : 0.f;
                v = make_float4(t[0], t[1], t[2], t[3]);
            }
        }
        return v;
    };
    auto ldB = [&](int k0) {
        if (k0 + bkr < K) return *(const float4*)(Bz + (size_t)(k0 + bkr) * N + col0 + bc);
        return make_float4(0.f, 0.f, 0.f, 0.f);
    };

    float4 av = ldA(0), bv = ldB(0);
    As[0][ah + 0][ar_] = av.x; As[0][ah + 1][ar_] = av.y;
    As[0][ah + 2][ar_] = av.z; As[0][ah + 3][ar_] = av.w;
    *(float4*)&Bs[0][bkr][bc] = bv;
    __syncthreads();

    float acc[8][8] = {};
    int ty8 = ty * 8, tx8 = tx * 8;
    for (int t = 0; t < nk; t++) {
        int cur = t & 1, nxt = cur ^ 1;
        if (t + 1 < nk) { av = ldA((t + 1) * TK); bv = ldB((t + 1) * TK); }
        #pragma unroll
        for (int k = 0; k < TK; k++) {
            float4 a0 = *(const float4*)&As[cur][k][ty8];
            float4 a1 = *(const float4*)&As[cur][k][ty8 + 4];
            float4 b0 = *(const float4*)&Bs[cur][k][tx8];
            float4 b1 = *(const float4*)&Bs[cur][k][tx8 + 4];
            float aa[8] = {a0.x, a0.y, a0.z, a0.w, a1.x, a1.y, a1.z, a1.w};
            float bb[8] = {b0.x, b0.y, b0.z, b0.w, b1.x, b1.y, b1.z, b1.w};
            #pragma unroll
            for (int i = 0; i < 8; i++)
                #pragma unroll
                for (int j = 0; j < 8; j++)
                    acc[i][j] += aa[i] * bb[j];
        }
        if (t + 1 < nk) {
            As[nxt][ah + 0][ar_] = av.x; As[nxt][ah + 1][ar_] = av.y;
            As[nxt][ah + 2][ar_] = av.z; As[nxt][ah + 3][ar_] = av.w;
            *(float4*)&Bs[nxt][bkr][bc] = bv;
        }
        __syncthreads();
    }
    float bb[8] = {};
    if (biasz) {
        #pragma unroll
        for (int j = 0; j < 8; j++) bb[j] = biasz[col0 + tx8 + j];
    }
    #pragma unroll
    for (int i = 0; i < 8; i++) {
        int r = row0 + ty8 + i;
        if (r >= Ml) continue;
        int orow = sC ? sC[r] : r;
        float sc = rowScale ? rowScale[orow] : 1.f;
        size_t cb = (size_t)orow * N + col0 + tx8;
        float v[8];
        #pragma unroll
        for (int j = 0; j < 8; j++) v[j] = acc[i][j] * sc + bb[j];
        if (residual) {
            float4 r0 = *(const float4*)(residual + cb);
            float4 r1 = *(const float4*)(residual + cb + 4);
            v[0] += r0.x; v[1] += r0.y; v[2] += r0.z; v[3] += r0.w;
            v[4] += r1.x; v[5] += r1.y; v[6] += r1.z; v[7] += r1.w;
        }
        if (doRelu) {
            #pragma unroll
            for (int j = 0; j < 8; j++) v[j] = fmaxf(v[j], 0.f);
        }
        *(float4*)(C + cb) = make_float4(v[0], v[1], v[2], v[3]);
        *(float4*)(C + cb + 4) = make_float4(v[4], v[5], v[6], v[7]);
    }
}

// ---------------- router ----------------
__global__ void router_kernel(const float* __restrict__ embed, const float* __restrict__ R,
                              const int* __restrict__ seqlen, float* __restrict__ gtok,
                              int* __restrict__ lists, int* __restrict__ cnt,
                              float* __restrict__ imp)
{
    int gw = (blockIdx.x * blockDim.x + threadIdx.x) >> 5;
    int lane = threadIdx.x & 31;
    if (gw >= NTOK) return;
    const float* xr = embed + (size_t)gw * DMODEL;
    float l0 = 0, l1 = 0, l2 = 0, l3 = 0;
    for (int d = lane; d < DMODEL; d += 32) {
        float v = xr[d];
        const float* rr = R + d * 4;
        l0 += v * rr[0]; l1 += v * rr[1]; l2 += v * rr[2]; l3 += v * rr[3];
    }
    for (int off = 16; off; off >>= 1) {
        l0 += __shfl_xor_sync(0xffffffffu, l0, off);
        l1 += __shfl_xor_sync(0xffffffffu, l1, off);
        l2 += __shfl_xor_sync(0xffffffffu, l2, off);
        l3 += __shfl_xor_sync(0xffffffffu, l3, off);
    }
    if (lane == 0) {
        float mx = fmaxf(fmaxf(l0, l1), fmaxf(l2, l3));
        float e0 = __expf(l0 - mx), e1 = __expf(l1 - mx);
        float e2 = __expf(l2 - mx), e3 = __expf(l3 - mx);
        float inv = 1.f / (e0 + e1 + e2 + e3);
        float s0 = e0 * inv, s1 = e1 * inv, s2 = e2 * inv, s3 = e3 * inv;
        int em = 0; float gm = s0;
        if (s1 > gm) { gm = s1; em = 1; }
        if (s2 > gm) { gm = s2; em = 2; }
        if (s3 > gm) { gm = s3; em = 3; }
        int b = gw >> 9, t = gw & 511;
        if (t < seqlen[b]) {
            atomicAdd(&imp[0], s0); atomicAdd(&imp[1], s1);
            atomicAdd(&imp[2], s2); atomicAdd(&imp[3], s3);
        }
        gtok[gw] = gm;
        int slot = atomicAdd(&cnt[em], 1);
        lists[em * NTOK + slot] = gw;
    }
}

// ---------------- FSMN ----------------
__global__ void fsmn_kernel(const float* __restrict__ P, const float* __restrict__ fb,
                            const float* __restrict__ fa, const float* __restrict__ skipin,
                            float* __restrict__ outp)
{
    int idx = blockIdx.x * 256 + threadIdx.x;
    if (idx >= NTOK * DMODEL) return;
    int d = idx & 511;
    int t = (idx >> 9) & 511;
    float v = P[idx];
    #pragma unroll
    for (int k = 0; k < 4; k++) {
        int off = (k + 1) * 2;
        if (t - off >= 0) v += fb[k * DMODEL + d] * P[idx - off * DMODEL];
    }
    if (t + 1 < TLEN) v += fa[d] * P[idx + DMODEL];
    if (skipin) v += skipin[idx];
    outp[idx] = v;
}

// ---------------- PE ----------------
__global__ void pe_kernel(float* __restrict__ cur)
{
    int idx = blockIdx.x * 256 + threadIdx.x;
    if (idx >= NTOK * DMODEL) return;
    int d = idx & 511;
    int t = (idx >> 9) & 511;
    int i = d >> 1;
    float div = __expf(-(float)(2 * i) * (9.2103403719761836f / 512.f));
    float a = (float)t * div;
    cur[idx] += (d & 1) ? cosf(a) : sinf(a);
}

// ---------------- memory KV rows ----------------
__global__ void memrows_kernel(const float* __restrict__ mk, const float* __restrict__ mv,
                               float* __restrict__ Kb, float* __restrict__ Vb)
{
    int idx = blockIdx.x * 256 + threadIdx.x;
    if (idx >= BATCH * MMEM * DMODEL) return;
    int d = idx & 511;
    int r = idx >> 9;
    int m = r & 63;
    int b = r >> 6;
    size_t dst = ((size_t)(b * SFULL + TLEN + m)) * DMODEL + d;
    Kb[dst] = mk[m * DMODEL + d];
    Vb[dst] = mv[m * DMODEL + d];
}

// ---------------- flash attention ----------------
#define ATTN_SMEM (4*64*65*4)
__global__ void attn_kernel(const float* __restrict__ Q, const float* __restrict__ Kb,
                            const float* __restrict__ Vb, const int* __restrict__ seqlen,
                            float* __restrict__ O)
{
    extern __shared__ float sm[];
    float* Qs = sm;
    float* Ks = sm + 64 * 65;
    float* Vs = sm + 2 * 64 * 65;
    float* Ps = sm + 3 * 64 * 65;
    int q0 = blockIdx.x * 64, h = blockIdx.y, b = blockIdx.z;
    int tid = threadIdx.x, tx = tid & 15, ty = tid >> 4;
    int slen = seqlen[b];

    #pragma unroll
    for (int i = 0; i < 16; i++) {
        int idx = i * 256 + tid;
        int r = idx >> 6, d = idx & 63;
        Qs[r * 65 + d] = Q[((size_t)(b * TLEN + q0 + r)) * DMODEL + h * DH + d];
    }
    float acc[4][4] = {};
    float m_i[4], l_i[4] = {};
    #pragma unroll
    for (int i = 0; i < 4; i++) m_i[i] = -1e30f;

    for (int s0 = 0; s0 < SFULL; s0 += 64) {
        __syncthreads();
        #pragma unroll
        for (int i = 0; i < 16; i++) {
            int idx = i * 256 + tid;
            int r = idx >> 6, d = idx & 63;
            size_t base = ((size_t)(b * SFULL + s0 + r)) * DMODEL + h * DH + d;
            Ks[r * 65 + d] = Kb[base];
            Vs[r * 65 + d] = Vb[base];
        }
        __syncthreads();
        float st[4][4] = {};
        #pragma unroll 8
        for (int d = 0; d < 64; d++) {
            float a[4], bbv[4];
            #pragma unroll
            for (int i = 0; i < 4; i++) a[i] = Qs[(ty + 16 * i) * 65 + d];
            #pragma unroll
            for (int j = 0; j < 4; j++) bbv[j] = Ks[(tx + 16 * j) * 65 + d];
            #pragma unroll
            for (int i = 0; i < 4; i++)
                #pragma unroll
                for (int j = 0; j < 4; j++)
                    st[i][j] += a[i] * bbv[j];
        }
        #pragma unroll
        for (int i = 0; i < 4; i++) {
            #pragma unroll
            for (int j = 0; j < 4; j++) {
                st[i][j] *= 0.125f;
                int sg = s0 + tx + 16 * j;
                if (sg < TLEN && sg >= slen) st[i][j] = -1e9f;
            }
            float mr = fmaxf(fmaxf(st[i][0], st[i][1]), fmaxf(st[i][2], st[i][3]));
            mr = fmaxf(mr, __shfl_xor_sync(0xffffffffu, mr, 1));
            mr = fmaxf(mr, __shfl_xor_sync(0xffffffffu, mr, 2));
            mr = fmaxf(mr, __shfl_xor_sync(0xffffffffu, mr, 4));
            mr = fmaxf(mr, __shfl_xor_sync(0xffffffffu, mr, 8));
            float mn = fmaxf(m_i[i], mr);
            float lr = 0.f;
            #pragma unroll
            for (int j = 0; j < 4; j++) {
                float pv = __expf(st[i][j] - mn);
                Ps[(ty + 16 * i) * 65 + tx + 16 * j] = pv;
                lr += pv;
            }
            lr += __shfl_xor_sync(0xffffffffu, lr, 1);
            lr += __shfl_xor_sync(0xffffffffu, lr, 2);
            lr += __shfl_xor_sync(0xffffffffu, lr, 4);
            lr += __shfl_xor_sync(0xffffffffu, lr, 8);
            float scl = __expf(m_i[i] - mn);
            l_i[i] = l_i[i] * scl + lr;
            m_i[i] = mn;
            #pragma unroll
            for (int j = 0; j < 4; j++) acc[i][j] *= scl;
        }
        __syncthreads();
        #pragma unroll 8
        for (int s = 0; s < 64; s++) {
            float a[4], bbv[4];
            #pragma unroll
            for (int i = 0; i < 4; i++) a[i] = Ps[(ty + 16 * i) * 65 + s];
            #pragma unroll
            for (int j = 0; j < 4; j++) bbv[j] = Vs[s * 65 + tx + 16 * j];
            #pragma unroll
            for (int i = 0; i < 4; i++)
                #pragma unroll
                for (int j = 0; j < 4; j++)
                    acc[i][j] += a[i] * bbv[j];
        }
    }
    #pragma unroll
    for (int i = 0; i < 4; i++) {
        float inv = 1.f / l_i[i];
        #pragma unroll
        for (int j = 0; j < 4; j++)
            O[((size_t)(b * TLEN + q0 + ty + 16 * i)) * DMODEL + h * DH + tx + 16 * j] =
                acc[i][j] * inv;
    }
}

// ---------------- layernorm ----------------
__global__ void ln_kernel(const float* __restrict__ X, float* __restrict__ Y,
                          const float* __restrict__ gw, const float* __restrict__ bw)
{
    __shared__ float red[128];
    int row = blockIdx.x, tid = threadIdx.x;
    const float* xr = X + (size_t)row * DMODEL;
    float v[4]; float s = 0.f;
    #pragma unroll
    for (int i = 0; i < 4; i++) { v[i] = xr[tid + 128 * i]; s += v[i]; }
    red[tid] = s; __syncthreads();
    for (int off = 64; off > 0; off >>= 1) {
        if (tid < off) red[tid] += red[tid + off];
        __syncthreads();
    }
    float mu = red[0] * (1.f / 512.f);
    __syncthreads();
    float s2 = 0.f;
    #pragma unroll
    for (int i = 0; i < 4; i++) { float d = v[i] - mu; s2 += d * d; }
    red[tid] = s2; __syncthreads();
    for (int off = 64; off > 0; off >>= 1) {
        if (tid < off) red[tid] += red[tid + off];
        __syncthreads();
    }
    float inv = rsqrtf(red[0] * (1.f / 512.f) + 1e-5f);
    #pragma unroll
    for (int i = 0; i < 4; i++) {
        int c = tid + 128 * i;
        Y[(size_t)row * DMODEL + c] = (v[i] - mu) * inv * gw[c] + bw[c];
    }
}

// ---------------- aux ----------------
__global__ void aux_kernel(float* __restrict__ dst)
{
    float tot = 0.f;
    for (int l = 0; l < NLAYER; l++) {
        float m = 0.f;
        for (int e = 0; e < NEXP; e++) m += g_imp[l * 4 + e];
        m *= 0.25f;
        float var = 0.f;
        for (int e = 0; e < NEXP; e++) { float d = g_imp[l * 4 + e] - m; var += d * d; }
        var *= 0.25f;
        tot += var / (m * m + 1e-9f);
    }
    dst[0] = tot;
}

// ---------------- launcher ----------------
extern "C" void kernel_launch(void* const* d_in, const int* in_sizes, int n_in,
                              void* d_out, int out_size)
{
    const float* x         = (const float*)d_in[0];
    const int*   seq       = (const int*)  d_in[1];
    const float* emb_w1    = (const float*)d_in[2];
    const float* emb_b1    = (const float*)d_in[3];
    const float* emb_w2    = (const float*)d_in[4];
    const float* emb_wo    = (const float*)d_in[5];
    const float* f0_w1     = (const float*)d_in[6];
    const float* f0_b1     = (const float*)d_in[7];
    const float* f0_w2     = (const float*)d_in[8];
    const float* f0_router = (const float*)d_in[9];
    const float* f0_fb     = (const float*)d_in[10];
    const float* f0_fa     = (const float*)d_in[11];
    const float* f_w1      = (const float*)d_in[12];
    const float* f_b1      = (const float*)d_in[13];
    const float* f_w2      = (const float*)d_in[14];
    const float* f_router  = (const float*)d_in[15];
    const float* f_fb      = (const float*)d_in[16];
    const float* f_fa      = (const float*)d_in[17];
    const float* wq        = (const float*)d_in[18];
    const float* wk        = (const float*)d_in[19];
    const float* wv        = (const float*)d_in[20];
    const float* wvo       = (const float*)d_in[21];
    const float* mk        = (const float*)d_in[22];
    const float* mv        = (const float*)d_in[23];
    const float* lng       = (const float*)d_in[24];
    const float* lnb       = (const float*)d_in[25];
    const float* out_w     = (const float*)d_in[26];
    const float* out_b     = (const float*)d_in[27];
    float* out = (float*)d_out;

    float *embed, *hid, *cur, *p, *q, *kb, *vb, *ao, *tmp, *gtok, *imp;
    int *cnt, *lists, *kvmap;
    __nv_bfloat16 *whi, *wlo, *ahi, *alo;
    cudaGetSymbolAddress((void**)&embed, g_embed);
    cudaGetSymbolAddress((void**)&hid,   g_hid);
    cudaGetSymbolAddress((void**)&cur,   g_cur);
    cudaGetSymbolAddress((void**)&p,     g_p);
    cudaGetSymbolAddress((void**)&q,     g_q);
    cudaGetSymbolAddress((void**)&kb,    g_k);
    cudaGetSymbolAddress((void**)&vb,    g_v);
    cudaGetSymbolAddress((void**)&ao,    g_ao);
    cudaGetSymbolAddress((void**)&tmp,   g_tmp);
    cudaGetSymbolAddress((void**)&gtok,  g_gtok);
    cudaGetSymbolAddress((void**)&imp,   g_imp);
    cudaGetSymbolAddress((void**)&cnt,   g_cnt);
    cudaGetSymbolAddress((void**)&lists, g_lists);
    cudaGetSymbolAddress((void**)&kvmap, g_kvmap);
    cudaGetSymbolAddress((void**)&whi,   g_whi);
    cudaGetSymbolAddress((void**)&wlo,   g_wlo);
    cudaGetSymbolAddress((void**)&ahi,   g_ahi);
    cudaGetSymbolAddress((void**)&alo,   g_alo);

    cudaFuncSetAttribute(attn_kernel, cudaFuncAttributeMaxDynamicSharedMemorySize, ATTN_SMEM);

    auto SG = [](const float* A, const float* Bm, float* C, int M, int N, int K,
                 const float* bias, int relu, const int* ga, const int* sc,
                 const float* rs, const float* res, const int* Md,
                 int E = 1, int sB = 0, int sBias = 0, int sList = 0) {
        dim3 grid((N + 127) / 128, (M + 127) / 128, E);
        gemm128<<<grid, 256>>>(A, Bm, C, N, K, M, bias, relu, ga, sc, rs, res, Md,
                               sB, sBias, sList);
    };
    auto TG = [&](unsigned woff, float* C, int M, int N, int K,
                  const float* bias, int relu, const int* ga, const int* sc,
                  const float* rs, const float* res, const int* Md,
                  int E = 1, int sB = 0, int sBias = 0, int sList = 0) {
        dim3 grid(N / 128, (M + 127) / 128, E);
        tgemm<<<grid, 256>>>(ahi, alo, whi + woff, wlo + woff, C, N, K, M,
                             bias, relu, ga, sc, rs, res, Md, sB, sBias, sList);
    };
    auto ASPLIT = [&](const float* X, int n) {
        asplit<<<(n + 255) / 256, 256>>>(X, ahi, alo, n);
    };
    auto WT = [&](const float* W, unsigned off, int K, int N, int Z) {
        wsplitT<<<dim3(N / 32, K / 32, Z), dim3(32, 8)>>>(W, whi + off, wlo + off, K, N);
    };

    init_kernel<<<1, 1024>>>();

    // weight transposes + bf16 split
    WT(emb_w2, OFF_EMBW2, 1024, 512, 1);
    WT(emb_wo, OFF_EMBWO, 512, 4096, 1);
    WT(f0_w2,  OFF_F0W2, 1024, 512, 4);
    WT(f_w1,   OFF_FW1, 512, 1024, 28);
    WT(f_w2,   OFF_FW2, 1024, 512, 28);
    WT(wq,     OFF_WQ, 512, 512, 2);
    WT(wk,     OFF_WK, 512, 512, 2);
    WT(wv,     OFF_WV, 512, 512, 2);
    WT(wvo,    OFF_WO, 512, 512, 2);
    WT(out_w,  OFF_OUTW, 512, 4096, 1);

    // embed sub-network + embed_out
    SG(x, emb_w1, hid, NTOK, DHID, DIN, emb_b1, 1, 0, 0, 0, 0, 0);
    ASPLIT(hid, NTOK * DHID);
    TG(OFF_EMBW2, embed, NTOK, DMODEL, DHID, 0, 0, 0, 0, 0, 0, 0);
    ASPLIT(embed, NTOK * DMODEL);
    TG(OFF_EMBWO, out + (size_t)NTOK * DOUT, NTOK, DOUT, DMODEL, 0, 0, 0, 0, 0, 0, 0);

    for (int l = 0; l < NLAYER; l++) {
        const float* Rl = (l == 0) ? f0_router : f_router + (size_t)(l - 1) * DMODEL * NEXP;
        router_kernel<<<NTOK / 8, 256>>>(embed, Rl, seq, gtok, lists, cnt + l * 4, imp + l * 4);

        if (l == 0) {
            SG(x, f0_w1, hid, NTOK, DHID, DIN, f0_b1, 1, lists, lists, 0, 0, cnt,
               NEXP, DIN * DHID, DHID, NTOK);
            ASPLIT(hid, NTOK * DHID);
            TG(OFF_F0W2, p, NTOK, DMODEL, DHID, 0, 0, lists, lists, gtok, 0, cnt,
               NEXP, DMODEL * DHID, 0, NTOK);
        } else {
            ASPLIT(cur, NTOK * DMODEL);
            TG(OFF_FW1 + (unsigned)(l - 1) * 4u * DMODEL * DHID, hid, NTOK, DHID, DMODEL,
               f_b1 + (size_t)(l - 1) * NEXP * DHID, 1, lists, lists, 0, 0, cnt + l * 4,
               NEXP, DMODEL * DHID, DHID, NTOK);
            ASPLIT(hid, NTOK * DHID);
            TG(OFF_FW2 + (unsigned)(l - 1) * 4u * DHID * DMODEL, p, NTOK, DMODEL, DHID,
               0, 0, lists, lists, gtok, 0, cnt + l * 4,
               NEXP, DHID * DMODEL, 0, NTOK);
        }
        const float* fbL = (l == 0) ? f0_fb : f_fb + (size_t)(l - 1) * 4 * DMODEL;
        const float* faL = (l == 0) ? f0_fa : f_fa + (size_t)(l - 1) * DMODEL;
        fsmn_kernel<<<NTOK * DMODEL / 256, 256>>>(p, fbL, faL,
                                                  (l == 0) ? (const float*)0 : cur, cur);

        if (l == 3) pe_kernel<<<NTOK * DMODEL / 256, 256>>>(cur);

        if (l == 3 || l == 7) {
            int bi = l / 4;
            unsigned wo = (unsigned)bi * 512u * 512u;
            ASPLIT(cur, NTOK * DMODEL);
            TG(OFF_WQ + wo, q, NTOK, DMODEL, DMODEL, 0, 0, 0, 0, 0, 0, 0);
            TG(OFF_WK + wo, kb, NTOK, DMODEL, DMODEL, 0, 0, 0, kvmap, 0, 0, 0);
            TG(OFF_WV + wo, vb, NTOK, DMODEL, DMODEL, 0, 0, 0, kvmap, 0, 0, 0);
            memrows_kernel<<<BATCH * MMEM * DMODEL / 256, 256>>>(
                mk + (size_t)bi * MMEM * DMODEL, mv + (size_t)bi * MMEM * DMODEL, kb, vb);
            attn_kernel<<<dim3(TLEN / 64, NHEAD, BATCH), 256, ATTN_SMEM>>>(q, kb, vb, seq, ao);
            ASPLIT(ao, NTOK * DMODEL);
            TG(OFF_WO + wo, tmp, NTOK, DMODEL, DMODEL, 0, 0, 0, 0, 0, cur, 0);
            ln_kernel<<<NTOK, 128>>>(tmp, cur, lng + bi * DMODEL, lnb + bi * DMODEL);
        }
    }

    ASPLIT(cur, NTOK * DMODEL);
    TG(OFF_OUTW, out, NTOK, DOUT, DMODEL, out_b, 0, 0, 0, 0, 0, 0);
    aux_kernel<<<1, 1>>>(out + 2 * (size_t)NTOK * DOUT);
}

// round 5
// speedup vs baseline: 3.6153x; 1.0947x over previous
#include <cuda_runtime.h>
#include <cuda_bf16.h>
#include <math.h>
#include <stdint.h>

// ---------------- problem constants ----------------
#define BATCH 4
#define TLEN  512
#define NTOK  (BATCH*TLEN)        // 2048
#define DIN   80
#define DOUT  4096
#define DMODEL 512
#define DHID  1024
#define NEXP  4
#define NLAYER 8
#define NHEAD 8
#define DH    64
#define MMEM  64
#define SFULL (TLEN+MMEM)         // 576

// ---------------- device scratch (static, no allocs) ----------------
__device__ float g_embed[NTOK*DMODEL];
__device__ float g_cur[NTOK*DMODEL];
__device__ float g_p[NTOK*DMODEL];
__device__ float g_q[NTOK*DMODEL];
__device__ float g_k[BATCH*SFULL*DMODEL];
__device__ float g_v[BATCH*SFULL*DMODEL];
__device__ float g_ao[NTOK*DMODEL];
__device__ float g_tmp[NTOK*DMODEL];
__device__ float g_gtok[NTOK];
__device__ float g_imp[NLAYER*NEXP];
__device__ int   g_cnt[NLAYER*NEXP];
__device__ int   g_lists[NEXP*NTOK];
__device__ int   g_kvmap[NTOK];

// bf16 weight pools (transposed to [N,K]) and activation split buffers
#define WPOOL (40u*1024u*1024u)
__device__ __nv_bfloat16 g_whi[WPOOL];
__device__ __nv_bfloat16 g_wlo[WPOOL];
__device__ __nv_bfloat16 g_ahi[NTOK*DMODEL];   // split of d=512 activations
__device__ __nv_bfloat16 g_alo[NTOK*DMODEL];
__device__ __nv_bfloat16 g_bhi[NTOK*DHID];     // split of d=1024 activations (hid)
__device__ __nv_bfloat16 g_blo[NTOK*DHID];

// pool offsets (elements)
#define OFF_EMBW2 0u
#define OFF_EMBWO (OFF_EMBW2 + 512u*1024u)
#define OFF_F0W2  (OFF_EMBWO + 4096u*512u)
#define OFF_FW1   (OFF_F0W2 + 4u*512u*1024u)
#define OFF_FW2   (OFF_FW1 + 28u*1024u*512u)
#define OFF_WQ    (OFF_FW2 + 28u*512u*1024u)
#define OFF_WK    (OFF_WQ + 2u*512u*512u)
#define OFF_WV    (OFF_WK + 2u*512u*512u)
#define OFF_WO    (OFF_WV + 2u*512u*512u)
#define OFF_OUTW  (OFF_WO + 2u*512u*512u)

// ---------------- warp-MMA helpers ----------------
__device__ __forceinline__ uint32_t s2u(const void* p) {
    uint32_t a;
    asm("{ .reg .u64 t; cvta.to.shared.u64 t, %1; cvt.u32.u64 %0, t; }" : "=r"(a) : "l"(p));
    return a;
}
__device__ __forceinline__ void ldsm4(uint32_t* r, uint32_t addr) {
    asm volatile("ldmatrix.sync.aligned.m8n8.x4.shared.b16 {%0,%1,%2,%3}, [%4];"
        : "=r"(r[0]), "=r"(r[1]), "=r"(r[2]), "=r"(r[3]) : "r"(addr));
}
__device__ __forceinline__ void ldsm2(uint32_t* r, uint32_t addr) {
    asm volatile("ldmatrix.sync.aligned.m8n8.x2.shared.b16 {%0,%1}, [%2];"
        : "=r"(r[0]), "=r"(r[1]) : "r"(addr));
}
__device__ __forceinline__ void ldsm2t(uint32_t* r, uint32_t addr) {
    asm volatile("ldmatrix.sync.aligned.m8n8.x2.trans.shared.b16 {%0,%1}, [%2];"
        : "=r"(r[0]), "=r"(r[1]) : "r"(addr));
}
__device__ __forceinline__ void mma_bf16(float* c, const uint32_t* a, const uint32_t* b) {
    asm volatile("mma.sync.aligned.m16n8k16.row.col.f32.bf16.bf16.f32 "
        "{%0,%1,%2,%3}, {%4,%5,%6,%7}, {%8,%9}, {%0,%1,%2,%3};"
        : "+f"(c[0]), "+f"(c[1]), "+f"(c[2]), "+f"(c[3])
        : "r"(a[0]), "r"(a[1]), "r"(a[2]), "r"(a[3]), "r"(b[0]), "r"(b[1]));
}
__device__ __forceinline__ uint32_t packbf(float a, float b) {
    __nv_bfloat162 h = __floats2bfloat162_rn(a, b);
    return *(uint32_t*)&h;
}
__device__ __forceinline__ float bfres(float x) {
    return x - __bfloat162float(__float2bfloat16(x));
}

// ---------------- init ----------------
__global__ void init_kernel() {
    int t = threadIdx.x;
    if (t < NLAYER*NEXP) { g_cnt[t] = 0; g_imp[t] = 0.f; }
    for (int i = t; i < NTOK; i += blockDim.x)
        g_kvmap[i] = (i >> 9) * SFULL + (i & 511);
}

// ---------------- weight transpose + bf16 hi/lo split: W[K,N] -> out[N,K] ----------------
__global__ void wsplitT(const float* __restrict__ W, __nv_bfloat16* __restrict__ hi,
                        __nv_bfloat16* __restrict__ lo, int K, int N)
{
    __shared__ float t[32][33];
    size_t zo = (size_t)blockIdx.z * K * N;
    const float* Wz = W + zo;
    __nv_bfloat16* hz = hi + zo;
    __nv_bfloat16* lz = lo + zo;
    int n0 = blockIdx.x * 32, k0 = blockIdx.y * 32;
    int tx = threadIdx.x, ty = threadIdx.y;
    #pragma unroll
    for (int i = 0; i < 4; i++)
        t[ty + 8 * i][tx] = Wz[(size_t)(k0 + ty + 8 * i) * N + n0 + tx];
    __syncthreads();
    #pragma unroll
    for (int i = 0; i < 4; i++) {
        float v = t[tx][ty + 8 * i];
        __nv_bfloat16 h = __float2bfloat16(v);
        size_t o = (size_t)(n0 + ty + 8 * i) * K + k0 + tx;
        hz[o] = h;
        lz[o] = __float2bfloat16(v - __bfloat162float(h));
    }
}

// ---------------- activation bf16 hi/lo split ----------------
__global__ void asplit(const float* __restrict__ X, __nv_bfloat16* __restrict__ hi,
                       __nv_bfloat16* __restrict__ lo, int n)
{
    int i = blockIdx.x * 256 + threadIdx.x;
    if (i >= n) return;
    float v = X[i];
    __nv_bfloat16 h = __float2bfloat16(v);
    hi[i] = h;
    lo[i] = __float2bfloat16(v - __bfloat162float(h));
}

// ---------------- bf16 tensor-core GEMM (128x128 tile, mma.sync, 3-pass hi/lo) ----------------
#define KC 32
#define APITCH 40
__global__ __launch_bounds__(256, 2)
void tgemm(const __nv_bfloat16* __restrict__ Ahi, const __nv_bfloat16* __restrict__ Alo,
           const __nv_bfloat16* __restrict__ Bhi, const __nv_bfloat16* __restrict__ Blo,
           float* __restrict__ C,
           __nv_bfloat16* __restrict__ Chi, __nv_bfloat16* __restrict__ Clo,
           int N, int K, int Mstatic,
           const float* __restrict__ bias, int doRelu,
           const int* __restrict__ gatherA, const int* __restrict__ scatterC,
           const float* __restrict__ rowScale, const float* __restrict__ residual,
           const int* __restrict__ Mdev, int strideB, int strideBias, int strideList)
{
    __shared__ __nv_bfloat16 sAh[128 * APITCH];
    __shared__ __nv_bfloat16 sAl[128 * APITCH];
    __shared__ __nv_bfloat16 sBh[128 * APITCH];
    __shared__ __nv_bfloat16 sBl[128 * APITCH];

    int e = blockIdx.z;
    const __nv_bfloat16* Bhz = Bhi + (size_t)e * strideB;
    const __nv_bfloat16* Blz = Blo + (size_t)e * strideB;
    const float* biasz = bias ? bias + (size_t)e * strideBias : (const float*)0;
    const int* gA = gatherA ? gatherA + (size_t)e * strideList : (const int*)0;
    const int* sC = scatterC ? scatterC + (size_t)e * strideList : (const int*)0;
    int Ml = Mdev ? Mdev[e] : Mstatic;
    int row0 = blockIdx.y * 128;
    if (row0 >= Ml) return;
    int col0 = blockIdx.x * 128;
    int tid = threadIdx.x, wid = tid >> 5, lane = tid & 31;

    int arow[2], brow[2], lr[2], lu[2];
    #pragma unroll
    for (int i = 0; i < 2; i++) {
        int unit = tid + i * 256;
        lr[i] = unit >> 2;
        lu[i] = unit & 3;
        int gr = row0 + lr[i];
        arow[i] = (gr < Ml) ? (gA ? gA[gr] : gr) : -1;
        brow[i] = col0 + lr[i];
    }

    float acc[4][4][4] = {};
    int wm = wid >> 2, wn = wid & 3;
    int m_base = wm * 64, n_base = wn * 32;

    uint32_t sAhB = s2u(sAh), sAlB = s2u(sAl), sBhB = s2u(sBh), sBlB = s2u(sBl);
    int l8 = lane & 7, mat = lane >> 3;

    int nc = K / KC;
    for (int c = 0; c < nc; c++) {
        int k0 = c * KC;
        #pragma unroll
        for (int i = 0; i < 2; i++) {
            uint32_t soff = (uint32_t)(lr[i] * APITCH + lu[i] * 8);
            uint4 z = make_uint4(0, 0, 0, 0);
            size_t ab = (size_t)arow[i] * K + k0 + lu[i] * 8;
            *(uint4*)&sAh[soff] = (arow[i] >= 0) ? *(const uint4*)(Ahi + ab) : z;
            *(uint4*)&sAl[soff] = (arow[i] >= 0) ? *(const uint4*)(Alo + ab) : z;
            size_t bb = (size_t)brow[i] * K + k0 + lu[i] * 8;
            *(uint4*)&sBh[soff] = *(const uint4*)(Bhz + bb);
            *(uint4*)&sBl[soff] = *(const uint4*)(Blz + bb);
        }
        __syncthreads();

        #pragma unroll
        for (int pass = 0; pass < 3; pass++) {
            uint32_t aB = (pass == 2) ? sAlB : sAhB;
            uint32_t bB = (pass == 1) ? sBlB : sBhB;
            #pragma unroll
            for (int ks = 0; ks < KC / 16; ks++) {
                int kb = ks * 16;
                uint32_t af[4][4], bf[4][2];
                #pragma unroll
                for (int mf = 0; mf < 4; mf++) {
                    int r = m_base + mf * 16 + (mat & 1) * 8 + l8;
                    int cc = kb + (mat >> 1) * 8;
                    ldsm4(af[mf], aB + (uint32_t)(r * APITCH + cc) * 2);
                }
                #pragma unroll
                for (int nf = 0; nf < 4; nf++) {
                    int r = n_base + nf * 8 + l8;
                    int cc = kb + ((lane >> 3) & 1) * 8;
                    ldsm2(bf[nf], bB + (uint32_t)(r * APITCH + cc) * 2);
                }
                #pragma unroll
                for (int mf = 0; mf < 4; mf++)
                    #pragma unroll
                    for (int nf = 0; nf < 4; nf++)
                        mma_bf16(acc[mf][nf], af[mf], bf[nf]);
            }
        }
        __syncthreads();
    }

    int g = lane >> 2, t2 = (lane & 3) * 2;
    #pragma unroll
    for (int mf = 0; mf < 4; mf++) {
        #pragma unroll
        for (int half = 0; half < 2; half++) {
            int r = row0 + m_base + mf * 16 + g + half * 8;
            if (r >= Ml) continue;
            int orow = sC ? sC[r] : r;
            float sc = rowScale ? rowScale[orow] : 1.f;
            size_t rb = (size_t)orow * N;
            #pragma unroll
            for (int nf = 0; nf < 4; nf++) {
                int cc = col0 + n_base + nf * 8 + t2;
                float v0 = acc[mf][nf][half * 2 + 0] * sc;
                float v1 = acc[mf][nf][half * 2 + 1] * sc;
                if (biasz) { v0 += biasz[cc]; v1 += biasz[cc + 1]; }
                if (residual) { v0 += residual[rb + cc]; v1 += residual[rb + cc + 1]; }
                if (doRelu) { v0 = fmaxf(v0, 0.f); v1 = fmaxf(v1, 0.f); }
                if (C) *(float2*)(C + rb + cc) = make_float2(v0, v1);
                if (Chi) {
                    __nv_bfloat16 h0 = __float2bfloat16(v0), h1 = __float2bfloat16(v1);
                    __nv_bfloat162 hh; hh.x = h0; hh.y = h1;
                    *(__nv_bfloat162*)(Chi + rb + cc) = hh;
                    __nv_bfloat162 ll;
                    ll.x = __float2bfloat16(v0 - __bfloat162float(h0));
                    ll.y = __float2bfloat16(v1 - __bfloat162float(h1));
                    *(__nv_bfloat162*)(Clo + rb + cc) = ll;
                }
            }
        }
    }
}

// ---------------- SIMT GEMM (K=80 cases) ----------------
#define TK 8
__global__ __launch_bounds__(256, 2)
void gemm128(const float* __restrict__ A, const float* __restrict__ Bm,
             float* __restrict__ C,
             __nv_bfloat16* __restrict__ Chi, __nv_bfloat16* __restrict__ Clo,
             int N, int K, int Mstatic,
             const float* __restrict__ bias, int doRelu,
             const int* __restrict__ gatherA, const int* __restrict__ scatterC,
             const int* __restrict__ Mdev, int strideB, int strideBias, int strideList)
{
    __shared__ float As[2][TK][132];
    __shared__ float Bs[2][TK][132];
    int e = blockIdx.z;
    const float* Bz = Bm + (size_t)e * strideB;
    const float* biasz = bias ? bias + (size_t)e * strideBias : (const float*)0;
    const int* gA = gatherA ? gatherA + (size_t)e * strideList : (const int*)0;
    const int* sC = scatterC ? scatterC + (size_t)e * strideList : (const int*)0;
    int Ml = Mdev ? Mdev[e] : Mstatic;
    int row0 = blockIdx.y * 128;
    if (row0 >= Ml) return;
    int col0 = blockIdx.x * 128;
    int tid = threadIdx.x;
    int tx = tid & 15, ty = tid >> 4;

    int ar_ = tid >> 1;
    int ah = (tid & 1) * 4;
    int agr = row0 + ar_;
    int arow = -1;
    if (agr < Ml) arow = gA ? gA[agr] : agr;
    int bkr = tid >> 5;
    int bc = (tid & 31) * 4;
    int nk = (K + TK - 1) / TK;

    auto ldA = [&](int k0) {
        float4 v = make_float4(0.f, 0.f, 0.f, 0.f);
        if (arow >= 0) {
            if (k0 + ah + 3 < K) v = *(const float4*)(A + (size_t)arow * K + k0 + ah);
            else {
                const float* p = A + (size_t)arow * K;
                float t[4];
                #pragma unroll
                for (int q = 0; q < 4; q++) t[q] = (k0 + ah + q < K) ? p[k0 + ah + q] : 0.f;
                v = make_float4(t[0], t[1], t[2], t[3]);
            }
        }
        return v;
    };
    auto ldB = [&](int k0) {
        if (k0 + bkr < K) return *(const float4*)(Bz + (size_t)(k0 + bkr) * N + col0 + bc);
        return make_float4(0.f, 0.f, 0.f, 0.f);
    };

    float4 av = ldA(0), bv = ldB(0);
    As[0][ah + 0][ar_] = av.x; As[0][ah + 1][ar_] = av.y;
    As[0][ah + 2][ar_] = av.z; As[0][ah + 3][ar_] = av.w;
    *(float4*)&Bs[0][bkr][bc] = bv;
    __syncthreads();

    float acc[8][8] = {};
    int ty8 = ty * 8, tx8 = tx * 8;
    for (int t = 0; t < nk; t++) {
        int cur = t & 1, nxt = cur ^ 1;
        if (t + 1 < nk) { av = ldA((t + 1) * TK); bv = ldB((t + 1) * TK); }
        #pragma unroll
        for (int k = 0; k < TK; k++) {
            float4 a0 = *(const float4*)&As[cur][k][ty8];
            float4 a1 = *(const float4*)&As[cur][k][ty8 + 4];
            float4 b0 = *(const float4*)&Bs[cur][k][tx8];
            float4 b1 = *(const float4*)&Bs[cur][k][tx8 + 4];
            float aa[8] = {a0.x, a0.y, a0.z, a0.w, a1.x, a1.y, a1.z, a1.w};
            float bb[8] = {b0.x, b0.y, b0.z, b0.w, b1.x, b1.y, b1.z, b1.w};
            #pragma unroll
            for (int i = 0; i < 8; i++)
                #pragma unroll
                for (int j = 0; j < 8; j++)
                    acc[i][j] += aa[i] * bb[j];
        }
        if (t + 1 < nk) {
            As[nxt][ah + 0][ar_] = av.x; As[nxt][ah + 1][ar_] = av.y;
            As[nxt][ah + 2][ar_] = av.z; As[nxt][ah + 3][ar_] = av.w;
            *(float4*)&Bs[nxt][bkr][bc] = bv;
        }
        __syncthreads();
    }
    float bb[8] = {};
    if (biasz) {
        #pragma unroll
        for (int j = 0; j < 8; j++) bb[j] = biasz[col0 + tx8 + j];
    }
    #pragma unroll
    for (int i = 0; i < 8; i++) {
        int r = row0 + ty8 + i;
        if (r >= Ml) continue;
        int orow = sC ? sC[r] : r;
        size_t cb = (size_t)orow * N + col0 + tx8;
        float v[8];
        #pragma unroll
        for (int j = 0; j < 8; j++) {
            v[j] = acc[i][j] + bb[j];
            if (doRelu) v[j] = fmaxf(v[j], 0.f);
        }
        if (C) {
            *(float4*)(C + cb) = make_float4(v[0], v[1], v[2], v[3]);
            *(float4*)(C + cb + 4) = make_float4(v[4], v[5], v[6], v[7]);
        }
        if (Chi) {
            #pragma unroll
            for (int j = 0; j < 8; j += 2) {
                __nv_bfloat16 h0 = __float2bfloat16(v[j]), h1 = __float2bfloat16(v[j + 1]);
                __nv_bfloat162 hh; hh.x = h0; hh.y = h1;
                *(__nv_bfloat162*)(Chi + cb + j) = hh;
                __nv_bfloat162 ll;
                ll.x = __float2bfloat16(v[j] - __bfloat162float(h0));
                ll.y = __float2bfloat16(v[j + 1] - __bfloat162float(h1));
                *(__nv_bfloat162*)(Clo + cb + j) = ll;
            }
        }
    }
}

// ---------------- router ----------------
__global__ void router_kernel(const float* __restrict__ embed, const float* __restrict__ R,
                              const int* __restrict__ seqlen, float* __restrict__ gtok,
                              int* __restrict__ lists, int* __restrict__ cnt,
                              float* __restrict__ imp)
{
    int gw = (blockIdx.x * blockDim.x + threadIdx.x) >> 5;
    int lane = threadIdx.x & 31;
    if (gw >= NTOK) return;
    const float* xr = embed + (size_t)gw * DMODEL;
    float l0 = 0, l1 = 0, l2 = 0, l3 = 0;
    for (int d = lane; d < DMODEL; d += 32) {
        float v = xr[d];
        const float* rr = R + d * 4;
        l0 += v * rr[0]; l1 += v * rr[1]; l2 += v * rr[2]; l3 += v * rr[3];
    }
    for (int off = 16; off; off >>= 1) {
        l0 += __shfl_xor_sync(0xffffffffu, l0, off);
        l1 += __shfl_xor_sync(0xffffffffu, l1, off);
        l2 += __shfl_xor_sync(0xffffffffu, l2, off);
        l3 += __shfl_xor_sync(0xffffffffu, l3, off);
    }
    if (lane == 0) {
        float mx = fmaxf(fmaxf(l0, l1), fmaxf(l2, l3));
        float e0 = __expf(l0 - mx), e1 = __expf(l1 - mx);
        float e2 = __expf(l2 - mx), e3 = __expf(l3 - mx);
        float inv = 1.f / (e0 + e1 + e2 + e3);
        float s0 = e0 * inv, s1 = e1 * inv, s2 = e2 * inv, s3 = e3 * inv;
        int em = 0; float gm = s0;
        if (s1 > gm) { gm = s1; em = 1; }
        if (s2 > gm) { gm = s2; em = 2; }
        if (s3 > gm) { gm = s3; em = 3; }
        int b = gw >> 9, t = gw & 511;
        if (t < seqlen[b]) {
            atomicAdd(&imp[0], s0); atomicAdd(&imp[1], s1);
            atomicAdd(&imp[2], s2); atomicAdd(&imp[3], s3);
        }
        gtok[gw] = gm;
        int slot = atomicAdd(&cnt[em], 1);
        lists[em * NTOK + slot] = gw;
    }
}

// ---------------- FSMN (emits split(cur) too) ----------------
__global__ void fsmn_kernel(const float* __restrict__ P, const float* __restrict__ fb,
                            const float* __restrict__ fa, const float* __restrict__ skipin,
                            float* __restrict__ outp)
{
    int idx = blockIdx.x * 256 + threadIdx.x;
    if (idx >= NTOK * DMODEL) return;
    int d = idx & 511;
    int t = (idx >> 9) & 511;
    float v = P[idx];
    #pragma unroll
    for (int k = 0; k < 4; k++) {
        int off = (k + 1) * 2;
        if (t - off >= 0) v += fb[k * DMODEL + d] * P[idx - off * DMODEL];
    }
    if (t + 1 < TLEN) v += fa[d] * P[idx + DMODEL];
    if (skipin) v += skipin[idx];
    outp[idx] = v;
    __nv_bfloat16 h = __float2bfloat16(v);
    g_ahi[idx] = h;
    g_alo[idx] = __float2bfloat16(v - __bfloat162float(h));
}

// ---------------- PE (updates split too) ----------------
__global__ void pe_kernel(float* __restrict__ cur)
{
    int idx = blockIdx.x * 256 + threadIdx.x;
    if (idx >= NTOK * DMODEL) return;
    int d = idx & 511;
    int t = (idx >> 9) & 511;
    int i = d >> 1;
    float div = __expf(-(float)(2 * i) * (9.2103403719761836f / 512.f));
    float a = (float)t * div;
    float v = cur[idx] + ((d & 1) ? cosf(a) : sinf(a));
    cur[idx] = v;
    __nv_bfloat16 h = __float2bfloat16(v);
    g_ahi[idx] = h;
    g_alo[idx] = __float2bfloat16(v - __bfloat162float(h));
}

// ---------------- memory KV rows ----------------
__global__ void memrows_kernel(const float* __restrict__ mk, const float* __restrict__ mv,
                               float* __restrict__ Kb, float* __restrict__ Vb)
{
    int idx = blockIdx.x * 256 + threadIdx.x;
    if (idx >= BATCH * MMEM * DMODEL) return;
    int d = idx & 511;
    int r = idx >> 9;
    int m = r & 63;
    int b = r >> 6;
    size_t dst = ((size_t)(b * SFULL + TLEN + m)) * DMODEL + d;
    Kb[dst] = mk[m * DMODEL + d];
    Vb[dst] = mv[m * DMODEL + d];
}

// ---------------- tensor-core flash attention ----------------
// 128 q rows / block, 8 warps x 16 rows, 64-wide S tiles, 3-pass bf16 hi/lo.
#define AT_PITCH 72
#define AT_QH 0
#define AT_QL (128*AT_PITCH)
#define AT_KH (2*128*AT_PITCH)
#define AT_KL (AT_KH + 64*AT_PITCH)
#define AT_VH (AT_KL + 64*AT_PITCH)
#define AT_VL (AT_VH + 64*AT_PITCH)
#define ATTN_SMEM ((AT_VL + 64*AT_PITCH) * 2)
__global__ __launch_bounds__(256, 1)
void attn_mma(const float* __restrict__ Q, const float* __restrict__ Kb,
              const float* __restrict__ Vb, const int* __restrict__ seqlen,
              float* __restrict__ O)
{
    extern __shared__ __nv_bfloat16 sb[];
    int q0 = blockIdx.x * 128, h = blockIdx.y, b = blockIdx.z;
    int tid = threadIdx.x, wid = tid >> 5, lane = tid & 31;
    int slen = seqlen[b];
    int l8 = lane & 7, mat = lane >> 3, g = lane >> 2, t2 = (lane & 3) * 2;
    int mrow = wid * 16;

    // load Q tile (128x64) fp32 -> hi/lo bf16 smem
    #pragma unroll
    for (int i = 0; i < 8; i++) {
        int u = i * 256 + tid;
        int r = u >> 4, c = (u & 15) * 4;
        float4 v = *(const float4*)(Q + ((size_t)(b * TLEN + q0 + r)) * DMODEL + h * DH + c);
        float f[4] = {v.x, v.y, v.z, v.w};
        #pragma unroll
        for (int j = 0; j < 4; j++) {
            __nv_bfloat16 hh = __float2bfloat16(f[j]);
            sb[AT_QH + r * AT_PITCH + c + j] = hh;
            sb[AT_QL + r * AT_PITCH + c + j] = __float2bfloat16(f[j] - __bfloat162float(hh));
        }
    }

    uint32_t QhB = s2u(sb + AT_QH), QlB = s2u(sb + AT_QL);
    uint32_t KhB = s2u(sb + AT_KH), KlB = s2u(sb + AT_KL);
    uint32_t VhB = s2u(sb + AT_VH), VlB = s2u(sb + AT_VL);

    float o[8][4] = {};
    float m0 = -1e30f, m1 = -1e30f, l0 = 0.f, l1 = 0.f;

    for (int s0 = 0; s0 < SFULL; s0 += 64) {
        __syncthreads();
        #pragma unroll
        for (int i = 0; i < 4; i++) {
            int u = i * 256 + tid;
            int r = u >> 4, c = (u & 15) * 4;
            size_t base = ((size_t)(b * SFULL + s0 + r)) * DMODEL + h * DH + c;
            float4 kv = *(const float4*)(Kb + base);
            float4 vv = *(const float4*)(Vb + base);
            float fk[4] = {kv.x, kv.y, kv.z, kv.w};
            float fv[4] = {vv.x, vv.y, vv.z, vv.w};
            #pragma unroll
            for (int j = 0; j < 4; j++) {
                __nv_bfloat16 hk = __float2bfloat16(fk[j]);
                sb[AT_KH + r * AT_PITCH + c + j] = hk;
                sb[AT_KL + r * AT_PITCH + c + j] = __float2bfloat16(fk[j] - __bfloat162float(hk));
                __nv_bfloat16 hv = __float2bfloat16(fv[j]);
                sb[AT_VH + r * AT_PITCH + c + j] = hv;
                sb[AT_VL + r * AT_PITCH + c + j] = __float2bfloat16(fv[j] - __bfloat162float(hv));
            }
        }
        __syncthreads();

        // S = Q @ K^T  (16 x 64 per warp)
        float sc[8][4] = {};
        #pragma unroll
        for (int pass = 0; pass < 3; pass++) {
            uint32_t aB = (pass == 2) ? QlB : QhB;
            uint32_t bB = (pass == 1) ? KlB : KhB;
            #pragma unroll
            for (int kc = 0; kc < 4; kc++) {
                uint32_t af[4];
                ldsm4(af, aB + (uint32_t)((mrow + (mat & 1) * 8 + l8) * AT_PITCH
                                          + kc * 16 + (mat >> 1) * 8) * 2);
                #pragma unroll
                for (int nf = 0; nf < 8; nf++) {
                    uint32_t bf2[2];
                    ldsm2(bf2, bB + (uint32_t)((nf * 8 + l8) * AT_PITCH
                                               + kc * 16 + ((lane >> 3) & 1) * 8) * 2);
                    mma_bf16(sc[nf], af, bf2);
                }
            }
        }

        // scale + mask + online softmax
        float rm0 = -1e30f, rm1 = -1e30f;
        #pragma unroll
        for (int nf = 0; nf < 8; nf++) {
            #pragma unroll
            for (int j = 0; j < 4; j++) {
                int sg = s0 + nf * 8 + t2 + (j & 1);
                float v = sc[nf][j] * 0.125f;
                sc[nf][j] = (sg >= slen && sg < TLEN) ? -1e9f : v;
            }
            rm0 = fmaxf(rm0, fmaxf(sc[nf][0], sc[nf][1]));
            rm1 = fmaxf(rm1, fmaxf(sc[nf][2], sc[nf][3]));
        }
        rm0 = fmaxf(rm0, __shfl_xor_sync(0xffffffffu, rm0, 1));
        rm0 = fmaxf(rm0, __shfl_xor_sync(0xffffffffu, rm0, 2));
        rm1 = fmaxf(rm1, __shfl_xor_sync(0xffffffffu, rm1, 1));
        rm1 = fmaxf(rm1, __shfl_xor_sync(0xffffffffu, rm1, 2));
        float mn0 = fmaxf(m0, rm0), mn1 = fmaxf(m1, rm1);
        float e0 = __expf(m0 - mn0), e1 = __expf(m1 - mn1);
        float rs0 = 0.f, rs1 = 0.f;
        #pragma unroll
        for (int nf = 0; nf < 8; nf++) {
            sc[nf][0] = __expf(sc[nf][0] - mn0); rs0 += sc[nf][0];
            sc[nf][1] = __expf(sc[nf][1] - mn0); rs0 += sc[nf][1];
            sc[nf][2] = __expf(sc[nf][2] - mn1); rs1 += sc[nf][2];
            sc[nf][3] = __expf(sc[nf][3] - mn1); rs1 += sc[nf][3];
        }
        rs0 += __shfl_xor_sync(0xffffffffu, rs0, 1);
        rs0 += __shfl_xor_sync(0xffffffffu, rs0, 2);
        rs1 += __shfl_xor_sync(0xffffffffu, rs1, 1);
        rs1 += __shfl_xor_sync(0xffffffffu, rs1, 2);
        l0 = l0 * e0 + rs0; l1 = l1 * e1 + rs1;
        m0 = mn0; m1 = mn1;
        #pragma unroll
        for (int nf = 0; nf < 8; nf++) {
            o[nf][0] *= e0; o[nf][1] *= e0; o[nf][2] *= e1; o[nf][3] *= e1;
        }

        // P hi/lo a-frags (reuse S c-frags directly)
        uint32_t phi[4][4], plo[4][4];
        #pragma unroll
        for (int kc = 0; kc < 4; kc++) {
            float* A = sc[2 * kc];
            float* B = sc[2 * kc + 1];
            phi[kc][0] = packbf(A[0], A[1]); phi[kc][1] = packbf(A[2], A[3]);
            phi[kc][2] = packbf(B[0], B[1]); phi[kc][3] = packbf(B[2], B[3]);
            plo[kc][0] = packbf(bfres(A[0]), bfres(A[1]));
            plo[kc][1] = packbf(bfres(A[2]), bfres(A[3]));
            plo[kc][2] = packbf(bfres(B[0]), bfres(B[1]));
            plo[kc][3] = packbf(bfres(B[2]), bfres(B[3]));
        }

        // O += P @ V   (V via ldmatrix.trans)
        #pragma unroll
        for (int pass = 0; pass < 3; pass++) {
            uint32_t vB = (pass == 1) ? VlB : VhB;
            #pragma unroll
            for (int kc = 0; kc < 4; kc++) {
                const uint32_t* pf = (pass == 2) ? plo[kc] : phi[kc];
                #pragma unroll
                for (int nf = 0; nf < 8; nf++) {
                    uint32_t bf2[2];
                    ldsm2t(bf2, vB + (uint32_t)((kc * 16 + ((lane >> 3) & 1) * 8 + l8) * AT_PITCH
                                                + nf * 8) * 2);
                    mma_bf16(o[nf], pf, bf2);
                }
            }
        }
    }

    float inv0 = 1.f / l0, inv1 = 1.f / l1;
    int r0 = q0 + mrow + g;
    #pragma unroll
    for (int nf = 0; nf < 8; nf++) {
        int cc = h * DH + nf * 8 + t2;
        *(float2*)(O + ((size_t)(b * TLEN + r0)) * DMODEL + cc) =
            make_float2(o[nf][0] * inv0, o[nf][1] * inv0);
        *(float2*)(O + ((size_t)(b * TLEN + r0 + 8)) * DMODEL + cc) =
            make_float2(o[nf][2] * inv1, o[nf][3] * inv1);
    }
}

// ---------------- layernorm (emits split(cur) too) ----------------
__global__ void ln_kernel(const float* __restrict__ X, float* __restrict__ Y,
                          const float* __restrict__ gw, const float* __restrict__ bw)
{
    __shared__ float red[128];
    int row = blockIdx.x, tid = threadIdx.x;
    const float* xr = X + (size_t)row * DMODEL;
    float v[4]; float s = 0.f;
    #pragma unroll
    for (int i = 0; i < 4; i++) { v[i] = xr[tid + 128 * i]; s += v[i]; }
    red[tid] = s; __syncthreads();
    for (int off = 64; off > 0; off >>= 1) {
        if (tid < off) red[tid] += red[tid + off];
        __syncthreads();
    }
    float mu = red[0] * (1.f / 512.f);
    __syncthreads();
    float s2 = 0.f;
    #pragma unroll
    for (int i = 0; i < 4; i++) { float d = v[i] - mu; s2 += d * d; }
    red[tid] = s2; __syncthreads();
    for (int off = 64; off > 0; off >>= 1) {
        if (tid < off) red[tid] += red[tid + off];
        __syncthreads();
    }
    float inv = rsqrtf(red[0] * (1.f / 512.f) + 1e-5f);
    #pragma unroll
    for (int i = 0; i < 4; i++) {
        int c = tid + 128 * i;
        float y = (v[i] - mu) * inv * gw[c] + bw[c];
        size_t idx = (size_t)row * DMODEL + c;
        Y[idx] = y;
        __nv_bfloat16 h = __float2bfloat16(y);
        g_ahi[idx] = h;
        g_alo[idx] = __float2bfloat16(y - __bfloat162float(h));
    }
}

// ---------------- aux ----------------
__global__ void aux_kernel(float* __restrict__ dst)
{
    float tot = 0.f;
    for (int l = 0; l < NLAYER; l++) {
        float m = 0.f;
        for (int e = 0; e < NEXP; e++) m += g_imp[l * 4 + e];
        m *= 0.25f;
        float var = 0.f;
        for (int e = 0; e < NEXP; e++) { float d = g_imp[l * 4 + e] - m; var += d * d; }
        var *= 0.25f;
        tot += var / (m * m + 1e-9f);
    }
    dst[0] = tot;
}

// ---------------- launcher ----------------
extern "C" void kernel_launch(void* const* d_in, const int* in_sizes, int n_in,
                              void* d_out, int out_size)
{
    const float* x         = (const float*)d_in[0];
    const int*   seq       = (const int*)  d_in[1];
    const float* emb_w1    = (const float*)d_in[2];
    const float* emb_b1    = (const float*)d_in[3];
    const float* emb_w2    = (const float*)d_in[4];
    const float* emb_wo    = (const float*)d_in[5];
    const float* f0_w1     = (const float*)d_in[6];
    const float* f0_b1     = (const float*)d_in[7];
    const float* f0_w2     = (const float*)d_in[8];
    const float* f0_router = (const float*)d_in[9];
    const float* f0_fb     = (const float*)d_in[10];
    const float* f0_fa     = (const float*)d_in[11];
    const float* f_w1      = (const float*)d_in[12];
    const float* f_b1      = (const float*)d_in[13];
    const float* f_w2      = (const float*)d_in[14];
    const float* f_router  = (const float*)d_in[15];
    const float* f_fb      = (const float*)d_in[16];
    const float* f_fa      = (const float*)d_in[17];
    const float* wq        = (const float*)d_in[18];
    const float* wk        = (const float*)d_in[19];
    const float* wv        = (const float*)d_in[20];
    const float* wvo       = (const float*)d_in[21];
    const float* mk        = (const float*)d_in[22];
    const float* mv        = (const float*)d_in[23];
    const float* lng       = (const float*)d_in[24];
    const float* lnb       = (const float*)d_in[25];
    const float* out_w     = (const float*)d_in[26];
    const float* out_b     = (const float*)d_in[27];
    float* out = (float*)d_out;

    float *embed, *cur, *p, *q, *kb, *vb, *ao, *tmp, *gtok, *imp;
    int *cnt, *lists, *kvmap;
    __nv_bfloat16 *whi, *wlo, *ahi, *alo, *bhi, *blo;
    cudaGetSymbolAddress((void**)&embed, g_embed);
    cudaGetSymbolAddress((void**)&cur,   g_cur);
    cudaGetSymbolAddress((void**)&p,     g_p);
    cudaGetSymbolAddress((void**)&q,     g_q);
    cudaGetSymbolAddress((void**)&kb,    g_k);
    cudaGetSymbolAddress((void**)&vb,    g_v);
    cudaGetSymbolAddress((void**)&ao,    g_ao);
    cudaGetSymbolAddress((void**)&tmp,   g_tmp);
    cudaGetSymbolAddress((void**)&gtok,  g_gtok);
    cudaGetSymbolAddress((void**)&imp,   g_imp);
    cudaGetSymbolAddress((void**)&cnt,   g_cnt);
    cudaGetSymbolAddress((void**)&lists, g_lists);
    cudaGetSymbolAddress((void**)&kvmap, g_kvmap);
    cudaGetSymbolAddress((void**)&whi,   g_whi);
    cudaGetSymbolAddress((void**)&wlo,   g_wlo);
    cudaGetSymbolAddress((void**)&ahi,   g_ahi);
    cudaGetSymbolAddress((void**)&alo,   g_alo);
    cudaGetSymbolAddress((void**)&bhi,   g_bhi);
    cudaGetSymbolAddress((void**)&blo,   g_blo);

    cudaFuncSetAttribute(attn_mma, cudaFuncAttributeMaxDynamicSharedMemorySize, ATTN_SMEM);

    auto TG = [&](unsigned woff, const __nv_bfloat16* Ah, const __nv_bfloat16* Al,
                  float* C, __nv_bfloat16* Ch, __nv_bfloat16* Cl,
                  int M, int N, int K,
                  const float* bias, int relu, const int* ga, const int* sc,
                  const float* rs, const float* res, const int* Md,
                  int E = 1, int sB = 0, int sBias = 0, int sList = 0) {
        dim3 grid(N / 128, (M + 127) / 128, E);
        tgemm<<<grid, 256>>>(Ah, Al, whi + woff, wlo + woff, C, Ch, Cl, N, K, M,
                             bias, relu, ga, sc, rs, res, Md, sB, sBias, sList);
    };
    auto WT = [&](const float* W, unsigned off, int K, int N, int Z) {
        wsplitT<<<dim3(N / 32, K / 32, Z), dim3(32, 8)>>>(W, whi + off, wlo + off, K, N);
    };

    init_kernel<<<1, 1024>>>();

    WT(emb_w2, OFF_EMBW2, 1024, 512, 1);
    WT(emb_wo, OFF_EMBWO, 512, 4096, 1);
    WT(f0_w2,  OFF_F0W2, 1024, 512, 4);
    WT(f_w1,   OFF_FW1, 512, 1024, 28);
    WT(f_w2,   OFF_FW2, 1024, 512, 28);
    WT(wq,     OFF_WQ, 512, 512, 2);
    WT(wk,     OFF_WK, 512, 512, 2);
    WT(wv,     OFF_WV, 512, 512, 2);
    WT(wvo,    OFF_WO, 512, 512, 2);
    WT(out_w,  OFF_OUTW, 512, 4096, 1);

    // embed sub-network: x @ w1 (K=80, SIMT, split out) -> @ w2 -> embed (+split) -> embed_out
    gemm128<<<dim3(8, 16, 1), 256>>>(x, emb_w1, 0, bhi, blo, DHID, DIN, NTOK,
                                     emb_b1, 1, 0, 0, 0, 0, 0, 0);
    TG(OFF_EMBW2, bhi, blo, embed, ahi, alo, NTOK, DMODEL, DHID, 0, 0, 0, 0, 0, 0, 0);
    TG(OFF_EMBWO, ahi, alo, out + (size_t)NTOK * DOUT, 0, 0, NTOK, DOUT, DMODEL,
       0, 0, 0, 0, 0, 0, 0);

    for (int l = 0; l < NLAYER; l++) {
        const float* Rl = (l == 0) ? f0_router : f_router + (size_t)(l - 1) * DMODEL * NEXP;
        router_kernel<<<NTOK / 8, 256>>>(embed, Rl, seq, gtok, lists, cnt + l * 4, imp + l * 4);

        if (l == 0) {
            gemm128<<<dim3(8, 16, NEXP), 256>>>(x, f0_w1, 0, bhi, blo, DHID, DIN, NTOK,
                                                f0_b1, 1, lists, lists, cnt,
                                                DIN * DHID, DHID, NTOK);
            TG(OFF_F0W2, bhi, blo, p, 0, 0, NTOK, DMODEL, DHID, 0, 0, lists, lists,
               gtok, 0, cnt, NEXP, DMODEL * DHID, 0, NTOK);
        } else {
            TG(OFF_FW1 + (unsigned)(l - 1) * 4u * DMODEL * DHID, ahi, alo,
               0, bhi, blo, NTOK, DHID, DMODEL,
               f_b1 + (size_t)(l - 1) * NEXP * DHID, 1, lists, lists, 0, 0, cnt + l * 4,
               NEXP, DMODEL * DHID, DHID, NTOK);
            TG(OFF_FW2 + (unsigned)(l - 1) * 4u * DHID * DMODEL, bhi, blo,
               p, 0, 0, NTOK, DMODEL, DHID,
               0, 0, lists, lists, gtok, 0, cnt + l * 4,
               NEXP, DHID * DMODEL, 0, NTOK);
        }
        const float* fbL = (l == 0) ? f0_fb : f_fb + (size_t)(l - 1) * 4 * DMODEL;
        const float* faL = (l == 0) ? f0_fa : f_fa + (size_t)(l - 1) * DMODEL;
        fsmn_kernel<<<NTOK * DMODEL / 256, 256>>>(p, fbL, faL,
                                                  (l == 0) ? (const float*)0 : cur, cur);

        if (l == 3) pe_kernel<<<NTOK * DMODEL / 256, 256>>>(cur);

        if (l == 3 || l == 7) {
            int bi = l / 4;
            unsigned wo = (unsigned)bi * 512u * 512u;
            TG(OFF_WQ + wo, ahi, alo, q, 0, 0, NTOK, DMODEL, DMODEL, 0, 0, 0, 0, 0, 0, 0);
            TG(OFF_WK + wo, ahi, alo, kb, 0, 0, NTOK, DMODEL, DMODEL, 0, 0, 0, kvmap, 0, 0, 0);
            TG(OFF_WV + wo, ahi, alo, vb, 0, 0, NTOK, DMODEL, DMODEL, 0, 0, 0, kvmap, 0, 0, 0);
            memrows_kernel<<<BATCH * MMEM * DMODEL / 256, 256>>>(
                mk + (size_t)bi * MMEM * DMODEL, mv + (size_t)bi * MMEM * DMODEL, kb, vb);
            attn_mma<<<dim3(TLEN / 128, NHEAD, BATCH), 256, ATTN_SMEM>>>(q, kb, vb, seq, ao);
            asplit<<<NTOK * DMODEL / 256, 256>>>(ao, ahi, alo, NTOK * DMODEL);
            TG(OFF_WO + wo, ahi, alo, tmp, 0, 0, NTOK, DMODEL, DMODEL, 0, 0, 0, 0, 0, cur, 0);
            ln_kernel<<<NTOK, 128>>>(tmp, cur, lng + bi * DMODEL, lnb + bi * DMODEL);
        }
    }

    TG(OFF_OUTW, ahi, alo, out, 0, 0, NTOK, DOUT, DMODEL, out_b, 0, 0, 0, 0, 0, 0);
    aux_kernel<<<1, 1>>>(out + 2 * (size_t)NTOK * DOUT);
}

// round 6
// speedup vs baseline: 4.2756x; 1.1826x over previous
#include <cuda_runtime.h>
#include <cuda_bf16.h>
#include <math.h>
#include <stdint.h>

// ---------------- problem constants ----------------
#define BATCH 4
#define TLEN  512
#define NTOK  (BATCH*TLEN)        // 2048
#define DIN   80
#define DOUT  4096
#define DMODEL 512
#define DHID  1024
#define NEXP  4
#define NLAYER 8
#define NHEAD 8
#define DH    64
#define MMEM  64
#define SFULL (TLEN+MMEM)         // 576

// ---------------- device scratch (static, no allocs) ----------------
__device__ float g_embed[NTOK*DMODEL];
__device__ float g_cur[NTOK*DMODEL];
__device__ float g_p[NTOK*DMODEL];
__device__ float g_q[NTOK*DMODEL];
__device__ float g_k[BATCH*SFULL*DMODEL];
__device__ float g_v[BATCH*SFULL*DMODEL];
__device__ float g_ao[NTOK*DMODEL];
__device__ float g_tmp[NTOK*DMODEL];
__device__ float g_gtok[NTOK];
__device__ float g_imp[NLAYER*NEXP];
__device__ int   g_cnt[NLAYER*NEXP];
__device__ int   g_lists[NEXP*NTOK];
__device__ int   g_kvmap[NTOK];

#define WPOOL (40u*1024u*1024u)
__device__ __nv_bfloat16 g_whi[WPOOL];
__device__ __nv_bfloat16 g_wlo[WPOOL];
__device__ __nv_bfloat16 g_ahi[NTOK*DMODEL];
__device__ __nv_bfloat16 g_alo[NTOK*DMODEL];
__device__ __nv_bfloat16 g_bhi[NTOK*DHID];
__device__ __nv_bfloat16 g_blo[NTOK*DHID];

#define OFF_EMBW2 0u
#define OFF_EMBWO (OFF_EMBW2 + 512u*1024u)
#define OFF_F0W2  (OFF_EMBWO + 4096u*512u)
#define OFF_FW1   (OFF_F0W2 + 4u*512u*1024u)
#define OFF_FW2   (OFF_FW1 + 28u*1024u*512u)
#define OFF_WQ    (OFF_FW2 + 28u*512u*1024u)
#define OFF_WK    (OFF_WQ + 2u*512u*512u)
#define OFF_WV    (OFF_WK + 2u*512u*512u)
#define OFF_WO    (OFF_WV + 2u*512u*512u)
#define OFF_OUTW  (OFF_WO + 2u*512u*512u)

// ---------------- helpers ----------------
__device__ __forceinline__ uint32_t s2u(const void* p) {
    uint32_t a;
    asm("{ .reg .u64 t; cvta.to.shared.u64 t, %1; cvt.u32.u64 %0, t; }" : "=r"(a) : "l"(p));
    return a;
}
__device__ __forceinline__ void ldsm4(uint32_t* r, uint32_t addr) {
    asm volatile("ldmatrix.sync.aligned.m8n8.x4.shared.b16 {%0,%1,%2,%3}, [%4];"
        : "=r"(r[0]), "=r"(r[1]), "=r"(r[2]), "=r"(r[3]) : "r"(addr));
}
__device__ __forceinline__ void ldsm2(uint32_t* r, uint32_t addr) {
    asm volatile("ldmatrix.sync.aligned.m8n8.x2.shared.b16 {%0,%1}, [%2];"
        : "=r"(r[0]), "=r"(r[1]) : "r"(addr));
}
__device__ __forceinline__ void ldsm2t(uint32_t* r, uint32_t addr) {
    asm volatile("ldmatrix.sync.aligned.m8n8.x2.trans.shared.b16 {%0,%1}, [%2];"
        : "=r"(r[0]), "=r"(r[1]) : "r"(addr));
}
__device__ __forceinline__ void mma_bf16(float* c, const uint32_t* a, const uint32_t* b) {
    asm volatile("mma.sync.aligned.m16n8k16.row.col.f32.bf16.bf16.f32 "
        "{%0,%1,%2,%3}, {%4,%5,%6,%7}, {%8,%9}, {%0,%1,%2,%3};"
        : "+f"(c[0]), "+f"(c[1]), "+f"(c[2]), "+f"(c[3])
        : "r"(a[0]), "r"(a[1]), "r"(a[2]), "r"(a[3]), "r"(b[0]), "r"(b[1]));
}
__device__ __forceinline__ uint32_t packbf(float a, float b) {
    __nv_bfloat162 h = __floats2bfloat162_rn(a, b);
    return *(uint32_t*)&h;
}
__device__ __forceinline__ float bfres(float x) {
    return x - __bfloat162float(__float2bfloat16(x));
}
#define CPA(dst, src, sz) asm volatile("cp.async.ca.shared.global [%0], [%1], 16, %2;" \
    :: "r"(dst), "l"(src), "r"(sz))
#define CPC() asm volatile("cp.async.commit_group;" ::: "memory")
#define CPW() asm volatile("cp.async.wait_group 0;" ::: "memory")

// ---------------- init ----------------
__global__ void init_kernel() {
    int t = threadIdx.x;
    if (t < NLAYER*NEXP) { g_cnt[t] = 0; g_imp[t] = 0.f; }
    for (int i = t; i < NTOK; i += blockDim.x)
        g_kvmap[i] = (i >> 9) * SFULL + (i & 511);
}

// ---------------- weight transpose + split (64x64 vectorized) ----------------
__global__ void wsplitT(const float* __restrict__ W, __nv_bfloat16* __restrict__ hi,
                        __nv_bfloat16* __restrict__ lo, int K, int N)
{
    __shared__ float s[64][65];
    size_t zo = (size_t)blockIdx.z * K * N;
    int n0 = blockIdx.x * 64, k0 = blockIdx.y * 64;
    int tid = threadIdx.x;
    #pragma unroll
    for (int i = 0; i < 4; i++) {
        int idx = i * 256 + tid;
        int kr = idx >> 4, c4 = (idx & 15) * 4;
        float4 v = *(const float4*)(W + zo + (size_t)(k0 + kr) * N + n0 + c4);
        s[kr][c4] = v.x; s[kr][c4 + 1] = v.y; s[kr][c4 + 2] = v.z; s[kr][c4 + 3] = v.w;
    }
    __syncthreads();
    #pragma unroll
    for (int i = 0; i < 4; i++) {
        int idx = i * 256 + tid;
        int n = idx >> 4, q = (idx & 15) * 4;
        float v0 = s[q][n], v1 = s[q + 1][n], v2 = s[q + 2][n], v3 = s[q + 3][n];
        __nv_bfloat162 h01 = __floats2bfloat162_rn(v0, v1);
        __nv_bfloat162 h23 = __floats2bfloat162_rn(v2, v3);
        __nv_bfloat162 l01 = __floats2bfloat162_rn(v0 - __bfloat162float(h01.x),
                                                   v1 - __bfloat162float(h01.y));
        __nv_bfloat162 l23 = __floats2bfloat162_rn(v2 - __bfloat162float(h23.x),
                                                   v3 - __bfloat162float(h23.y));
        size_t o = zo + (size_t)(n0 + n) * K + k0 + q;
        uint2 hw, lw;
        hw.x = *(uint32_t*)&h01; hw.y = *(uint32_t*)&h23;
        lw.x = *(uint32_t*)&l01; lw.y = *(uint32_t*)&l23;
        *(uint2*)(hi + o) = hw;
        *(uint2*)(lo + o) = lw;
    }
}

// ---------------- activation split ----------------
__global__ void asplit(const float* __restrict__ X, __nv_bfloat16* __restrict__ hi,
                       __nv_bfloat16* __restrict__ lo, int n)
{
    int i = blockIdx.x * 256 + threadIdx.x;
    if (i >= n) return;
    float v = X[i];
    __nv_bfloat16 h = __float2bfloat16(v);
    hi[i] = h;
    lo[i] = __float2bfloat16(v - __bfloat162float(h));
}

// ---------------- bf16 tensor-core GEMM: cp.async pipelined, frag-reuse 3-pass ----------------
#define KC 32
#define PITCHB 80                 // bytes per smem row (40 bf16)
#define TILEB (128*PITCHB)        // 10240
#define STAGEB (4*TILEB)          // 40960
#define TG_SMEM (2*STAGEB)        // 81920
__global__ __launch_bounds__(256, 2)
void tgemm(const __nv_bfloat16* __restrict__ Ahi, const __nv_bfloat16* __restrict__ Alo,
           const __nv_bfloat16* __restrict__ Bhi, const __nv_bfloat16* __restrict__ Blo,
           float* __restrict__ C,
           __nv_bfloat16* __restrict__ Chi, __nv_bfloat16* __restrict__ Clo,
           int N, int K, int Mstatic,
           const float* __restrict__ bias, int doRelu,
           const int* __restrict__ gatherA, const int* __restrict__ scatterC,
           const float* __restrict__ rowScale, const float* __restrict__ residual,
           const int* __restrict__ Mdev, int strideB, int strideBias, int strideList)
{
    extern __shared__ char smem[];
    int e = blockIdx.z;
    const __nv_bfloat16* Bhz = Bhi + (size_t)e * strideB;
    const __nv_bfloat16* Blz = Blo + (size_t)e * strideB;
    const float* biasz = bias ? bias + (size_t)e * strideBias : (const float*)0;
    const int* gA = gatherA ? gatherA + (size_t)e * strideList : (const int*)0;
    const int* sC = scatterC ? scatterC + (size_t)e * strideList : (const int*)0;
    int Ml = Mdev ? Mdev[e] : Mstatic;
    int row0 = blockIdx.y * 128;
    if (row0 >= Ml) return;
    int col0 = blockIdx.x * 128;
    int tid = threadIdx.x, wid = tid >> 5, lane = tid & 31;
    uint32_t sb = s2u(smem);

    int arow[2], brow[2], lr[2], lu[2];
    #pragma unroll
    for (int i = 0; i < 2; i++) {
        int unit = tid + i * 256;
        lr[i] = unit >> 2;
        lu[i] = unit & 3;
        int gr = row0 + lr[i];
        arow[i] = (gr < Ml) ? (gA ? gA[gr] : gr) : -1;
        brow[i] = col0 + lr[i];
    }

    auto issue = [&](int c, int stage) {
        int k0 = c * KC;
        uint32_t base = sb + stage * STAGEB;
        #pragma unroll
        for (int i = 0; i < 2; i++) {
            uint32_t off = (uint32_t)(lr[i] * PITCHB + lu[i] * 16);
            int ar = arow[i] >= 0 ? arow[i] : 0;
            uint32_t asz = arow[i] >= 0 ? 16u : 0u;
            const char* ah = (const char*)(Ahi + (size_t)ar * K + k0 + lu[i] * 8);
            const char* al = (const char*)(Alo + (size_t)ar * K + k0 + lu[i] * 8);
            const char* bh = (const char*)(Bhz + (size_t)brow[i] * K + k0 + lu[i] * 8);
            const char* bl = (const char*)(Blz + (size_t)brow[i] * K + k0 + lu[i] * 8);
            CPA(base + off, ah, asz);
            CPA(base + TILEB + off, al, asz);
            CPA(base + 2u * TILEB + off, bh, 16u);
            CPA(base + 3u * TILEB + off, bl, 16u);
        }
    };

    float acc[4][4][4] = {};
    int wm = wid >> 2, wn = wid & 3;
    int m_base = wm * 64, n_base = wn * 32;
    int l8 = lane & 7, mat = lane >> 3;

    int nc = K / KC;
    issue(0, 0); CPC();

    for (int c = 0; c < nc; c++) {
        CPW();
        __syncthreads();
        if (c + 1 < nc) { issue(c + 1, (c + 1) & 1); CPC(); }

        uint32_t base = sb + (c & 1) * STAGEB;
        uint32_t ahB = base, alB = base + TILEB;
        uint32_t bhB = base + 2u * TILEB, blB = base + 3u * TILEB;
        #pragma unroll
        for (int ks = 0; ks < 2; ks++) {
            int kb = ks * 16;
            uint32_t aoff = (uint32_t)(kb + (mat >> 1) * 8) * 2;
            uint32_t boff = (uint32_t)(kb + ((lane >> 3) & 1) * 8) * 2;
            uint32_t af[4][4], bfh[4][2], bfl[4][2];
            #pragma unroll
            for (int mf = 0; mf < 4; mf++)
                ldsm4(af[mf], ahB + (uint32_t)(m_base + mf * 16 + (mat & 1) * 8 + l8) * PITCHB + aoff);
            #pragma unroll
            for (int nf = 0; nf < 4; nf++)
                ldsm2(bfh[nf], bhB + (uint32_t)(n_base + nf * 8 + l8) * PITCHB + boff);
            #pragma unroll
            for (int mf = 0; mf < 4; mf++)
                #pragma unroll
                for (int nf = 0; nf < 4; nf++)
                    mma_bf16(acc[mf][nf], af[mf], bfh[nf]);
            #pragma unroll
            for (int nf = 0; nf < 4; nf++)
                ldsm2(bfl[nf], blB + (uint32_t)(n_base + nf * 8 + l8) * PITCHB + boff);
            #pragma unroll
            for (int mf = 0; mf < 4; mf++)
                #pragma unroll
                for (int nf = 0; nf < 4; nf++)
                    mma_bf16(acc[mf][nf], af[mf], bfl[nf]);
            #pragma unroll
            for (int mf = 0; mf < 4; mf++)
                ldsm4(af[mf], alB + (uint32_t)(m_base + mf * 16 + (mat & 1) * 8 + l8) * PITCHB + aoff);
            #pragma unroll
            for (int mf = 0; mf < 4; mf++)
                #pragma unroll
                for (int nf = 0; nf < 4; nf++)
                    mma_bf16(acc[mf][nf], af[mf], bfh[nf]);
        }
    }

    int g = lane >> 2, t2 = (lane & 3) * 2;
    #pragma unroll
    for (int mf = 0; mf < 4; mf++) {
        #pragma unroll
        for (int half = 0; half < 2; half++) {
            int r = row0 + m_base + mf * 16 + g + half * 8;
            if (r >= Ml) continue;
            int orow = sC ? sC[r] : r;
            float sc = rowScale ? rowScale[orow] : 1.f;
            size_t rb = (size_t)orow * N;
            #pragma unroll
            for (int nf = 0; nf < 4; nf++) {
                int cc = col0 + n_base + nf * 8 + t2;
                float v0 = acc[mf][nf][half * 2 + 0] * sc;
                float v1 = acc[mf][nf][half * 2 + 1] * sc;
                if (biasz) { v0 += biasz[cc]; v1 += biasz[cc + 1]; }
                if (residual) { v0 += residual[rb + cc]; v1 += residual[rb + cc + 1]; }
                if (doRelu) { v0 = fmaxf(v0, 0.f); v1 = fmaxf(v1, 0.f); }
                if (C) *(float2*)(C + rb + cc) = make_float2(v0, v1);
                if (Chi) {
                    __nv_bfloat16 h0 = __float2bfloat16(v0), h1 = __float2bfloat16(v1);
                    __nv_bfloat162 hh; hh.x = h0; hh.y = h1;
                    *(__nv_bfloat162*)(Chi + rb + cc) = hh;
                    __nv_bfloat162 ll;
                    ll.x = __float2bfloat16(v0 - __bfloat162float(h0));
                    ll.y = __float2bfloat16(v1 - __bfloat162float(h1));
                    *(__nv_bfloat162*)(Clo + rb + cc) = ll;
                }
            }
        }
    }
}

// ---------------- SIMT GEMM (K=80 cases) ----------------
#define TK 8
__global__ __launch_bounds__(256, 2)
void gemm128(const float* __restrict__ A, const float* __restrict__ Bm,
             float* __restrict__ C,
             __nv_bfloat16* __restrict__ Chi, __nv_bfloat16* __restrict__ Clo,
             int N, int K, int Mstatic,
             const float* __restrict__ bias, int doRelu,
             const int* __restrict__ gatherA, const int* __restrict__ scatterC,
             const int* __restrict__ Mdev, int strideB, int strideBias, int strideList)
{
    __shared__ float As[2][TK][132];
    __shared__ float Bs[2][TK][132];
    int e = blockIdx.z;
    const float* Bz = Bm + (size_t)e * strideB;
    const float* biasz = bias ? bias + (size_t)e * strideBias : (const float*)0;
    const int* gA = gatherA ? gatherA + (size_t)e * strideList : (const int*)0;
    const int* sC = scatterC ? scatterC + (size_t)e * strideList : (const int*)0;
    int Ml = Mdev ? Mdev[e] : Mstatic;
    int row0 = blockIdx.y * 128;
    if (row0 >= Ml) return;
    int col0 = blockIdx.x * 128;
    int tid = threadIdx.x;
    int tx = tid & 15, ty = tid >> 4;

    int ar_ = tid >> 1;
    int ah = (tid & 1) * 4;
    int agr = row0 + ar_;
    int arow = -1;
    if (agr < Ml) arow = gA ? gA[agr] : agr;
    int bkr = tid >> 5;
    int bc = (tid & 31) * 4;
    int nk = (K + TK - 1) / TK;

    auto ldA = [&](int k0) {
        float4 v = make_float4(0.f, 0.f, 0.f, 0.f);
        if (arow >= 0) {
            if (k0 + ah + 3 < K) v = *(const float4*)(A + (size_t)arow * K + k0 + ah);
            else {
                const float* p = A + (size_t)arow * K;
                float t[4];
                #pragma unroll
                for (int q = 0; q < 4; q++) t[q] = (k0 + ah + q < K) ? p[k0 + ah + q] : 0.f;
                v = make_float4(t[0], t[1], t[2], t[3]);
            }
        }
        return v;
    };
    auto ldB = [&](int k0) {
        if (k0 + bkr < K) return *(const float4*)(Bz + (size_t)(k0 + bkr) * N + col0 + bc);
        return make_float4(0.f, 0.f, 0.f, 0.f);
    };

    float4 av = ldA(0), bv = ldB(0);
    As[0][ah + 0][ar_] = av.x; As[0][ah + 1][ar_] = av.y;
    As[0][ah + 2][ar_] = av.z; As[0][ah + 3][ar_] = av.w;
    *(float4*)&Bs[0][bkr][bc] = bv;
    __syncthreads();

    float acc[8][8] = {};
    int ty8 = ty * 8, tx8 = tx * 8;
    for (int t = 0; t < nk; t++) {
        int cur = t & 1, nxt = cur ^ 1;
        if (t + 1 < nk) { av = ldA((t + 1) * TK); bv = ldB((t + 1) * TK); }
        #pragma unroll
        for (int k = 0; k < TK; k++) {
            float4 a0 = *(const float4*)&As[cur][k][ty8];
            float4 a1 = *(const float4*)&As[cur][k][ty8 + 4];
            float4 b0 = *(const float4*)&Bs[cur][k][tx8];
            float4 b1 = *(const float4*)&Bs[cur][k][tx8 + 4];
            float aa[8] = {a0.x, a0.y, a0.z, a0.w, a1.x, a1.y, a1.z, a1.w};
            float bb[8] = {b0.x, b0.y, b0.z, b0.w, b1.x, b1.y, b1.z, b1.w};
            #pragma unroll
            for (int i = 0; i < 8; i++)
                #pragma unroll
                for (int j = 0; j < 8; j++)
                    acc[i][j] += aa[i] * bb[j];
        }
        if (t + 1 < nk) {
            As[nxt][ah + 0][ar_] = av.x; As[nxt][ah + 1][ar_] = av.y;
            As[nxt][ah + 2][ar_] = av.z; As[nxt][ah + 3][ar_] = av.w;
            *(float4*)&Bs[nxt][bkr][bc] = bv;
        }
        __syncthreads();
    }
    float bb[8] = {};
    if (biasz) {
        #pragma unroll
        for (int j = 0; j < 8; j++) bb[j] = biasz[col0 + tx8 + j];
    }
    #pragma unroll
    for (int i = 0; i < 8; i++) {
        int r = row0 + ty8 + i;
        if (r >= Ml) continue;
        int orow = sC ? sC[r] : r;
        size_t cb = (size_t)orow * N + col0 + tx8;
        float v[8];
        #pragma unroll
        for (int j = 0; j < 8; j++) {
            v[j] = acc[i][j] + bb[j];
            if (doRelu) v[j] = fmaxf(v[j], 0.f);
        }
        if (C) {
            *(float4*)(C + cb) = make_float4(v[0], v[1], v[2], v[3]);
            *(float4*)(C + cb + 4) = make_float4(v[4], v[5], v[6], v[7]);
        }
        if (Chi) {
            #pragma unroll
            for (int j = 0; j < 8; j += 2) {
                __nv_bfloat16 h0 = __float2bfloat16(v[j]), h1 = __float2bfloat16(v[j + 1]);
                __nv_bfloat162 hh; hh.x = h0; hh.y = h1;
                *(__nv_bfloat162*)(Chi + cb + j) = hh;
                __nv_bfloat162 ll;
                ll.x = __float2bfloat16(v[j] - __bfloat162float(h0));
                ll.y = __float2bfloat16(v[j + 1] - __bfloat162float(h1));
                *(__nv_bfloat162*)(Clo + cb + j) = ll;
            }
        }
    }
}

// ---------------- router ----------------
__global__ void router_kernel(const float* __restrict__ embed, const float* __restrict__ R,
                              const int* __restrict__ seqlen, float* __restrict__ gtok,
                              int* __restrict__ lists, int* __restrict__ cnt,
                              float* __restrict__ imp)
{
    int gw = (blockIdx.x * blockDim.x + threadIdx.x) >> 5;
    int lane = threadIdx.x & 31;
    if (gw >= NTOK) return;
    const float* xr = embed + (size_t)gw * DMODEL;
    float l0 = 0, l1 = 0, l2 = 0, l3 = 0;
    for (int d = lane; d < DMODEL; d += 32) {
        float v = xr[d];
        const float* rr = R + d * 4;
        l0 += v * rr[0]; l1 += v * rr[1]; l2 += v * rr[2]; l3 += v * rr[3];
    }
    for (int off = 16; off; off >>= 1) {
        l0 += __shfl_xor_sync(0xffffffffu, l0, off);
        l1 += __shfl_xor_sync(0xffffffffu, l1, off);
        l2 += __shfl_xor_sync(0xffffffffu, l2, off);
        l3 += __shfl_xor_sync(0xffffffffu, l3, off);
    }
    if (lane == 0) {
        float mx = fmaxf(fmaxf(l0, l1), fmaxf(l2, l3));
        float e0 = __expf(l0 - mx), e1 = __expf(l1 - mx);
        float e2 = __expf(l2 - mx), e3 = __expf(l3 - mx);
        float inv = 1.f / (e0 + e1 + e2 + e3);
        float s0 = e0 * inv, s1 = e1 * inv, s2 = e2 * inv, s3 = e3 * inv;
        int em = 0; float gm = s0;
        if (s1 > gm) { gm = s1; em = 1; }
        if (s2 > gm) { gm = s2; em = 2; }
        if (s3 > gm) { gm = s3; em = 3; }
        int b = gw >> 9, t = gw & 511;
        if (t < seqlen[b]) {
            atomicAdd(&imp[0], s0); atomicAdd(&imp[1], s1);
            atomicAdd(&imp[2], s2); atomicAdd(&imp[3], s3);
        }
        gtok[gw] = gm;
        int slot = atomicAdd(&cnt[em], 1);
        lists[em * NTOK + slot] = gw;
    }
}

// ---------------- FSMN (emits split(cur)) ----------------
__global__ void fsmn_kernel(const float* __restrict__ P, const float* __restrict__ fb,
                            const float* __restrict__ fa, const float* __restrict__ skipin,
                            float* __restrict__ outp)
{
    int idx = blockIdx.x * 256 + threadIdx.x;
    if (idx >= NTOK * DMODEL) return;
    int d = idx & 511;
    int t = (idx >> 9) & 511;
    float v = P[idx];
    #pragma unroll
    for (int k = 0; k < 4; k++) {
        int off = (k + 1) * 2;
        if (t - off >= 0) v += fb[k * DMODEL + d] * P[idx - off * DMODEL];
    }
    if (t + 1 < TLEN) v += fa[d] * P[idx + DMODEL];
    if (skipin) v += skipin[idx];
    outp[idx] = v;
    __nv_bfloat16 h = __float2bfloat16(v);
    g_ahi[idx] = h;
    g_alo[idx] = __float2bfloat16(v - __bfloat162float(h));
}

// ---------------- PE ----------------
__global__ void pe_kernel(float* __restrict__ cur)
{
    int idx = blockIdx.x * 256 + threadIdx.x;
    if (idx >= NTOK * DMODEL) return;
    int d = idx & 511;
    int t = (idx >> 9) & 511;
    int i = d >> 1;
    float div = __expf(-(float)(2 * i) * (9.2103403719761836f / 512.f));
    float a = (float)t * div;
    float v = cur[idx] + ((d & 1) ? cosf(a) : sinf(a));
    cur[idx] = v;
    __nv_bfloat16 h = __float2bfloat16(v);
    g_ahi[idx] = h;
    g_alo[idx] = __float2bfloat16(v - __bfloat162float(h));
}

// ---------------- memory KV rows ----------------
__global__ void memrows_kernel(const float* __restrict__ mk, const float* __restrict__ mv,
                               float* __restrict__ Kb, float* __restrict__ Vb)
{
    int idx = blockIdx.x * 256 + threadIdx.x;
    if (idx >= BATCH * MMEM * DMODEL) return;
    int d = idx & 511;
    int r = idx >> 9;
    int m = r & 63;
    int b = r >> 6;
    size_t dst = ((size_t)(b * SFULL + TLEN + m)) * DMODEL + d;
    Kb[dst] = mk[m * DMODEL + d];
    Vb[dst] = mv[m * DMODEL + d];
}

// ---------------- tensor-core flash attention ----------------
#define AT_PITCH 72
#define AT_QH 0
#define AT_QL (128*AT_PITCH)
#define AT_KH (2*128*AT_PITCH)
#define AT_KL (AT_KH + 64*AT_PITCH)
#define AT_VH (AT_KL + 64*AT_PITCH)
#define AT_VL (AT_VH + 64*AT_PITCH)
#define ATTN_SMEM ((AT_VL + 64*AT_PITCH) * 2)
__global__ __launch_bounds__(256, 1)
void attn_mma(const float* __restrict__ Q, const float* __restrict__ Kb,
              const float* __restrict__ Vb, const int* __restrict__ seqlen,
              float* __restrict__ O)
{
    extern __shared__ __nv_bfloat16 sb[];
    int q0 = blockIdx.x * 128, h = blockIdx.y, b = blockIdx.z;
    int tid = threadIdx.x, wid = tid >> 5, lane = tid & 31;
    int slen = seqlen[b];
    int l8 = lane & 7, mat = lane >> 3, g = lane >> 2, t2 = (lane & 3) * 2;
    int mrow = wid * 16;

    #pragma unroll
    for (int i = 0; i < 8; i++) {
        int u = i * 256 + tid;
        int r = u >> 4, c = (u & 15) * 4;
        float4 v = *(const float4*)(Q + ((size_t)(b * TLEN + q0 + r)) * DMODEL + h * DH + c);
        float f[4] = {v.x, v.y, v.z, v.w};
        #pragma unroll
        for (int j = 0; j < 4; j++) {
            __nv_bfloat16 hh = __float2bfloat16(f[j]);
            sb[AT_QH + r * AT_PITCH + c + j] = hh;
            sb[AT_QL + r * AT_PITCH + c + j] = __float2bfloat16(f[j] - __bfloat162float(hh));
        }
    }

    uint32_t QhB = s2u(sb + AT_QH), QlB = s2u(sb + AT_QL);
    uint32_t KhB = s2u(sb + AT_KH), KlB = s2u(sb + AT_KL);
    uint32_t VhB = s2u(sb + AT_VH), VlB = s2u(sb + AT_VL);

    float o[8][4] = {};
    float m0 = -1e30f, m1 = -1e30f, l0 = 0.f, l1 = 0.f;

    for (int s0 = 0; s0 < SFULL; s0 += 64) {
        __syncthreads();
        #pragma unroll
        for (int i = 0; i < 4; i++) {
            int u = i * 256 + tid;
            int r = u >> 4, c = (u & 15) * 4;
            size_t base = ((size_t)(b * SFULL + s0 + r)) * DMODEL + h * DH + c;
            float4 kv = *(const float4*)(Kb + base);
            float4 vv = *(const float4*)(Vb + base);
            float fk[4] = {kv.x, kv.y, kv.z, kv.w};
            float fv[4] = {vv.x, vv.y, vv.z, vv.w};
            #pragma unroll
            for (int j = 0; j < 4; j++) {
                __nv_bfloat16 hk = __float2bfloat16(fk[j]);
                sb[AT_KH + r * AT_PITCH + c + j] = hk;
                sb[AT_KL + r * AT_PITCH + c + j] = __float2bfloat16(fk[j] - __bfloat162float(hk));
                __nv_bfloat16 hv = __float2bfloat16(fv[j]);
                sb[AT_VH + r * AT_PITCH + c + j] = hv;
                sb[AT_VL + r * AT_PITCH + c + j] = __float2bfloat16(fv[j] - __bfloat162float(hv));
            }
        }
        __syncthreads();

        float sc[8][4] = {};
        #pragma unroll
        for (int pass = 0; pass < 3; pass++) {
            uint32_t aB = (pass == 2) ? QlB : QhB;
            uint32_t bB = (pass == 1) ? KlB : KhB;
            #pragma unroll
            for (int kc = 0; kc < 4; kc++) {
                uint32_t af[4];
                ldsm4(af, aB + (uint32_t)((mrow + (mat & 1) * 8 + l8) * AT_PITCH
                                          + kc * 16 + (mat >> 1) * 8) * 2);
                #pragma unroll
                for (int nf = 0; nf < 8; nf++) {
                    uint32_t bf2[2];
                    ldsm2(bf2, bB + (uint32_t)((nf * 8 + l8) * AT_PITCH
                                               + kc * 16 + ((lane >> 3) & 1) * 8) * 2);
                    mma_bf16(sc[nf], af, bf2);
                }
            }
        }

        float rm0 = -1e30f, rm1 = -1e30f;
        #pragma unroll
        for (int nf = 0; nf < 8; nf++) {
            #pragma unroll
            for (int j = 0; j < 4; j++) {
                int sg = s0 + nf * 8 + t2 + (j & 1);
                float v = sc[nf][j] * 0.125f;
                sc[nf][j] = (sg >= slen && sg < TLEN) ? -1e9f : v;
            }
            rm0 = fmaxf(rm0, fmaxf(sc[nf][0], sc[nf][1]));
            rm1 = fmaxf(rm1, fmaxf(sc[nf][2], sc[nf][3]));
        }
        rm0 = fmaxf(rm0, __shfl_xor_sync(0xffffffffu, rm0, 1));
        rm0 = fmaxf(rm0, __shfl_xor_sync(0xffffffffu, rm0, 2));
        rm1 = fmaxf(rm1, __shfl_xor_sync(0xffffffffu, rm1, 1));
        rm1 = fmaxf(rm1, __shfl_xor_sync(0xffffffffu, rm1, 2));
        float mn0 = fmaxf(m0, rm0), mn1 = fmaxf(m1, rm1);
        float e0 = __expf(m0 - mn0), e1 = __expf(m1 - mn1);
        float rs0 = 0.f, rs1 = 0.f;
        #pragma unroll
        for (int nf = 0; nf < 8; nf++) {
            sc[nf][0] = __expf(sc[nf][0] - mn0); rs0 += sc[nf][0];
            sc[nf][1] = __expf(sc[nf][1] - mn0); rs0 += sc[nf][1];
            sc[nf][2] = __expf(sc[nf][2] - mn1); rs1 += sc[nf][2];
            sc[nf][3] = __expf(sc[nf][3] - mn1); rs1 += sc[nf][3];
        }
        rs0 += __shfl_xor_sync(0xffffffffu, rs0, 1);
        rs0 += __shfl_xor_sync(0xffffffffu, rs0, 2);
        rs1 += __shfl_xor_sync(0xffffffffu, rs1, 1);
        rs1 += __shfl_xor_sync(0xffffffffu, rs1, 2);
        l0 = l0 * e0 + rs0; l1 = l1 * e1 + rs1;
        m0 = mn0; m1 = mn1;
        #pragma unroll
        for (int nf = 0; nf < 8; nf++) {
            o[nf][0] *= e0; o[nf][1] *= e0; o[nf][2] *= e1; o[nf][3] *= e1;
        }

        uint32_t phi[4][4], plo[4][4];
        #pragma unroll
        for (int kc = 0; kc < 4; kc++) {
            float* A = sc[2 * kc];
            float* B = sc[2 * kc + 1];
            phi[kc][0] = packbf(A[0], A[1]); phi[kc][1] = packbf(A[2], A[3]);
            phi[kc][2] = packbf(B[0], B[1]); phi[kc][3] = packbf(B[2], B[3]);
            plo[kc][0] = packbf(bfres(A[0]), bfres(A[1]));
            plo[kc][1] = packbf(bfres(A[2]), bfres(A[3]));
            plo[kc][2] = packbf(bfres(B[0]), bfres(B[1]));
            plo[kc][3] = packbf(bfres(B[2]), bfres(B[3]));
        }

        #pragma unroll
        for (int pass = 0; pass < 3; pass++) {
            uint32_t vB = (pass == 1) ? VlB : VhB;
            #pragma unroll
            for (int kc = 0; kc < 4; kc++) {
                const uint32_t* pf = (pass == 2) ? plo[kc] : phi[kc];
                #pragma unroll
                for (int nf = 0; nf < 8; nf++) {
                    uint32_t bf2[2];
                    ldsm2t(bf2, vB + (uint32_t)((kc * 16 + ((lane >> 3) & 1) * 8 + l8) * AT_PITCH
                                                + nf * 8) * 2);
                    mma_bf16(o[nf], pf, bf2);
                }
            }
        }
    }

    float inv0 = 1.f / l0, inv1 = 1.f / l1;
    int r0 = q0 + mrow + g;
    #pragma unroll
    for (int nf = 0; nf < 8; nf++) {
        int cc = h * DH + nf * 8 + t2;
        *(float2*)(O + ((size_t)(b * TLEN + r0)) * DMODEL + cc) =
            make_float2(o[nf][0] * inv0, o[nf][1] * inv0);
        *(float2*)(O + ((size_t)(b * TLEN + r0 + 8)) * DMODEL + cc) =
            make_float2(o[nf][2] * inv1, o[nf][3] * inv1);
    }
}

// ---------------- layernorm (emits split(cur)) ----------------
__global__ void ln_kernel(const float* __restrict__ X, float* __restrict__ Y,
                          const float* __restrict__ gw, const float* __restrict__ bw)
{
    __shared__ float red[128];
    int row = blockIdx.x, tid = threadIdx.x;
    const float* xr = X + (size_t)row * DMODEL;
    float v[4]; float s = 0.f;
    #pragma unroll
    for (int i = 0; i < 4; i++) { v[i] = xr[tid + 128 * i]; s += v[i]; }
    red[tid] = s; __syncthreads();
    for (int off = 64; off > 0; off >>= 1) {
        if (tid < off) red[tid] += red[tid + off];
        __syncthreads();
    }
    float mu = red[0] * (1.f / 512.f);
    __syncthreads();
    float s2 = 0.f;
    #pragma unroll
    for (int i = 0; i < 4; i++) { float d = v[i] - mu; s2 += d * d; }
    red[tid] = s2; __syncthreads();
    for (int off = 64; off > 0; off >>= 1) {
        if (tid < off) red[tid] += red[tid + off];
        __syncthreads();
    }
    float inv = rsqrtf(red[0] * (1.f / 512.f) + 1e-5f);
    #pragma unroll
    for (int i = 0; i < 4; i++) {
        int c = tid + 128 * i;
        float y = (v[i] - mu) * inv * gw[c] + bw[c];
        size_t idx = (size_t)row * DMODEL + c;
        Y[idx] = y;
        __nv_bfloat16 h = __float2bfloat16(y);
        g_ahi[idx] = h;
        g_alo[idx] = __float2bfloat16(y - __bfloat162float(h));
    }
}

// ---------------- aux ----------------
__global__ void aux_kernel(float* __restrict__ dst)
{
    float tot = 0.f;
    for (int l = 0; l < NLAYER; l++) {
        float m = 0.f;
        for (int e = 0; e < NEXP; e++) m += g_imp[l * 4 + e];
        m *= 0.25f;
        float var = 0.f;
        for (int e = 0; e < NEXP; e++) { float d = g_imp[l * 4 + e] - m; var += d * d; }
        var *= 0.25f;
        tot += var / (m * m + 1e-9f);
    }
    dst[0] = tot;
}

// ---------------- launcher ----------------
extern "C" void kernel_launch(void* const* d_in, const int* in_sizes, int n_in,
                              void* d_out, int out_size)
{
    const float* x         = (const float*)d_in[0];
    const int*   seq       = (const int*)  d_in[1];
    const float* emb_w1    = (const float*)d_in[2];
    const float* emb_b1    = (const float*)d_in[3];
    const float* emb_w2    = (const float*)d_in[4];
    const float* emb_wo    = (const float*)d_in[5];
    const float* f0_w1     = (const float*)d_in[6];
    const float* f0_b1     = (const float*)d_in[7];
    const float* f0_w2     = (const float*)d_in[8];
    const float* f0_router = (const float*)d_in[9];
    const float* f0_fb     = (const float*)d_in[10];
    const float* f0_fa     = (const float*)d_in[11];
    const float* f_w1      = (const float*)d_in[12];
    const float* f_b1      = (const float*)d_in[13];
    const float* f_w2      = (const float*)d_in[14];
    const float* f_router  = (const float*)d_in[15];
    const float* f_fb      = (const float*)d_in[16];
    const float* f_fa      = (const float*)d_in[17];
    const float* wq        = (const float*)d_in[18];
    const float* wk        = (const float*)d_in[19];
    const float* wv        = (const float*)d_in[20];
    const float* wvo       = (const float*)d_in[21];
    const float* mk        = (const float*)d_in[22];
    const float* mv        = (const float*)d_in[23];
    const float* lng       = (const float*)d_in[24];
    const float* lnb       = (const float*)d_in[25];
    const float* out_w     = (const float*)d_in[26];
    const float* out_b     = (const float*)d_in[27];
    float* out = (float*)d_out;

    float *embed, *cur, *p, *q, *kb, *vb, *ao, *tmp, *gtok, *imp;
    int *cnt, *lists, *kvmap;
    __nv_bfloat16 *whi, *wlo, *ahi, *alo, *bhi, *blo;
    cudaGetSymbolAddress((void**)&embed, g_embed);
    cudaGetSymbolAddress((void**)&cur,   g_cur);
    cudaGetSymbolAddress((void**)&p,     g_p);
    cudaGetSymbolAddress((void**)&q,     g_q);
    cudaGetSymbolAddress((void**)&kb,    g_k);
    cudaGetSymbolAddress((void**)&vb,    g_v);
    cudaGetSymbolAddress((void**)&ao,    g_ao);
    cudaGetSymbolAddress((void**)&tmp,   g_tmp);
    cudaGetSymbolAddress((void**)&gtok,  g_gtok);
    cudaGetSymbolAddress((void**)&imp,   g_imp);
    cudaGetSymbolAddress((void**)&cnt,   g_cnt);
    cudaGetSymbolAddress((void**)&lists, g_lists);
    cudaGetSymbolAddress((void**)&kvmap, g_kvmap);
    cudaGetSymbolAddress((void**)&whi,   g_whi);
    cudaGetSymbolAddress((void**)&wlo,   g_wlo);
    cudaGetSymbolAddress((void**)&ahi,   g_ahi);
    cudaGetSymbolAddress((void**)&alo,   g_alo);
    cudaGetSymbolAddress((void**)&bhi,   g_bhi);
    cudaGetSymbolAddress((void**)&blo,   g_blo);

    cudaFuncSetAttribute(attn_mma, cudaFuncAttributeMaxDynamicSharedMemorySize, ATTN_SMEM);
    cudaFuncSetAttribute(tgemm, cudaFuncAttributeMaxDynamicSharedMemorySize, TG_SMEM);

    auto TG = [&](unsigned woff, const __nv_bfloat16* Ah, const __nv_bfloat16* Al,
                  float* C, __nv_bfloat16* Ch, __nv_bfloat16* Cl,
                  int M, int N, int K,
                  const float* bias, int relu, const int* ga, const int* sc,
                  const float* rs, const float* res, const int* Md,
                  int E = 1, int sB = 0, int sBias = 0, int sList = 0) {
        dim3 grid(N / 128, (M + 127) / 128, E);
        tgemm<<<grid, 256, TG_SMEM>>>(Ah, Al, whi + woff, wlo + woff, C, Ch, Cl, N, K, M,
                                      bias, relu, ga, sc, rs, res, Md, sB, sBias, sList);
    };
    auto WT = [&](const float* W, unsigned off, int K, int N, int Z) {
        wsplitT<<<dim3(N / 64, K / 64, Z), 256>>>(W, whi + off, wlo + off, K, N);
    };

    init_kernel<<<1, 1024>>>();

    WT(emb_w2, OFF_EMBW2, 1024, 512, 1);
    WT(emb_wo, OFF_EMBWO, 512, 4096, 1);
    WT(f0_w2,  OFF_F0W2, 1024, 512, 4);
    WT(f_w1,   OFF_FW1, 512, 1024, 28);
    WT(f_w2,   OFF_FW2, 1024, 512, 28);
    WT(wq,     OFF_WQ, 512, 512, 2);
    WT(wk,     OFF_WK, 512, 512, 2);
    WT(wv,     OFF_WV, 512, 512, 2);
    WT(wvo,    OFF_WO, 512, 512, 2);
    WT(out_w,  OFF_OUTW, 512, 4096, 1);

    gemm128<<<dim3(8, 16, 1), 256>>>(x, emb_w1, 0, bhi, blo, DHID, DIN, NTOK,
                                     emb_b1, 1, 0, 0, 0, 0, 0, 0);
    TG(OFF_EMBW2, bhi, blo, embed, ahi, alo, NTOK, DMODEL, DHID, 0, 0, 0, 0, 0, 0, 0);
    TG(OFF_EMBWO, ahi, alo, out + (size_t)NTOK * DOUT, 0, 0, NTOK, DOUT, DMODEL,
       0, 0, 0, 0, 0, 0, 0);

    for (int l = 0; l < NLAYER; l++) {
        const float* Rl = (l == 0) ? f0_router : f_router + (size_t)(l - 1) * DMODEL * NEXP;
        router_kernel<<<NTOK / 8, 256>>>(embed, Rl, seq, gtok, lists, cnt + l * 4, imp + l * 4);

        if (l == 0) {
            gemm128<<<dim3(8, 16, NEXP), 256>>>(x, f0_w1, 0, bhi, blo, DHID, DIN, NTOK,
                                                f0_b1, 1, lists, lists, cnt,
                                                DIN * DHID, DHID, NTOK);
            TG(OFF_F0W2, bhi, blo, p, 0, 0, NTOK, DMODEL, DHID, 0, 0, lists, lists,
               gtok, 0, cnt, NEXP, DMODEL * DHID, 0, NTOK);
        } else {
            TG(OFF_FW1 + (unsigned)(l - 1) * 4u * DMODEL * DHID, ahi, alo,
               0, bhi, blo, NTOK, DHID, DMODEL,
               f_b1 + (size_t)(l - 1) * NEXP * DHID, 1, lists, lists, 0, 0, cnt + l * 4,
               NEXP, DMODEL * DHID, DHID, NTOK);
            TG(OFF_FW2 + (unsigned)(l - 1) * 4u * DHID * DMODEL, bhi, blo,
               p, 0, 0, NTOK, DMODEL, DHID,
               0, 0, lists, lists, gtok, 0, cnt + l * 4,
               NEXP, DHID * DMODEL, 0, NTOK);
        }
        const float* fbL = (l == 0) ? f0_fb : f_fb + (size_t)(l - 1) * 4 * DMODEL;
        const float* faL = (l == 0) ? f0_fa : f_fa + (size_t)(l - 1) * DMODEL;
        fsmn_kernel<<<NTOK * DMODEL / 256, 256>>>(p, fbL, faL,
                                                  (l == 0) ? (const float*)0 : cur, cur);

        if (l == 3) pe_kernel<<<NTOK * DMODEL / 256, 256>>>(cur);

        if (l == 3 || l == 7) {
            int bi = l / 4;
            unsigned wo = (unsigned)bi * 512u * 512u;
            TG(OFF_WQ + wo, ahi, alo, q, 0, 0, NTOK, DMODEL, DMODEL, 0, 0, 0, 0, 0, 0, 0);
            TG(OFF_WK + wo, ahi, alo, kb, 0, 0, NTOK, DMODEL, DMODEL, 0, 0, 0, kvmap, 0, 0, 0);
            TG(OFF_WV + wo, ahi, alo, vb, 0, 0, NTOK, DMODEL, DMODEL, 0, 0, 0, kvmap, 0, 0, 0);
            memrows_kernel<<<BATCH * MMEM * DMODEL / 256, 256>>>(
                mk + (size_t)bi * MMEM * DMODEL, mv + (size_t)bi * MMEM * DMODEL, kb, vb);
            attn_mma<<<dim3(TLEN / 128, NHEAD, BATCH), 256, ATTN_SMEM>>>(q, kb, vb, seq, ao);
            asplit<<<NTOK * DMODEL / 256, 256>>>(ao, ahi, alo, NTOK * DMODEL);
            TG(OFF_WO + wo, ahi, alo, tmp, 0, 0, NTOK, DMODEL, DMODEL, 0, 0, 0, 0, 0, cur, 0);
            ln_kernel<<<NTOK, 128>>>(tmp, cur, lng + bi * DMODEL, lnb + bi * DMODEL);
        }
    }

    TG(OFF_OUTW, ahi, alo, out, 0, 0, NTOK, DOUT, DMODEL, out_b, 0, 0, 0, 0, 0, 0);
    aux_kernel<<<1, 1>>>(out + 2 * (size_t)NTOK * DOUT);
}

// round 7
// speedup vs baseline: 4.4506x; 1.0409x over previous
#include <cuda_runtime.h>
#include <cuda_bf16.h>
#include <math.h>
#include <stdint.h>

// ---------------- problem constants ----------------
#define BATCH 4
#define TLEN  512
#define NTOK  (BATCH*TLEN)
#define DIN   80
#define DOUT  4096
#define DMODEL 512
#define DHID  1024
#define NEXP  4
#define NLAYER 8
#define NHEAD 8
#define DH    64
#define MMEM  64
#define SFULL (TLEN+MMEM)

// ---------------- device scratch ----------------
__device__ float g_embed[NTOK*DMODEL];
__device__ float g_cur[NTOK*DMODEL];
__device__ float g_p[NTOK*DMODEL];
__device__ float g_tmp[NTOK*DMODEL];
__device__ float g_gtok[NLAYER*NTOK];
__device__ float g_imp[NLAYER*NEXP];
__device__ int   g_cnt[NLAYER*NEXP];
__device__ int   g_lists[NLAYER*NEXP*NTOK];
__device__ int   g_kvmap[NTOK];

#define WPOOL (40u*1024u*1024u)
__device__ __nv_bfloat16 g_whi[WPOOL];
__device__ __nv_bfloat16 g_wlo[WPOOL];
__device__ __nv_bfloat16 g_ahi[NTOK*DMODEL];
__device__ __nv_bfloat16 g_alo[NTOK*DMODEL];
__device__ __nv_bfloat16 g_bhi[NTOK*DHID];
__device__ __nv_bfloat16 g_blo[NTOK*DHID];
__device__ __nv_bfloat16 g_qh[NTOK*DMODEL];
__device__ __nv_bfloat16 g_ql[NTOK*DMODEL];
__device__ __nv_bfloat16 g_kh[BATCH*SFULL*DMODEL];
__device__ __nv_bfloat16 g_kl[BATCH*SFULL*DMODEL];
__device__ __nv_bfloat16 g_vh[BATCH*SFULL*DMODEL];
__device__ __nv_bfloat16 g_vl[BATCH*SFULL*DMODEL];

#define OFF_EMBW2 0u
#define OFF_EMBWO (OFF_EMBW2 + 512u*1024u)
#define OFF_F0W2  (OFF_EMBWO + 4096u*512u)
#define OFF_FW1   (OFF_F0W2 + 4u*512u*1024u)
#define OFF_FW2   (OFF_FW1 + 28u*1024u*512u)
#define OFF_WQ    (OFF_FW2 + 28u*512u*1024u)
#define OFF_WK    (OFF_WQ + 2u*512u*512u)
#define OFF_WV    (OFF_WK + 2u*512u*512u)
#define OFF_WO    (OFF_WV + 2u*512u*512u)
#define OFF_OUTW  (OFF_WO + 2u*512u*512u)

// ---------------- helpers ----------------
__device__ __forceinline__ uint32_t s2u(const void* p) {
    uint32_t a;
    asm("{ .reg .u64 t; cvta.to.shared.u64 t, %1; cvt.u32.u64 %0, t; }" : "=r"(a) : "l"(p));
    return a;
}
__device__ __forceinline__ void ldsm4(uint32_t* r, uint32_t addr) {
    asm volatile("ldmatrix.sync.aligned.m8n8.x4.shared.b16 {%0,%1,%2,%3}, [%4];"
        : "=r"(r[0]), "=r"(r[1]), "=r"(r[2]), "=r"(r[3]) : "r"(addr));
}
__device__ __forceinline__ void ldsm2(uint32_t* r, uint32_t addr) {
    asm volatile("ldmatrix.sync.aligned.m8n8.x2.shared.b16 {%0,%1}, [%2];"
        : "=r"(r[0]), "=r"(r[1]) : "r"(addr));
}
__device__ __forceinline__ void ldsm2t(uint32_t* r, uint32_t addr) {
    asm volatile("ldmatrix.sync.aligned.m8n8.x2.trans.shared.b16 {%0,%1}, [%2];"
        : "=r"(r[0]), "=r"(r[1]) : "r"(addr));
}
__device__ __forceinline__ void mma_bf16(float* c, const uint32_t* a, const uint32_t* b) {
    asm volatile("mma.sync.aligned.m16n8k16.row.col.f32.bf16.bf16.f32 "
        "{%0,%1,%2,%3}, {%4,%5,%6,%7}, {%8,%9}, {%0,%1,%2,%3};"
        : "+f"(c[0]), "+f"(c[1]), "+f"(c[2]), "+f"(c[3])
        : "r"(a[0]), "r"(a[1]), "r"(a[2]), "r"(a[3]), "r"(b[0]), "r"(b[1]));
}
__device__ __forceinline__ uint32_t packbf(float a, float b) {
    __nv_bfloat162 h = __floats2bfloat162_rn(a, b);
    return *(uint32_t*)&h;
}
__device__ __forceinline__ float bfres(float x) {
    return x - __bfloat162float(__float2bfloat16(x));
}
#define CPA(dst, src, sz) asm volatile("cp.async.ca.shared.global [%0], [%1], 16, %2;" \
    :: "r"(dst), "l"(src), "r"(sz))
#define CPC() asm volatile("cp.async.commit_group;" ::: "memory")
#define CPW() asm volatile("cp.async.wait_group 0;" ::: "memory")

// ---------------- init ----------------
__global__ void init_kernel() {
    int t = threadIdx.x;
    if (t < NLAYER*NEXP) { g_cnt[t] = 0; g_imp[t] = 0.f; }
    for (int i = t; i < NTOK; i += blockDim.x)
        g_kvmap[i] = (i >> 9) * SFULL + (i & 511);
}

// ---------------- streaming weight split (keeps [K,N] layout) ----------------
__global__ void wsplit(const float* __restrict__ W, __nv_bfloat16* __restrict__ hi,
                       __nv_bfloat16* __restrict__ lo, int n4)
{
    int i = blockIdx.x * 256 + threadIdx.x;
    if (i >= n4) return;
    float4 v = ((const float4*)W)[i];
    __nv_bfloat162 h01 = __floats2bfloat162_rn(v.x, v.y);
    __nv_bfloat162 h23 = __floats2bfloat162_rn(v.z, v.w);
    __nv_bfloat162 l01 = __floats2bfloat162_rn(v.x - __bfloat162float(h01.x),
                                               v.y - __bfloat162float(h01.y));
    __nv_bfloat162 l23 = __floats2bfloat162_rn(v.z - __bfloat162float(h23.x),
                                               v.w - __bfloat162float(h23.y));
    uint2 hw, lw;
    hw.x = *(uint32_t*)&h01; hw.y = *(uint32_t*)&h23;
    lw.x = *(uint32_t*)&l01; lw.y = *(uint32_t*)&l23;
    *(uint2*)(hi + (size_t)i * 4) = hw;
    *(uint2*)(lo + (size_t)i * 4) = lw;
}

// ---------------- bf16 TC GEMM: A row-major [M,K], B k-major [K,N], cp.async 2-stage ----------------
#define KC 32
#define APITCHB 80
#define BPITCHB 272
#define A_TILE (128*APITCHB)
#define B_TILE (KC*BPITCHB)
#define STG (2*A_TILE + 2*B_TILE)
#define TG_SMEM (2*STG)
__global__ __launch_bounds__(256, 2)
void tgemm(const __nv_bfloat16* __restrict__ Ahi, const __nv_bfloat16* __restrict__ Alo,
           const __nv_bfloat16* __restrict__ Bhi, const __nv_bfloat16* __restrict__ Blo,
           float* __restrict__ C,
           __nv_bfloat16* __restrict__ Chi, __nv_bfloat16* __restrict__ Clo,
           int N, int K, int Mstatic,
           const float* __restrict__ bias, int doRelu,
           const int* __restrict__ gatherA, const int* __restrict__ scatterC,
           const float* __restrict__ rowScale, const float* __restrict__ residual,
           const int* __restrict__ Mdev, int strideB, int strideBias, int strideList)
{
    extern __shared__ char smem[];
    int e = blockIdx.z;
    const __nv_bfloat16* Bhz = Bhi + (size_t)e * strideB;
    const __nv_bfloat16* Blz = Blo + (size_t)e * strideB;
    const float* biasz = bias ? bias + (size_t)e * strideBias : (const float*)0;
    const int* gA = gatherA ? gatherA + (size_t)e * strideList : (const int*)0;
    const int* sC = scatterC ? scatterC + (size_t)e * strideList : (const int*)0;
    int Ml = Mdev ? Mdev[e] : Mstatic;
    int row0 = blockIdx.y * 128;
    if (row0 >= Ml) return;
    int col0 = blockIdx.x * 128;
    int tid = threadIdx.x, wid = tid >> 5, lane = tid & 31;
    uint32_t sb = s2u(smem);

    int arow[2], lr[2], lu[2];
    #pragma unroll
    for (int i = 0; i < 2; i++) {
        int unit = tid + i * 256;
        lr[i] = unit >> 2;
        lu[i] = unit & 3;
        int gr = row0 + lr[i];
        arow[i] = (gr < Ml) ? (gA ? gA[gr] : gr) : -1;
    }

    auto issue = [&](int c, int stage) {
        int k0 = c * KC;
        uint32_t base = sb + stage * STG;
        #pragma unroll
        for (int i = 0; i < 2; i++) {
            // A units
            uint32_t offA = (uint32_t)(lr[i] * APITCHB + lu[i] * 16);
            int ar = arow[i] >= 0 ? arow[i] : 0;
            uint32_t asz = arow[i] >= 0 ? 16u : 0u;
            CPA(base + offA, (const char*)(Ahi + (size_t)ar * K + k0 + lu[i] * 8), asz);
            CPA(base + A_TILE + offA, (const char*)(Alo + (size_t)ar * K + k0 + lu[i] * 8), asz);
            // B units (k-major)
            int unit = tid + i * 256;
            int bk = unit >> 4, bc16 = unit & 15;
            uint32_t offB = (uint32_t)(bk * BPITCHB + bc16 * 16);
            const char* bh = (const char*)(Bhz + (size_t)(k0 + bk) * N + col0 + bc16 * 8);
            const char* bl = (const char*)(Blz + (size_t)(k0 + bk) * N + col0 + bc16 * 8);
            CPA(base + 2u * A_TILE + offB, bh, 16u);
            CPA(base + 2u * A_TILE + B_TILE + offB, bl, 16u);
        }
    };

    float acc[4][4][4] = {};
    int wm = wid >> 2, wn = wid & 3;
    int m_base = wm * 64, n_base = wn * 32;
    int l8 = lane & 7, mat = lane >> 3, bsel = (lane >> 3) & 1;

    int nc = K / KC;
    issue(0, 0); CPC();

    for (int c = 0; c < nc; c++) {
        CPW();
        __syncthreads();
        if (c + 1 < nc) { issue(c + 1, (c + 1) & 1); CPC(); }

        uint32_t base = sb + (c & 1) * STG;
        uint32_t ahB = base, alB = base + A_TILE;
        uint32_t bhB = base + 2u * A_TILE, blB = base + 2u * A_TILE + B_TILE;
        #pragma unroll
        for (int ks = 0; ks < 2; ks++) {
            int kb = ks * 16;
            uint32_t aoff = (uint32_t)(kb + (mat >> 1) * 8) * 2;
            uint32_t af[4][4], bfh[4][2], bfl[4][2];
            #pragma unroll
            for (int mf = 0; mf < 4; mf++)
                ldsm4(af[mf], ahB + (uint32_t)(m_base + mf * 16 + (mat & 1) * 8 + l8) * APITCHB + aoff);
            #pragma unroll
            for (int nf = 0; nf < 4; nf++)
                ldsm2t(bfh[nf], bhB + (uint32_t)(kb + bsel * 8 + l8) * BPITCHB
                                    + (uint32_t)(n_base + nf * 8) * 2);
            #pragma unroll
            for (int mf = 0; mf < 4; mf++)
                #pragma unroll
                for (int nf = 0; nf < 4; nf++)
                    mma_bf16(acc[mf][nf], af[mf], bfh[nf]);
            #pragma unroll
            for (int nf = 0; nf < 4; nf++)
                ldsm2t(bfl[nf], blB + (uint32_t)(kb + bsel * 8 + l8) * BPITCHB
                                    + (uint32_t)(n_base + nf * 8) * 2);
            #pragma unroll
            for (int mf = 0; mf < 4; mf++)
                #pragma unroll
                for (int nf = 0; nf < 4; nf++)
                    mma_bf16(acc[mf][nf], af[mf], bfl[nf]);
            #pragma unroll
            for (int mf = 0; mf < 4; mf++)
                ldsm4(af[mf], alB + (uint32_t)(m_base + mf * 16 + (mat & 1) * 8 + l8) * APITCHB + aoff);
            #pragma unroll
            for (int mf = 0; mf < 4; mf++)
                #pragma unroll
                for (int nf = 0; nf < 4; nf++)
                    mma_bf16(acc[mf][nf], af[mf], bfh[nf]);
        }
    }

    int g = lane >> 2, t2 = (lane & 3) * 2;
    #pragma unroll
    for (int mf = 0; mf < 4; mf++) {
        #pragma unroll
        for (int half = 0; half < 2; half++) {
            int r = row0 + m_base + mf * 16 + g + half * 8;
            if (r >= Ml) continue;
            int orow = sC ? sC[r] : r;
            float sc = rowScale ? rowScale[orow] : 1.f;
            size_t rb = (size_t)orow * N;
            #pragma unroll
            for (int nf = 0; nf < 4; nf++) {
                int cc = col0 + n_base + nf * 8 + t2;
                float v0 = acc[mf][nf][half * 2 + 0] * sc;
                float v1 = acc[mf][nf][half * 2 + 1] * sc;
                if (biasz) { v0 += biasz[cc]; v1 += biasz[cc + 1]; }
                if (residual) { v0 += residual[rb + cc]; v1 += residual[rb + cc + 1]; }
                if (doRelu) { v0 = fmaxf(v0, 0.f); v1 = fmaxf(v1, 0.f); }
                if (C) *(float2*)(C + rb + cc) = make_float2(v0, v1);
                if (Chi) {
                    *(uint32_t*)(Chi + rb + cc) = packbf(v0, v1);
                    *(uint32_t*)(Clo + rb + cc) = packbf(bfres(v0), bfres(v1));
                }
            }
        }
    }
}

// ---------------- SIMT GEMM (K=80 cases), emits split ----------------
#define TK 8
__global__ __launch_bounds__(256, 2)
void gemm128(const float* __restrict__ A, const float* __restrict__ Bm,
             __nv_bfloat16* __restrict__ Chi, __nv_bfloat16* __restrict__ Clo,
             int N, int K, int Mstatic,
             const float* __restrict__ bias, int doRelu,
             const int* __restrict__ gatherA, const int* __restrict__ scatterC,
             const int* __restrict__ Mdev, int strideB, int strideBias, int strideList)
{
    __shared__ float As[2][TK][132];
    __shared__ float Bs[2][TK][132];
    int e = blockIdx.z;
    const float* Bz = Bm + (size_t)e * strideB;
    const float* biasz = bias ? bias + (size_t)e * strideBias : (const float*)0;
    const int* gA = gatherA ? gatherA + (size_t)e * strideList : (const int*)0;
    const int* sC = scatterC ? scatterC + (size_t)e * strideList : (const int*)0;
    int Ml = Mdev ? Mdev[e] : Mstatic;
    int row0 = blockIdx.y * 128;
    if (row0 >= Ml) return;
    int col0 = blockIdx.x * 128;
    int tid = threadIdx.x;
    int tx = tid & 15, ty = tid >> 4;

    int ar_ = tid >> 1;
    int ah = (tid & 1) * 4;
    int agr = row0 + ar_;
    int arow = -1;
    if (agr < Ml) arow = gA ? gA[agr] : agr;
    int bkr = tid >> 5;
    int bc = (tid & 31) * 4;
    int nk = (K + TK - 1) / TK;

    auto ldA = [&](int k0) {
        float4 v = make_float4(0.f, 0.f, 0.f, 0.f);
        if (arow >= 0) {
            if (k0 + ah + 3 < K) v = *(const float4*)(A + (size_t)arow * K + k0 + ah);
            else {
                const float* p = A + (size_t)arow * K;
                float t[4];
                #pragma unroll
                for (int q = 0; q < 4; q++) t[q] = (k0 + ah + q < K) ? p[k0 + ah + q] : 0.f;
                v = make_float4(t[0], t[1], t[2], t[3]);
            }
        }
        return v;
    };
    auto ldB = [&](int k0) {
        if (k0 + bkr < K) return *(const float4*)(Bz + (size_t)(k0 + bkr) * N + col0 + bc);
        return make_float4(0.f, 0.f, 0.f, 0.f);
    };

    float4 av = ldA(0), bv = ldB(0);
    As[0][ah + 0][ar_] = av.x; As[0][ah + 1][ar_] = av.y;
    As[0][ah + 2][ar_] = av.z; As[0][ah + 3][ar_] = av.w;
    *(float4*)&Bs[0][bkr][bc] = bv;
    __syncthreads();

    float acc[8][8] = {};
    int ty8 = ty * 8, tx8 = tx * 8;
    for (int t = 0; t < nk; t++) {
        int cur = t & 1, nxt = cur ^ 1;
        if (t + 1 < nk) { av = ldA((t + 1) * TK); bv = ldB((t + 1) * TK); }
        #pragma unroll
        for (int k = 0; k < TK; k++) {
            float4 a0 = *(const float4*)&As[cur][k][ty8];
            float4 a1 = *(const float4*)&As[cur][k][ty8 + 4];
            float4 b0 = *(const float4*)&Bs[cur][k][tx8];
            float4 b1 = *(const float4*)&Bs[cur][k][tx8 + 4];
            float aa[8] = {a0.x, a0.y, a0.z, a0.w, a1.x, a1.y, a1.z, a1.w};
            float bb[8] = {b0.x, b0.y, b0.z, b0.w, b1.x, b1.y, b1.z, b1.w};
            #pragma unroll
            for (int i = 0; i < 8; i++)
                #pragma unroll
                for (int j = 0; j < 8; j++)
                    acc[i][j] += aa[i] * bb[j];
        }
        if (t + 1 < nk) {
            As[nxt][ah + 0][ar_] = av.x; As[nxt][ah + 1][ar_] = av.y;
            As[nxt][ah + 2][ar_] = av.z; As[nxt][ah + 3][ar_] = av.w;
            *(float4*)&Bs[nxt][bkr][bc] = bv;
        }
        __syncthreads();
    }
    float bb[8] = {};
    if (biasz) {
        #pragma unroll
        for (int j = 0; j < 8; j++) bb[j] = biasz[col0 + tx8 + j];
    }
    #pragma unroll
    for (int i = 0; i < 8; i++) {
        int r = row0 + ty8 + i;
        if (r >= Ml) continue;
        int orow = sC ? sC[r] : r;
        size_t cb = (size_t)orow * N + col0 + tx8;
        #pragma unroll
        for (int j = 0; j < 8; j += 2) {
            float v0 = acc[i][j] + bb[j];
            float v1 = acc[i][j + 1] + bb[j + 1];
            if (doRelu) { v0 = fmaxf(v0, 0.f); v1 = fmaxf(v1, 0.f); }
            *(uint32_t*)(Chi + cb + j) = packbf(v0, v1);
            *(uint32_t*)(Clo + cb + j) = packbf(bfres(v0), bfres(v1));
        }
    }
}

// ---------------- fused router (all layers) ----------------
__global__ void router_all(const float* __restrict__ embed, const float* __restrict__ f0r,
                           const float* __restrict__ fr, const int* __restrict__ seqlen,
                           float* __restrict__ gtokA, int* __restrict__ listsA,
                           int* __restrict__ cntA, float* __restrict__ impA)
{
    int l = blockIdx.y;
    const float* R = (l == 0) ? f0r : fr + (size_t)(l - 1) * DMODEL * NEXP;
    float* gtok = gtokA + (size_t)l * NTOK;
    int* lists = listsA + (size_t)l * NEXP * NTOK;
    int* cnt = cntA + l * NEXP;
    float* imp = impA + l * NEXP;

    int gw = (blockIdx.x * blockDim.x + threadIdx.x) >> 5;
    int lane = threadIdx.x & 31;
    if (gw >= NTOK) return;
    const float* xr = embed + (size_t)gw * DMODEL;
    float l0 = 0, l1 = 0, l2 = 0, l3 = 0;
    for (int d = lane; d < DMODEL; d += 32) {
        float v = xr[d];
        const float* rr = R + d * 4;
        l0 += v * rr[0]; l1 += v * rr[1]; l2 += v * rr[2]; l3 += v * rr[3];
    }
    for (int off = 16; off; off >>= 1) {
        l0 += __shfl_xor_sync(0xffffffffu, l0, off);
        l1 += __shfl_xor_sync(0xffffffffu, l1, off);
        l2 += __shfl_xor_sync(0xffffffffu, l2, off);
        l3 += __shfl_xor_sync(0xffffffffu, l3, off);
    }
    if (lane == 0) {
        float mx = fmaxf(fmaxf(l0, l1), fmaxf(l2, l3));
        float e0 = __expf(l0 - mx), e1 = __expf(l1 - mx);
        float e2 = __expf(l2 - mx), e3 = __expf(l3 - mx);
        float inv = 1.f / (e0 + e1 + e2 + e3);
        float s0 = e0 * inv, s1 = e1 * inv, s2 = e2 * inv, s3 = e3 * inv;
        int em = 0; float gm = s0;
        if (s1 > gm) { gm = s1; em = 1; }
        if (s2 > gm) { gm = s2; em = 2; }
        if (s3 > gm) { gm = s3; em = 3; }
        int b = gw >> 9, t = gw & 511;
        if (t < seqlen[b]) {
            atomicAdd(&imp[0], s0); atomicAdd(&imp[1], s1);
            atomicAdd(&imp[2], s2); atomicAdd(&imp[3], s3);
        }
        gtok[gw] = gm;
        int slot = atomicAdd(&cnt[em], 1);
        lists[em * NTOK + slot] = gw;
    }
}

// ---------------- FSMN (emits split(cur)) ----------------
__global__ void fsmn_kernel(const float* __restrict__ P, const float* __restrict__ fb,
                            const float* __restrict__ fa, const float* __restrict__ skipin,
                            float* __restrict__ outp)
{
    int idx = blockIdx.x * 256 + threadIdx.x;
    if (idx >= NTOK * DMODEL) return;
    int d = idx & 511;
    int t = (idx >> 9) & 511;
    float v = P[idx];
    #pragma unroll
    for (int k = 0; k < 4; k++) {
        int off = (k + 1) * 2;
        if (t - off >= 0) v += fb[k * DMODEL + d] * P[idx - off * DMODEL];
    }
    if (t + 1 < TLEN) v += fa[d] * P[idx + DMODEL];
    if (skipin) v += skipin[idx];
    outp[idx] = v;
    __nv_bfloat16 h = __float2bfloat16(v);
    g_ahi[idx] = h;
    g_alo[idx] = __float2bfloat16(v - __bfloat162float(h));
}

// ---------------- PE ----------------
__global__ void pe_kernel(float* __restrict__ cur)
{
    int idx = blockIdx.x * 256 + threadIdx.x;
    if (idx >= NTOK * DMODEL) return;
    int d = idx & 511;
    int t = (idx >> 9) & 511;
    int i = d >> 1;
    float div = __expf(-(float)(2 * i) * (9.2103403719761836f / 512.f));
    float a = (float)t * div;
    float v = cur[idx] + ((d & 1) ? cosf(a) : sinf(a));
    cur[idx] = v;
    __nv_bfloat16 h = __float2bfloat16(v);
    g_ahi[idx] = h;
    g_alo[idx] = __float2bfloat16(v - __bfloat162float(h));
}

// ---------------- memory KV rows (bf16 split) ----------------
__global__ void memrows_kernel(const float* __restrict__ mk, const float* __restrict__ mv)
{
    int idx = blockIdx.x * 256 + threadIdx.x;
    if (idx >= BATCH * MMEM * DMODEL) return;
    int d = idx & 511;
    int r = idx >> 9;
    int m = r & 63;
    int b = r >> 6;
    size_t dst = ((size_t)(b * SFULL + TLEN + m)) * DMODEL + d;
    float kv = mk[m * DMODEL + d];
    float vv = mv[m * DMODEL + d];
    __nv_bfloat16 hk = __float2bfloat16(kv);
    g_kh[dst] = hk;
    g_kl[dst] = __float2bfloat16(kv - __bfloat162float(hk));
    __nv_bfloat16 hv = __float2bfloat16(vv);
    g_vh[dst] = hv;
    g_vl[dst] = __float2bfloat16(vv - __bfloat162float(hv));
}

// ---------------- tensor-core flash attention (bf16 in, split out) ----------------
#define AT_PITCH 72
#define AT_QH 0
#define AT_QL (128*AT_PITCH)
#define AT_KH (2*128*AT_PITCH)
#define AT_KL (AT_KH + 64*AT_PITCH)
#define AT_VH (AT_KL + 64*AT_PITCH)
#define AT_VL (AT_VH + 64*AT_PITCH)
#define ATTN_SMEM ((AT_VL + 64*AT_PITCH) * 2)
__global__ __launch_bounds__(256, 1)
void attn_mma(const __nv_bfloat16* __restrict__ qh, const __nv_bfloat16* __restrict__ ql,
              const __nv_bfloat16* __restrict__ kh, const __nv_bfloat16* __restrict__ kl,
              const __nv_bfloat16* __restrict__ vh, const __nv_bfloat16* __restrict__ vl,
              const int* __restrict__ seqlen,
              __nv_bfloat16* __restrict__ Ohi, __nv_bfloat16* __restrict__ Olo)
{
    extern __shared__ __nv_bfloat16 sb[];
    int q0 = blockIdx.x * 128, h = blockIdx.y, b = blockIdx.z;
    int tid = threadIdx.x, wid = tid >> 5, lane = tid & 31;
    int slen = seqlen[b];
    int l8 = lane & 7, mat = lane >> 3, g = lane >> 2, t2 = (lane & 3) * 2;
    int mrow = wid * 16;

    #pragma unroll
    for (int i = 0; i < 4; i++) {
        int u = i * 256 + tid;
        int r = u >> 3, c8 = u & 7;
        size_t src = ((size_t)(b * TLEN + q0 + r)) * DMODEL + h * DH + c8 * 8;
        *(uint4*)&sb[AT_QH + r * AT_PITCH + c8 * 8] = *(const uint4*)(qh + src);
        *(uint4*)&sb[AT_QL + r * AT_PITCH + c8 * 8] = *(const uint4*)(ql + src);
    }

    uint32_t QhB = s2u(sb + AT_QH), QlB = s2u(sb + AT_QL);
    uint32_t KhB = s2u(sb + AT_KH), KlB = s2u(sb + AT_KL);
    uint32_t VhB = s2u(sb + AT_VH), VlB = s2u(sb + AT_VL);

    float o[8][4] = {};
    float m0 = -1e30f, m1 = -1e30f, l0 = 0.f, l1 = 0.f;

    for (int s0 = 0; s0 < SFULL; s0 += 64) {
        __syncthreads();
        #pragma unroll
        for (int i = 0; i < 2; i++) {
            int u = i * 256 + tid;
            int r = u >> 3, c8 = u & 7;
            size_t src = ((size_t)(b * SFULL + s0 + r)) * DMODEL + h * DH + c8 * 8;
            uint32_t dst = r * AT_PITCH + c8 * 8;
            *(uint4*)&sb[AT_KH + dst] = *(const uint4*)(kh + src);
            *(uint4*)&sb[AT_KL + dst] = *(const uint4*)(kl + src);
            *(uint4*)&sb[AT_VH + dst] = *(const uint4*)(vh + src);
            *(uint4*)&sb[AT_VL + dst] = *(const uint4*)(vl + src);
        }
        __syncthreads();

        float sc[8][4] = {};
        #pragma unroll
        for (int pass = 0; pass < 3; pass++) {
            uint32_t aB = (pass == 2) ? QlB : QhB;
            uint32_t bB = (pass == 1) ? KlB : KhB;
            #pragma unroll
            for (int kc = 0; kc < 4; kc++) {
                uint32_t af[4];
                ldsm4(af, aB + (uint32_t)((mrow + (mat & 1) * 8 + l8) * AT_PITCH
                                          + kc * 16 + (mat >> 1) * 8) * 2);
                #pragma unroll
                for (int nf = 0; nf < 8; nf++) {
                    uint32_t bf2[2];
                    ldsm2(bf2, bB + (uint32_t)((nf * 8 + l8) * AT_PITCH
                                               + kc * 16 + ((lane >> 3) & 1) * 8) * 2);
                    mma_bf16(sc[nf], af, bf2);
                }
            }
        }

        float rm0 = -1e30f, rm1 = -1e30f;
        #pragma unroll
        for (int nf = 0; nf < 8; nf++) {
            #pragma unroll
            for (int j = 0; j < 4; j++) {
                int sg = s0 + nf * 8 + t2 + (j & 1);
                float v = sc[nf][j] * 0.125f;
                sc[nf][j] = (sg >= slen && sg < TLEN) ? -1e9f : v;
            }
            rm0 = fmaxf(rm0, fmaxf(sc[nf][0], sc[nf][1]));
            rm1 = fmaxf(rm1, fmaxf(sc[nf][2], sc[nf][3]));
        }
        rm0 = fmaxf(rm0, __shfl_xor_sync(0xffffffffu, rm0, 1));
        rm0 = fmaxf(rm0, __shfl_xor_sync(0xffffffffu, rm0, 2));
        rm1 = fmaxf(rm1, __shfl_xor_sync(0xffffffffu, rm1, 1));
        rm1 = fmaxf(rm1, __shfl_xor_sync(0xffffffffu, rm1, 2));
        float mn0 = fmaxf(m0, rm0), mn1 = fmaxf(m1, rm1);
        float e0 = __expf(m0 - mn0), e1 = __expf(m1 - mn1);
        float rs0 = 0.f, rs1 = 0.f;
        #pragma unroll
        for (int nf = 0; nf < 8; nf++) {
            sc[nf][0] = __expf(sc[nf][0] - mn0); rs0 += sc[nf][0];
            sc[nf][1] = __expf(sc[nf][1] - mn0); rs0 += sc[nf][1];
            sc[nf][2] = __expf(sc[nf][2] - mn1); rs1 += sc[nf][2];
            sc[nf][3] = __expf(sc[nf][3] - mn1); rs1 += sc[nf][3];
        }
        rs0 += __shfl_xor_sync(0xffffffffu, rs0, 1);
        rs0 += __shfl_xor_sync(0xffffffffu, rs0, 2);
        rs1 += __shfl_xor_sync(0xffffffffu, rs1, 1);
        rs1 += __shfl_xor_sync(0xffffffffu, rs1, 2);
        l0 = l0 * e0 + rs0; l1 = l1 * e1 + rs1;
        m0 = mn0; m1 = mn1;
        #pragma unroll
        for (int nf = 0; nf < 8; nf++) {
            o[nf][0] *= e0; o[nf][1] *= e0; o[nf][2] *= e1; o[nf][3] *= e1;
        }

        uint32_t phi[4][4], plo[4][4];
        #pragma unroll
        for (int kc = 0; kc < 4; kc++) {
            float* A = sc[2 * kc];
            float* B = sc[2 * kc + 1];
            phi[kc][0] = packbf(A[0], A[1]); phi[kc][1] = packbf(A[2], A[3]);
            phi[kc][2] = packbf(B[0], B[1]); phi[kc][3] = packbf(B[2], B[3]);
            plo[kc][0] = packbf(bfres(A[0]), bfres(A[1]));
            plo[kc][1] = packbf(bfres(A[2]), bfres(A[3]));
            plo[kc][2] = packbf(bfres(B[0]), bfres(B[1]));
            plo[kc][3] = packbf(bfres(B[2]), bfres(B[3]));
        }

        #pragma unroll
        for (int pass = 0; pass < 3; pass++) {
            uint32_t vB = (pass == 1) ? VlB : VhB;
            #pragma unroll
            for (int kc = 0; kc < 4; kc++) {
                const uint32_t* pf = (pass == 2) ? plo[kc] : phi[kc];
                #pragma unroll
                for (int nf = 0; nf < 8; nf++) {
                    uint32_t bf2[2];
                    ldsm2t(bf2, vB + (uint32_t)((kc * 16 + ((lane >> 3) & 1) * 8 + l8) * AT_PITCH
                                                + nf * 8) * 2);
                    mma_bf16(o[nf], pf, bf2);
                }
            }
        }
    }

    float inv0 = 1.f / l0, inv1 = 1.f / l1;
    int r0 = q0 + mrow + g;
    #pragma unroll
    for (int nf = 0; nf < 8; nf++) {
        int cc = h * DH + nf * 8 + t2;
        size_t i0 = ((size_t)(b * TLEN + r0)) * DMODEL + cc;
        size_t i1 = ((size_t)(b * TLEN + r0 + 8)) * DMODEL + cc;
        float v0 = o[nf][0] * inv0, v1 = o[nf][1] * inv0;
        float w0 = o[nf][2] * inv1, w1 = o[nf][3] * inv1;
        *(uint32_t*)(Ohi + i0) = packbf(v0, v1);
        *(uint32_t*)(Olo + i0) = packbf(bfres(v0), bfres(v1));
        *(uint32_t*)(Ohi + i1) = packbf(w0, w1);
        *(uint32_t*)(Olo + i1) = packbf(bfres(w0), bfres(w1));
    }
}

// ---------------- layernorm (emits split(cur)) ----------------
__global__ void ln_kernel(const float* __restrict__ X, float* __restrict__ Y,
                          const float* __restrict__ gw, const float* __restrict__ bw)
{
    __shared__ float red[128];
    int row = blockIdx.x, tid = threadIdx.x;
    const float* xr = X + (size_t)row * DMODEL;
    float v[4]; float s = 0.f;
    #pragma unroll
    for (int i = 0; i < 4; i++) { v[i] = xr[tid + 128 * i]; s += v[i]; }
    red[tid] = s; __syncthreads();
    for (int off = 64; off > 0; off >>= 1) {
        if (tid < off) red[tid] += red[tid + off];
        __syncthreads();
    }
    float mu = red[0] * (1.f / 512.f);
    __syncthreads();
    float s2 = 0.f;
    #pragma unroll
    for (int i = 0; i < 4; i++) { float d = v[i] - mu; s2 += d * d; }
    red[tid] = s2; __syncthreads();
    for (int off = 64; off > 0; off >>= 1) {
        if (tid < off) red[tid] += red[tid + off];
        __syncthreads();
    }
    float inv = rsqrtf(red[0] * (1.f / 512.f) + 1e-5f);
    #pragma unroll
    for (int i = 0; i < 4; i++) {
        int c = tid + 128 * i;
        float y = (v[i] - mu) * inv * gw[c] + bw[c];
        size_t idx = (size_t)row * DMODEL + c;
        Y[idx] = y;
        __nv_bfloat16 h = __float2bfloat16(y);
        g_ahi[idx] = h;
        g_alo[idx] = __float2bfloat16(y - __bfloat162float(h));
    }
}

// ---------------- aux ----------------
__global__ void aux_kernel(float* __restrict__ dst)
{
    float tot = 0.f;
    for (int l = 0; l < NLAYER; l++) {
        float m = 0.f;
        for (int e = 0; e < NEXP; e++) m += g_imp[l * 4 + e];
        m *= 0.25f;
        float var = 0.f;
        for (int e = 0; e < NEXP; e++) { float d = g_imp[l * 4 + e] - m; var += d * d; }
        var *= 0.25f;
        tot += var / (m * m + 1e-9f);
    }
    dst[0] = tot;
}

// ---------------- launcher ----------------
extern "C" void kernel_launch(void* const* d_in, const int* in_sizes, int n_in,
                              void* d_out, int out_size)
{
    const float* x         = (const float*)d_in[0];
    const int*   seq       = (const int*)  d_in[1];
    const float* emb_w1    = (const float*)d_in[2];
    const float* emb_b1    = (const float*)d_in[3];
    const float* emb_w2    = (const float*)d_in[4];
    const float* emb_wo    = (const float*)d_in[5];
    const float* f0_w1     = (const float*)d_in[6];
    const float* f0_b1     = (const float*)d_in[7];
    const float* f0_w2     = (const float*)d_in[8];
    const float* f0_router = (const float*)d_in[9];
    const float* f0_fb     = (const float*)d_in[10];
    const float* f0_fa     = (const float*)d_in[11];
    const float* f_w1      = (const float*)d_in[12];
    const float* f_b1      = (const float*)d_in[13];
    const float* f_w2      = (const float*)d_in[14];
    const float* f_router  = (const float*)d_in[15];
    const float* f_fb      = (const float*)d_in[16];
    const float* f_fa      = (const float*)d_in[17];
    const float* wq        = (const float*)d_in[18];
    const float* wk        = (const float*)d_in[19];
    const float* wv        = (const float*)d_in[20];
    const float* wvo       = (const float*)d_in[21];
    const float* mk        = (const float*)d_in[22];
    const float* mv        = (const float*)d_in[23];
    const float* lng       = (const float*)d_in[24];
    const float* lnb       = (const float*)d_in[25];
    const float* out_w     = (const float*)d_in[26];
    const float* out_b     = (const float*)d_in[27];
    float* out = (float*)d_out;

    float *embed, *cur, *p, *tmp, *gtok, *imp;
    int *cnt, *lists, *kvmap;
    __nv_bfloat16 *whi, *wlo, *ahi, *alo, *bhi, *blo, *qh, *ql, *kh, *kl, *vh, *vl;
    cudaGetSymbolAddress((void**)&embed, g_embed);
    cudaGetSymbolAddress((void**)&cur,   g_cur);
    cudaGetSymbolAddress((void**)&p,     g_p);
    cudaGetSymbolAddress((void**)&tmp,   g_tmp);
    cudaGetSymbolAddress((void**)&gtok,  g_gtok);
    cudaGetSymbolAddress((void**)&imp,   g_imp);
    cudaGetSymbolAddress((void**)&cnt,   g_cnt);
    cudaGetSymbolAddress((void**)&lists, g_lists);
    cudaGetSymbolAddress((void**)&kvmap, g_kvmap);
    cudaGetSymbolAddress((void**)&whi,   g_whi);
    cudaGetSymbolAddress((void**)&wlo,   g_wlo);
    cudaGetSymbolAddress((void**)&ahi,   g_ahi);
    cudaGetSymbolAddress((void**)&alo,   g_alo);
    cudaGetSymbolAddress((void**)&bhi,   g_bhi);
    cudaGetSymbolAddress((void**)&blo,   g_blo);
    cudaGetSymbolAddress((void**)&qh,    g_qh);
    cudaGetSymbolAddress((void**)&ql,    g_ql);
    cudaGetSymbolAddress((void**)&kh,    g_kh);
    cudaGetSymbolAddress((void**)&kl,    g_kl);
    cudaGetSymbolAddress((void**)&vh,    g_vh);
    cudaGetSymbolAddress((void**)&vl,    g_vl);

    cudaFuncSetAttribute(attn_mma, cudaFuncAttributeMaxDynamicSharedMemorySize, ATTN_SMEM);
    cudaFuncSetAttribute(tgemm, cudaFuncAttributeMaxDynamicSharedMemorySize, TG_SMEM);

    auto TG = [&](unsigned woff, const __nv_bfloat16* Ah, const __nv_bfloat16* Al,
                  float* C, __nv_bfloat16* Ch, __nv_bfloat16* Cl,
                  int M, int N, int K,
                  const float* bias, int relu, const int* ga, const int* sc,
                  const float* rs, const float* res, const int* Md,
                  int E = 1, int sB = 0, int sBias = 0, int sList = 0) {
        dim3 grid(N / 128, (M + 127) / 128, E);
        tgemm<<<grid, 256, TG_SMEM>>>(Ah, Al, whi + woff, wlo + woff, C, Ch, Cl, N, K, M,
                                      bias, relu, ga, sc, rs, res, Md, sB, sBias, sList);
    };
    auto WS = [&](const float* W, unsigned off, int nelem) {
        wsplit<<<(nelem / 4 + 255) / 256, 256>>>(W, whi + off, wlo + off, nelem / 4);
    };

    init_kernel<<<1, 1024>>>();

    WS(emb_w2, OFF_EMBW2, 1024 * 512);
    WS(emb_wo, OFF_EMBWO, 512 * 4096);
    WS(f0_w2,  OFF_F0W2, 4 * 1024 * 512);
    WS(f_w1,   OFF_FW1, 28 * 512 * 1024);
    WS(f_w2,   OFF_FW2, 28 * 1024 * 512);
    WS(wq,     OFF_WQ, 2 * 512 * 512);
    WS(wk,     OFF_WK, 2 * 512 * 512);
    WS(wv,     OFF_WV, 2 * 512 * 512);
    WS(wvo,    OFF_WO, 2 * 512 * 512);
    WS(out_w,  OFF_OUTW, 512 * 4096);

    // embed sub-network
    gemm128<<<dim3(8, 16, 1), 256>>>(x, emb_w1, bhi, blo, DHID, DIN, NTOK,
                                     emb_b1, 1, 0, 0, 0, 0, 0, 0);
    TG(OFF_EMBW2, bhi, blo, embed, ahi, alo, NTOK, DMODEL, DHID, 0, 0, 0, 0, 0, 0, 0);
    TG(OFF_EMBWO, ahi, alo, out + (size_t)NTOK * DOUT, 0, 0, NTOK, DOUT, DMODEL,
       0, 0, 0, 0, 0, 0, 0);

    // all routers at once (depend only on embed)
    router_all<<<dim3(NTOK / 8, NLAYER), 256>>>(embed, f0_router, f_router, seq,
                                                gtok, lists, cnt, imp);

    for (int l = 0; l < NLAYER; l++) {
        int* lst = lists + (size_t)l * NEXP * NTOK;
        float* gt = gtok + (size_t)l * NTOK;
        int* ct = cnt + l * 4;

        if (l == 0) {
            gemm128<<<dim3(8, 16, NEXP), 256>>>(x, f0_w1, bhi, blo, DHID, DIN, NTOK,
                                                f0_b1, 1, lst, lst, ct,
                                                DIN * DHID, DHID, NTOK);
            TG(OFF_F0W2, bhi, blo, p, 0, 0, NTOK, DMODEL, DHID, 0, 0, lst, lst,
               gt, 0, ct, NEXP, DMODEL * DHID, 0, NTOK);
        } else {
            TG(OFF_FW1 + (unsigned)(l - 1) * 4u * DMODEL * DHID, ahi, alo,
               0, bhi, blo, NTOK, DHID, DMODEL,
               f_b1 + (size_t)(l - 1) * NEXP * DHID, 1, lst, lst, 0, 0, ct,
               NEXP, DMODEL * DHID, DHID, NTOK);
            TG(OFF_FW2 + (unsigned)(l - 1) * 4u * DHID * DMODEL, bhi, blo,
               p, 0, 0, NTOK, DMODEL, DHID,
               0, 0, lst, lst, gt, 0, ct,
               NEXP, DHID * DMODEL, 0, NTOK);
        }
        const float* fbL = (l == 0) ? f0_fb : f_fb + (size_t)(l - 1) * 4 * DMODEL;
        const float* faL = (l == 0) ? f0_fa : f_fa + (size_t)(l - 1) * DMODEL;
        fsmn_kernel<<<NTOK * DMODEL / 256, 256>>>(p, fbL, faL,
                                                  (l == 0) ? (const float*)0 : cur, cur);

        if (l == 3) pe_kernel<<<NTOK * DMODEL / 256, 256>>>(cur);

        if (l == 3 || l == 7) {
            int bi = l / 4;
            unsigned wo = (unsigned)bi * 512u * 512u;
            TG(OFF_WQ + wo, ahi, alo, 0, qh, ql, NTOK, DMODEL, DMODEL, 0, 0, 0, 0, 0, 0, 0);
            TG(OFF_WK + wo, ahi, alo, 0, kh, kl, NTOK, DMODEL, DMODEL, 0, 0, 0, kvmap, 0, 0, 0);
            TG(OFF_WV + wo, ahi, alo, 0, vh, vl, NTOK, DMODEL, DMODEL, 0, 0, 0, kvmap, 0, 0, 0);
            memrows_kernel<<<BATCH * MMEM * DMODEL / 256, 256>>>(
                mk + (size_t)bi * MMEM * DMODEL, mv + (size_t)bi * MMEM * DMODEL);
            attn_mma<<<dim3(TLEN / 128, NHEAD, BATCH), 256, ATTN_SMEM>>>(
                qh, ql, kh, kl, vh, vl, seq, bhi, blo);
            TG(OFF_WO + wo, bhi, blo, tmp, 0, 0, NTOK, DMODEL, DMODEL, 0, 0, 0, 0, 0, cur, 0);
            ln_kernel<<<NTOK, 128>>>(tmp, cur, lng + bi * DMODEL, lnb + bi * DMODEL);
        }
    }

    TG(OFF_OUTW, ahi, alo, out, 0, 0, NTOK, DOUT, DMODEL, out_b, 0, 0, 0, 0, 0, 0);
    aux_kernel<<<1, 1>>>(out + 2 * (size_t)NTOK * DOUT);
}

// round 8
// speedup vs baseline: 4.5115x; 1.0137x over previous
#include <cuda_runtime.h>
#include <cuda_bf16.h>
#include <math.h>
#include <stdint.h>

// ---------------- problem constants ----------------
#define BATCH 4
#define TLEN  512
#define NTOK  (BATCH*TLEN)
#define DIN   80
#define DOUT  4096
#define DMODEL 512
#define DHID  1024
#define NEXP  4
#define NLAYER 8
#define NHEAD 8
#define DH    64
#define MMEM  64
#define SFULL (TLEN+MMEM)
#define BSF   (BATCH*SFULL)
#define QKV_ROWS (NTOK + 2*BSF)

// ---------------- device scratch ----------------
__device__ float g_embed[NTOK*DMODEL];
__device__ float g_cur[NTOK*DMODEL];
__device__ float g_p[NTOK*DMODEL];
__device__ float g_tmp[NTOK*DMODEL];
__device__ float g_gtok[NLAYER*NTOK];
__device__ float g_imp[NLAYER*NEXP];
__device__ int   g_cnt[NLAYER*NEXP];
__device__ int   g_lists[NLAYER*NEXP*NTOK];
__device__ int   g_maps[3*NTOK];     // [identity | NTOK+kvmap | NTOK+BSF+kvmap]

#define WPOOL (40u*1024u*1024u)
__device__ __nv_bfloat16 g_whi[WPOOL];
__device__ __nv_bfloat16 g_wlo[WPOOL];
__device__ __nv_bfloat16 g_ahi[NTOK*DMODEL];
__device__ __nv_bfloat16 g_alo[NTOK*DMODEL];
__device__ __nv_bfloat16 g_bhi[NTOK*DHID];
__device__ __nv_bfloat16 g_blo[NTOK*DHID];
__device__ __nv_bfloat16 g_qkvh[QKV_ROWS*DMODEL];
__device__ __nv_bfloat16 g_qkvl[QKV_ROWS*DMODEL];

#define OFF_EMBW2 0u
#define OFF_EMBWO (OFF_EMBW2 + 512u*1024u)
#define OFF_F0W2  (OFF_EMBWO + 4096u*512u)
#define OFF_FW1   (OFF_F0W2 + 4u*512u*1024u)
#define OFF_FW2   (OFF_FW1 + 28u*1024u*512u)
#define OFF_QKV   (OFF_FW2 + 28u*512u*1024u)    // per bi: [wq|wk|wv] each 512*512
#define OFF_WO    (OFF_QKV + 6u*512u*512u)
#define OFF_OUTW  (OFF_WO + 2u*512u*512u)
#define MAT_SZ    (512u*512u)

// ---------------- helpers ----------------
__device__ __forceinline__ uint32_t s2u(const void* p) {
    uint32_t a;
    asm("{ .reg .u64 t; cvta.to.shared.u64 t, %1; cvt.u32.u64 %0, t; }" : "=r"(a) : "l"(p));
    return a;
}
__device__ __forceinline__ void ldsm4(uint32_t* r, uint32_t addr) {
    asm volatile("ldmatrix.sync.aligned.m8n8.x4.shared.b16 {%0,%1,%2,%3}, [%4];"
        : "=r"(r[0]), "=r"(r[1]), "=r"(r[2]), "=r"(r[3]) : "r"(addr));
}
__device__ __forceinline__ void ldsm2(uint32_t* r, uint32_t addr) {
    asm volatile("ldmatrix.sync.aligned.m8n8.x2.shared.b16 {%0,%1}, [%2];"
        : "=r"(r[0]), "=r"(r[1]) : "r"(addr));
}
__device__ __forceinline__ void ldsm2t(uint32_t* r, uint32_t addr) {
    asm volatile("ldmatrix.sync.aligned.m8n8.x2.trans.shared.b16 {%0,%1}, [%2];"
        : "=r"(r[0]), "=r"(r[1]) : "r"(addr));
}
__device__ __forceinline__ void mma_bf16(float* c, const uint32_t* a, const uint32_t* b) {
    asm volatile("mma.sync.aligned.m16n8k16.row.col.f32.bf16.bf16.f32 "
        "{%0,%1,%2,%3}, {%4,%5,%6,%7}, {%8,%9}, {%0,%1,%2,%3};"
        : "+f"(c[0]), "+f"(c[1]), "+f"(c[2]), "+f"(c[3])
        : "r"(a[0]), "r"(a[1]), "r"(a[2]), "r"(a[3]), "r"(b[0]), "r"(b[1]));
}
__device__ __forceinline__ uint32_t packbf(float a, float b) {
    __nv_bfloat162 h = __floats2bfloat162_rn(a, b);
    return *(uint32_t*)&h;
}
__device__ __forceinline__ float bfres(float x) {
    return x - __bfloat162float(__float2bfloat16(x));
}
#define CPA(dst, src, sz) asm volatile("cp.async.ca.shared.global [%0], [%1], 16, %2;" \
    :: "r"(dst), "l"(src), "r"(sz))
#define CPC() asm volatile("cp.async.commit_group;" ::: "memory")
#define CPW() asm volatile("cp.async.wait_group 0;" ::: "memory")

// ---------------- init ----------------
__global__ void init_kernel() {
    int t = threadIdx.x;
    if (t < NLAYER*NEXP) { g_cnt[t] = 0; g_imp[t] = 0.f; }
    for (int i = t; i < NTOK; i += blockDim.x) {
        int kv = (i >> 9) * SFULL + (i & 511);
        g_maps[i] = i;
        g_maps[NTOK + i] = NTOK + kv;
        g_maps[2 * NTOK + i] = NTOK + BSF + kv;
    }
}

// ---------------- streaming weight split, 4x ILP ----------------
__global__ void wsplit(const float* __restrict__ W, __nv_bfloat16* __restrict__ hi,
                       __nv_bfloat16* __restrict__ lo, int n4)
{
    int base = (blockIdx.x * 256 + threadIdx.x) * 4;
    if (base + 3 >= n4 + 4 && base >= n4) return;
    float4 v[4];
    #pragma unroll
    for (int j = 0; j < 4; j++) v[j] = ((const float4*)W)[base + j];
    #pragma unroll
    for (int j = 0; j < 4; j++) {
        __nv_bfloat162 h01 = __floats2bfloat162_rn(v[j].x, v[j].y);
        __nv_bfloat162 h23 = __floats2bfloat162_rn(v[j].z, v[j].w);
        __nv_bfloat162 l01 = __floats2bfloat162_rn(v[j].x - __bfloat162float(h01.x),
                                                   v[j].y - __bfloat162float(h01.y));
        __nv_bfloat162 l23 = __floats2bfloat162_rn(v[j].z - __bfloat162float(h23.x),
                                                   v[j].w - __bfloat162float(h23.y));
        uint2 hw, lw;
        hw.x = *(uint32_t*)&h01; hw.y = *(uint32_t*)&h23;
        lw.x = *(uint32_t*)&l01; lw.y = *(uint32_t*)&l23;
        *(uint2*)(hi + (size_t)(base + j) * 4) = hw;
        *(uint2*)(lo + (size_t)(base + j) * 4) = lw;
    }
}

// ---------------- bf16 TC GEMM (A [M,K] row-major, B [K,N] k-major, cp.async 2-stage) ----------------
#define KC 32
#define APITCHB 80
#define BPITCHB 272
#define A_TILE (128*APITCHB)
#define B_TILE (KC*BPITCHB)
#define STG (2*A_TILE + 2*B_TILE)
#define TG_SMEM (2*STG)
__global__ __launch_bounds__(256, 2)
void tgemm(const __nv_bfloat16* __restrict__ Ahi, const __nv_bfloat16* __restrict__ Alo,
           const __nv_bfloat16* __restrict__ Bhi, const __nv_bfloat16* __restrict__ Blo,
           float* __restrict__ C,
           __nv_bfloat16* __restrict__ Chi, __nv_bfloat16* __restrict__ Clo,
           int N, int K, int Mstatic,
           const float* __restrict__ bias, int doRelu,
           const int* __restrict__ gatherA, const int* __restrict__ scatterC,
           const float* __restrict__ rowScale, const float* __restrict__ residual,
           const int* __restrict__ Mdev, int strideB, int strideBias, int strideList)
{
    extern __shared__ char smem[];
    int e = blockIdx.z;
    const __nv_bfloat16* Bhz = Bhi + (size_t)e * strideB;
    const __nv_bfloat16* Blz = Blo + (size_t)e * strideB;
    const float* biasz = bias ? bias + (size_t)e * strideBias : (const float*)0;
    const int* gA = gatherA ? gatherA + (size_t)e * strideList : (const int*)0;
    const int* sC = scatterC ? scatterC + (size_t)e * strideList : (const int*)0;
    int Ml = Mdev ? Mdev[e] : Mstatic;
    int row0 = blockIdx.y * 128;
    if (row0 >= Ml) return;
    int col0 = blockIdx.x * 128;
    int tid = threadIdx.x, wid = tid >> 5, lane = tid & 31;
    uint32_t sb = s2u(smem);

    int arow[2], lr[2], lu[2];
    #pragma unroll
    for (int i = 0; i < 2; i++) {
        int unit = tid + i * 256;
        lr[i] = unit >> 2;
        lu[i] = unit & 3;
        int gr = row0 + lr[i];
        arow[i] = (gr < Ml) ? (gA ? gA[gr] : gr) : -1;
    }

    auto issue = [&](int c, int stage) {
        int k0 = c * KC;
        uint32_t base = sb + stage * STG;
        #pragma unroll
        for (int i = 0; i < 2; i++) {
            uint32_t offA = (uint32_t)(lr[i] * APITCHB + lu[i] * 16);
            int ar = arow[i] >= 0 ? arow[i] : 0;
            uint32_t asz = arow[i] >= 0 ? 16u : 0u;
            CPA(base + offA, (const char*)(Ahi + (size_t)ar * K + k0 + lu[i] * 8), asz);
            CPA(base + A_TILE + offA, (const char*)(Alo + (size_t)ar * K + k0 + lu[i] * 8), asz);
            int unit = tid + i * 256;
            int bk = unit >> 4, bc16 = unit & 15;
            uint32_t offB = (uint32_t)(bk * BPITCHB + bc16 * 16);
            const char* bh = (const char*)(Bhz + (size_t)(k0 + bk) * N + col0 + bc16 * 8);
            const char* bl = (const char*)(Blz + (size_t)(k0 + bk) * N + col0 + bc16 * 8);
            CPA(base + 2u * A_TILE + offB, bh, 16u);
            CPA(base + 2u * A_TILE + B_TILE + offB, bl, 16u);
        }
    };

    float acc[4][4][4] = {};
    int wm = wid >> 2, wn = wid & 3;
    int m_base = wm * 64, n_base = wn * 32;
    int l8 = lane & 7, mat = lane >> 3, bsel = (lane >> 3) & 1;

    int nc = K / KC;
    issue(0, 0); CPC();

    for (int c = 0; c < nc; c++) {
        CPW();
        __syncthreads();
        if (c + 1 < nc) { issue(c + 1, (c + 1) & 1); CPC(); }

        uint32_t base = sb + (c & 1) * STG;
        uint32_t ahB = base, alB = base + A_TILE;
        uint32_t bhB = base + 2u * A_TILE, blB = base + 2u * A_TILE + B_TILE;
        #pragma unroll
        for (int ks = 0; ks < 2; ks++) {
            int kb = ks * 16;
            uint32_t aoff = (uint32_t)(kb + (mat >> 1) * 8) * 2;
            uint32_t af[4][4], bfh[4][2], bfl[4][2];
            #pragma unroll
            for (int mf = 0; mf < 4; mf++)
                ldsm4(af[mf], ahB + (uint32_t)(m_base + mf * 16 + (mat & 1) * 8 + l8) * APITCHB + aoff);
            #pragma unroll
            for (int nf = 0; nf < 4; nf++)
                ldsm2t(bfh[nf], bhB + (uint32_t)(kb + bsel * 8 + l8) * BPITCHB
                                    + (uint32_t)(n_base + nf * 8) * 2);
            #pragma unroll
            for (int mf = 0; mf < 4; mf++)
                #pragma unroll
                for (int nf = 0; nf < 4; nf++)
                    mma_bf16(acc[mf][nf], af[mf], bfh[nf]);
            #pragma unroll
            for (int nf = 0; nf < 4; nf++)
                ldsm2t(bfl[nf], blB + (uint32_t)(kb + bsel * 8 + l8) * BPITCHB
                                    + (uint32_t)(n_base + nf * 8) * 2);
            #pragma unroll
            for (int mf = 0; mf < 4; mf++)
                #pragma unroll
                for (int nf = 0; nf < 4; nf++)
                    mma_bf16(acc[mf][nf], af[mf], bfl[nf]);
            #pragma unroll
            for (int mf = 0; mf < 4; mf++)
                ldsm4(af[mf], alB + (uint32_t)(m_base + mf * 16 + (mat & 1) * 8 + l8) * APITCHB + aoff);
            #pragma unroll
            for (int mf = 0; mf < 4; mf++)
                #pragma unroll
                for (int nf = 0; nf < 4; nf++)
                    mma_bf16(acc[mf][nf], af[mf], bfh[nf]);
        }
    }

    int g = lane >> 2, t2 = (lane & 3) * 2;
    #pragma unroll
    for (int mf = 0; mf < 4; mf++) {
        #pragma unroll
        for (int half = 0; half < 2; half++) {
            int r = row0 + m_base + mf * 16 + g + half * 8;
            if (r >= Ml) continue;
            int orow = sC ? sC[r] : r;
            float sc = rowScale ? rowScale[orow] : 1.f;
            size_t rb = (size_t)orow * N;
            #pragma unroll
            for (int nf = 0; nf < 4; nf++) {
                int cc = col0 + n_base + nf * 8 + t2;
                float v0 = acc[mf][nf][half * 2 + 0] * sc;
                float v1 = acc[mf][nf][half * 2 + 1] * sc;
                if (biasz) { v0 += biasz[cc]; v1 += biasz[cc + 1]; }
                if (residual) { v0 += residual[rb + cc]; v1 += residual[rb + cc + 1]; }
                if (doRelu) { v0 = fmaxf(v0, 0.f); v1 = fmaxf(v1, 0.f); }
                if (C) *(float2*)(C + rb + cc) = make_float2(v0, v1);
                if (Chi) {
                    *(uint32_t*)(Chi + rb + cc) = packbf(v0, v1);
                    *(uint32_t*)(Clo + rb + cc) = packbf(bfres(v0), bfres(v1));
                }
            }
        }
    }
}

// ---------------- SIMT GEMM (K=80 cases), emits split ----------------
#define TK 8
__global__ __launch_bounds__(256, 2)
void gemm128(const float* __restrict__ A, const float* __restrict__ Bm,
             __nv_bfloat16* __restrict__ Chi, __nv_bfloat16* __restrict__ Clo,
             int N, int K, int Mstatic,
             const float* __restrict__ bias, int doRelu,
             const int* __restrict__ gatherA, const int* __restrict__ scatterC,
             const int* __restrict__ Mdev, int strideB, int strideBias, int strideList)
{
    __shared__ float As[2][TK][132];
    __shared__ float Bs[2][TK][132];
    int e = blockIdx.z;
    const float* Bz = Bm + (size_t)e * strideB;
    const float* biasz = bias ? bias + (size_t)e * strideBias : (const float*)0;
    const int* gA = gatherA ? gatherA + (size_t)e * strideList : (const int*)0;
    const int* sC = scatterC ? scatterC + (size_t)e * strideList : (const int*)0;
    int Ml = Mdev ? Mdev[e] : Mstatic;
    int row0 = blockIdx.y * 128;
    if (row0 >= Ml) return;
    int col0 = blockIdx.x * 128;
    int tid = threadIdx.x;
    int tx = tid & 15, ty = tid >> 4;

    int ar_ = tid >> 1;
    int ah = (tid & 1) * 4;
    int agr = row0 + ar_;
    int arow = -1;
    if (agr < Ml) arow = gA ? gA[agr] : agr;
    int bkr = tid >> 5;
    int bc = (tid & 31) * 4;
    int nk = (K + TK - 1) / TK;

    auto ldA = [&](int k0) {
        float4 v = make_float4(0.f, 0.f, 0.f, 0.f);
        if (arow >= 0) {
            if (k0 + ah + 3 < K) v = *(const float4*)(A + (size_t)arow * K + k0 + ah);
            else {
                const float* p = A + (size_t)arow * K;
                float t[4];
                #pragma unroll
                for (int q = 0; q < 4; q++) t[q] = (k0 + ah + q < K) ? p[k0 + ah + q] : 0.f;
                v = make_float4(t[0], t[1], t[2], t[3]);
            }
        }
        return v;
    };
    auto ldB = [&](int k0) {
        if (k0 + bkr < K) return *(const float4*)(Bz + (size_t)(k0 + bkr) * N + col0 + bc);
        return make_float4(0.f, 0.f, 0.f, 0.f);
    };

    float4 av = ldA(0), bv = ldB(0);
    As[0][ah + 0][ar_] = av.x; As[0][ah + 1][ar_] = av.y;
    As[0][ah + 2][ar_] = av.z; As[0][ah + 3][ar_] = av.w;
    *(float4*)&Bs[0][bkr][bc] = bv;
    __syncthreads();

    float acc[8][8] = {};
    int ty8 = ty * 8, tx8 = tx * 8;
    for (int t = 0; t < nk; t++) {
        int cur = t & 1, nxt = cur ^ 1;
        if (t + 1 < nk) { av = ldA((t + 1) * TK); bv = ldB((t + 1) * TK); }
        #pragma unroll
        for (int k = 0; k < TK; k++) {
            float4 a0 = *(const float4*)&As[cur][k][ty8];
            float4 a1 = *(const float4*)&As[cur][k][ty8 + 4];
            float4 b0 = *(const float4*)&Bs[cur][k][tx8];
            float4 b1 = *(const float4*)&Bs[cur][k][tx8 + 4];
            float aa[8] = {a0.x, a0.y, a0.z, a0.w, a1.x, a1.y, a1.z, a1.w};
            float bb[8] = {b0.x, b0.y, b0.z, b0.w, b1.x, b1.y, b1.z, b1.w};
            #pragma unroll
            for (int i = 0; i < 8; i++)
                #pragma unroll
                for (int j = 0; j < 8; j++)
                    acc[i][j] += aa[i] * bb[j];
        }
        if (t + 1 < nk) {
            As[nxt][ah + 0][ar_] = av.x; As[nxt][ah + 1][ar_] = av.y;
            As[nxt][ah + 2][ar_] = av.z; As[nxt][ah + 3][ar_] = av.w;
            *(float4*)&Bs[nxt][bkr][bc] = bv;
        }
        __syncthreads();
    }
    float bb[8] = {};
    if (biasz) {
        #pragma unroll
        for (int j = 0; j < 8; j++) bb[j] = biasz[col0 + tx8 + j];
    }
    #pragma unroll
    for (int i = 0; i < 8; i++) {
        int r = row0 + ty8 + i;
        if (r >= Ml) continue;
        int orow = sC ? sC[r] : r;
        size_t cb = (size_t)orow * N + col0 + tx8;
        #pragma unroll
        for (int j = 0; j < 8; j += 2) {
            float v0 = acc[i][j] + bb[j];
            float v1 = acc[i][j + 1] + bb[j + 1];
            if (doRelu) { v0 = fmaxf(v0, 0.f); v1 = fmaxf(v1, 0.f); }
            *(uint32_t*)(Chi + cb + j) = packbf(v0, v1);
            *(uint32_t*)(Clo + cb + j) = packbf(bfres(v0), bfres(v1));
        }
    }
}

// ---------------- fused router (all layers) ----------------
__global__ void router_all(const float* __restrict__ embed, const float* __restrict__ f0r,
                           const float* __restrict__ fr, const int* __restrict__ seqlen,
                           float* __restrict__ gtokA, int* __restrict__ listsA,
                           int* __restrict__ cntA, float* __restrict__ impA)
{
    int l = blockIdx.y;
    const float* R = (l == 0) ? f0r : fr + (size_t)(l - 1) * DMODEL * NEXP;
    float* gtok = gtokA + (size_t)l * NTOK;
    int* lists = listsA + (size_t)l * NEXP * NTOK;
    int* cnt = cntA + l * NEXP;
    float* imp = impA + l * NEXP;

    int gw = (blockIdx.x * blockDim.x + threadIdx.x) >> 5;
    int lane = threadIdx.x & 31;
    if (gw >= NTOK) return;
    const float* xr = embed + (size_t)gw * DMODEL;
    float l0 = 0, l1 = 0, l2 = 0, l3 = 0;
    for (int d = lane; d < DMODEL; d += 32) {
        float v = xr[d];
        const float* rr = R + d * 4;
        l0 += v * rr[0]; l1 += v * rr[1]; l2 += v * rr[2]; l3 += v * rr[3];
    }
    for (int off = 16; off; off >>= 1) {
        l0 += __shfl_xor_sync(0xffffffffu, l0, off);
        l1 += __shfl_xor_sync(0xffffffffu, l1, off);
        l2 += __shfl_xor_sync(0xffffffffu, l2, off);
        l3 += __shfl_xor_sync(0xffffffffu, l3, off);
    }
    if (lane == 0) {
        float mx = fmaxf(fmaxf(l0, l1), fmaxf(l2, l3));
        float e0 = __expf(l0 - mx), e1 = __expf(l1 - mx);
        float e2 = __expf(l2 - mx), e3 = __expf(l3 - mx);
        float inv = 1.f / (e0 + e1 + e2 + e3);
        float s0 = e0 * inv, s1 = e1 * inv, s2 = e2 * inv, s3 = e3 * inv;
        int em = 0; float gm = s0;
        if (s1 > gm) { gm = s1; em = 1; }
        if (s2 > gm) { gm = s2; em = 2; }
        if (s3 > gm) { gm = s3; em = 3; }
        int b = gw >> 9, t = gw & 511;
        if (t < seqlen[b]) {
            atomicAdd(&imp[0], s0); atomicAdd(&imp[1], s1);
            atomicAdd(&imp[2], s2); atomicAdd(&imp[3], s3);
        }
        gtok[gw] = gm;
        int slot = atomicAdd(&cnt[em], 1);
        lists[em * NTOK + slot] = gw;
    }
}

// ---------------- FSMN (+optional PE, emits split(cur)) ----------------
__global__ void fsmn_kernel(const float* __restrict__ P, const float* __restrict__ fb,
                            const float* __restrict__ fa, const float* __restrict__ skipin,
                            float* __restrict__ outp, int doPE)
{
    int idx = blockIdx.x * 256 + threadIdx.x;
    if (idx >= NTOK * DMODEL) return;
    int d = idx & 511;
    int t = (idx >> 9) & 511;
    float v = P[idx];
    #pragma unroll
    for (int k = 0; k < 4; k++) {
        int off = (k + 1) * 2;
        if (t - off >= 0) v += fb[k * DMODEL + d] * P[idx - off * DMODEL];
    }
    if (t + 1 < TLEN) v += fa[d] * P[idx + DMODEL];
    if (skipin) v += skipin[idx];
    if (doPE) {
        int i = d >> 1;
        float div = __expf(-(float)(2 * i) * (9.2103403719761836f / 512.f));
        float a = (float)t * div;
        v += (d & 1) ? cosf(a) : sinf(a);
    }
    outp[idx] = v;
    __nv_bfloat16 h = __float2bfloat16(v);
    g_ahi[idx] = h;
    g_alo[idx] = __float2bfloat16(v - __bfloat162float(h));
}

// ---------------- memory KV rows -> qkv buffer sections ----------------
__global__ void memrows_kernel(const float* __restrict__ mk, const float* __restrict__ mv)
{
    int idx = blockIdx.x * 256 + threadIdx.x;
    if (idx >= BATCH * MMEM * DMODEL) return;
    int d = idx & 511;
    int r = idx >> 9;
    int m = r & 63;
    int b = r >> 6;
    size_t krow = (size_t)(NTOK + b * SFULL + TLEN + m);
    size_t vrow = krow + BSF;
    float kv = mk[m * DMODEL + d];
    float vv = mv[m * DMODEL + d];
    __nv_bfloat16 hk = __float2bfloat16(kv);
    g_qkvh[krow * DMODEL + d] = hk;
    g_qkvl[krow * DMODEL + d] = __float2bfloat16(kv - __bfloat162float(hk));
    __nv_bfloat16 hv = __float2bfloat16(vv);
    g_qkvh[vrow * DMODEL + d] = hv;
    g_qkvl[vrow * DMODEL + d] = __float2bfloat16(vv - __bfloat162float(hv));
}

// ---------------- tensor-core flash attention ----------------
#define AT_PITCH 72
#define AT_QH 0
#define AT_QL (128*AT_PITCH)
#define AT_KH (2*128*AT_PITCH)
#define AT_KL (AT_KH + 64*AT_PITCH)
#define AT_VH (AT_KL + 64*AT_PITCH)
#define AT_VL (AT_VH + 64*AT_PITCH)
#define ATTN_SMEM ((AT_VL + 64*AT_PITCH) * 2)
__global__ __launch_bounds__(256, 1)
void attn_mma(const __nv_bfloat16* __restrict__ qh, const __nv_bfloat16* __restrict__ ql,
              const __nv_bfloat16* __restrict__ kh, const __nv_bfloat16* __restrict__ kl,
              const __nv_bfloat16* __restrict__ vh, const __nv_bfloat16* __restrict__ vl,
              const int* __restrict__ seqlen,
              __nv_bfloat16* __restrict__ Ohi, __nv_bfloat16* __restrict__ Olo)
{
    extern __shared__ __nv_bfloat16 sb[];
    int q0 = blockIdx.x * 128, h = blockIdx.y, b = blockIdx.z;
    int tid = threadIdx.x, wid = tid >> 5, lane = tid & 31;
    int slen = seqlen[b];
    int l8 = lane & 7, mat = lane >> 3, g = lane >> 2, t2 = (lane & 3) * 2;
    int mrow = wid * 16;

    #pragma unroll
    for (int i = 0; i < 4; i++) {
        int u = i * 256 + tid;
        int r = u >> 3, c8 = u & 7;
        size_t src = ((size_t)(b * TLEN + q0 + r)) * DMODEL + h * DH + c8 * 8;
        *(uint4*)&sb[AT_QH + r * AT_PITCH + c8 * 8] = *(const uint4*)(qh + src);
        *(uint4*)&sb[AT_QL + r * AT_PITCH + c8 * 8] = *(const uint4*)(ql + src);
    }

    uint32_t QhB = s2u(sb + AT_QH), QlB = s2u(sb + AT_QL);
    uint32_t KhB = s2u(sb + AT_KH), KlB = s2u(sb + AT_KL);
    uint32_t VhB = s2u(sb + AT_VH), VlB = s2u(sb + AT_VL);

    float o[8][4] = {};
    float m0 = -1e30f, m1 = -1e30f, l0 = 0.f, l1 = 0.f;

    for (int s0 = 0; s0 < SFULL; s0 += 64) {
        __syncthreads();
        #pragma unroll
        for (int i = 0; i < 2; i++) {
            int u = i * 256 + tid;
            int r = u >> 3, c8 = u & 7;
            size_t src = ((size_t)(b * SFULL + s0 + r)) * DMODEL + h * DH + c8 * 8;
            uint32_t dst = r * AT_PITCH + c8 * 8;
            *(uint4*)&sb[AT_KH + dst] = *(const uint4*)(kh + src);
            *(uint4*)&sb[AT_KL + dst] = *(const uint4*)(kl + src);
            *(uint4*)&sb[AT_VH + dst] = *(const uint4*)(vh + src);
            *(uint4*)&sb[AT_VL + dst] = *(const uint4*)(vl + src);
        }
        __syncthreads();

        float sc[8][4] = {};
        #pragma unroll
        for (int pass = 0; pass < 3; pass++) {
            uint32_t aB = (pass == 2) ? QlB : QhB;
            uint32_t bB = (pass == 1) ? KlB : KhB;
            #pragma unroll
            for (int kc = 0; kc < 4; kc++) {
                uint32_t af[4];
                ldsm4(af, aB + (uint32_t)((mrow + (mat & 1) * 8 + l8) * AT_PITCH
                                          + kc * 16 + (mat >> 1) * 8) * 2);
                #pragma unroll
                for (int nf = 0; nf < 8; nf++) {
                    uint32_t bf2[2];
                    ldsm2(bf2, bB + (uint32_t)((nf * 8 + l8) * AT_PITCH
                                               + kc * 16 + ((lane >> 3) & 1) * 8) * 2);
                    mma_bf16(sc[nf], af, bf2);
                }
            }
        }

        float rm0 = -1e30f, rm1 = -1e30f;
        #pragma unroll
        for (int nf = 0; nf < 8; nf++) {
            #pragma unroll
            for (int j = 0; j < 4; j++) {
                int sg = s0 + nf * 8 + t2 + (j & 1);
                float v = sc[nf][j] * 0.125f;
                sc[nf][j] = (sg >= slen && sg < TLEN) ? -1e9f : v;
            }
            rm0 = fmaxf(rm0, fmaxf(sc[nf][0], sc[nf][1]));
            rm1 = fmaxf(rm1, fmaxf(sc[nf][2], sc[nf][3]));
        }
        rm0 = fmaxf(rm0, __shfl_xor_sync(0xffffffffu, rm0, 1));
        rm0 = fmaxf(rm0, __shfl_xor_sync(0xffffffffu, rm0, 2));
        rm1 = fmaxf(rm1, __shfl_xor_sync(0xffffffffu, rm1, 1));
        rm1 = fmaxf(rm1, __shfl_xor_sync(0xffffffffu, rm1, 2));
        float mn0 = fmaxf(m0, rm0), mn1 = fmaxf(m1, rm1);
        float e0 = __expf(m0 - mn0), e1 = __expf(m1 - mn1);
        float rs0 = 0.f, rs1 = 0.f;
        #pragma unroll
        for (int nf = 0; nf < 8; nf++) {
            sc[nf][0] = __expf(sc[nf][0] - mn0); rs0 += sc[nf][0];
            sc[nf][1] = __expf(sc[nf][1] - mn0); rs0 += sc[nf][1];
            sc[nf][2] = __expf(sc[nf][2] - mn1); rs1 += sc[nf][2];
            sc[nf][3] = __expf(sc[nf][3] - mn1); rs1 += sc[nf][3];
        }
        rs0 += __shfl_xor_sync(0xffffffffu, rs0, 1);
        rs0 += __shfl_xor_sync(0xffffffffu, rs0, 2);
        rs1 += __shfl_xor_sync(0xffffffffu, rs1, 1);
        rs1 += __shfl_xor_sync(0xffffffffu, rs1, 2);
        l0 = l0 * e0 + rs0; l1 = l1 * e1 + rs1;
        m0 = mn0; m1 = mn1;
        #pragma unroll
        for (int nf = 0; nf < 8; nf++) {
            o[nf][0] *= e0; o[nf][1] *= e0; o[nf][2] *= e1; o[nf][3] *= e1;
        }

        uint32_t phi[4][4], plo[4][4];
        #pragma unroll
        for (int kc = 0; kc < 4; kc++) {
            float* A = sc[2 * kc];
            float* B = sc[2 * kc + 1];
            phi[kc][0] = packbf(A[0], A[1]); phi[kc][1] = packbf(A[2], A[3]);
            phi[kc][2] = packbf(B[0], B[1]); phi[kc][3] = packbf(B[2], B[3]);
            plo[kc][0] = packbf(bfres(A[0]), bfres(A[1]));
            plo[kc][1] = packbf(bfres(A[2]), bfres(A[3]));
            plo[kc][2] = packbf(bfres(B[0]), bfres(B[1]));
            plo[kc][3] = packbf(bfres(B[2]), bfres(B[3]));
        }

        #pragma unroll
        for (int pass = 0; pass < 3; pass++) {
            uint32_t vB = (pass == 1) ? VlB : VhB;
            #pragma unroll
            for (int kc = 0; kc < 4; kc++) {
                const uint32_t* pf = (pass == 2) ? plo[kc] : phi[kc];
                #pragma unroll
                for (int nf = 0; nf < 8; nf++) {
                    uint32_t bf2[2];
                    ldsm2t(bf2, vB + (uint32_t)((kc * 16 + ((lane >> 3) & 1) * 8 + l8) * AT_PITCH
                                                + nf * 8) * 2);
                    mma_bf16(o[nf], pf, bf2);
                }
            }
        }
    }

    float inv0 = 1.f / l0, inv1 = 1.f / l1;
    int r0 = q0 + mrow + g;
    #pragma unroll
    for (int nf = 0; nf < 8; nf++) {
        int cc = h * DH + nf * 8 + t2;
        size_t i0 = ((size_t)(b * TLEN + r0)) * DMODEL + cc;
        size_t i1 = ((size_t)(b * TLEN + r0 + 8)) * DMODEL + cc;
        float v0 = o[nf][0] * inv0, v1 = o[nf][1] * inv0;
        float w0 = o[nf][2] * inv1, w1 = o[nf][3] * inv1;
        *(uint32_t*)(Ohi + i0) = packbf(v0, v1);
        *(uint32_t*)(Olo + i0) = packbf(bfres(v0), bfres(v1));
        *(uint32_t*)(Ohi + i1) = packbf(w0, w1);
        *(uint32_t*)(Olo + i1) = packbf(bfres(w0), bfres(w1));
    }
}

// ---------------- layernorm (emits split(cur)) ----------------
__global__ void ln_kernel(const float* __restrict__ X, float* __restrict__ Y,
                          const float* __restrict__ gw, const float* __restrict__ bw)
{
    __shared__ float red[128];
    int row = blockIdx.x, tid = threadIdx.x;
    const float* xr = X + (size_t)row * DMODEL;
    float v[4]; float s = 0.f;
    #pragma unroll
    for (int i = 0; i < 4; i++) { v[i] = xr[tid + 128 * i]; s += v[i]; }
    red[tid] = s; __syncthreads();
    for (int off = 64; off > 0; off >>= 1) {
        if (tid < off) red[tid] += red[tid + off];
        __syncthreads();
    }
    float mu = red[0] * (1.f / 512.f);
    __syncthreads();
    float s2 = 0.f;
    #pragma unroll
    for (int i = 0; i < 4; i++) { float d = v[i] - mu; s2 += d * d; }
    red[tid] = s2; __syncthreads();
    for (int off = 64; off > 0; off >>= 1) {
        if (tid < off) red[tid] += red[tid + off];
        __syncthreads();
    }
    float inv = rsqrtf(red[0] * (1.f / 512.f) + 1e-5f);
    #pragma unroll
    for (int i = 0; i < 4; i++) {
        int c = tid + 128 * i;
        float y = (v[i] - mu) * inv * gw[c] + bw[c];
        size_t idx = (size_t)row * DMODEL + c;
        Y[idx] = y;
        __nv_bfloat16 h = __float2bfloat16(y);
        g_ahi[idx] = h;
        g_alo[idx] = __float2bfloat16(y - __bfloat162float(h));
    }
}

// ---------------- aux ----------------
__global__ void aux_kernel(float* __restrict__ dst)
{
    float tot = 0.f;
    for (int l = 0; l < NLAYER; l++) {
        float m = 0.f;
        for (int e = 0; e < NEXP; e++) m += g_imp[l * 4 + e];
        m *= 0.25f;
        float var = 0.f;
        for (int e = 0; e < NEXP; e++) { float d = g_imp[l * 4 + e] - m; var += d * d; }
        var *= 0.25f;
        tot += var / (m * m + 1e-9f);
    }
    dst[0] = tot;
}

// ---------------- launcher ----------------
extern "C" void kernel_launch(void* const* d_in, const int* in_sizes, int n_in,
                              void* d_out, int out_size)
{
    const float* x         = (const float*)d_in[0];
    const int*   seq       = (const int*)  d_in[1];
    const float* emb_w1    = (const float*)d_in[2];
    const float* emb_b1    = (const float*)d_in[3];
    const float* emb_w2    = (const float*)d_in[4];
    const float* emb_wo    = (const float*)d_in[5];
    const float* f0_w1     = (const float*)d_in[6];
    const float* f0_b1     = (const float*)d_in[7];
    const float* f0_w2     = (const float*)d_in[8];
    const float* f0_router = (const float*)d_in[9];
    const float* f0_fb     = (const float*)d_in[10];
    const float* f0_fa     = (const float*)d_in[11];
    const float* f_w1      = (const float*)d_in[12];
    const float* f_b1      = (const float*)d_in[13];
    const float* f_w2      = (const float*)d_in[14];
    const float* f_router  = (const float*)d_in[15];
    const float* f_fb      = (const float*)d_in[16];
    const float* f_fa      = (const float*)d_in[17];
    const float* wq        = (const float*)d_in[18];
    const float* wk        = (const float*)d_in[19];
    const float* wv        = (const float*)d_in[20];
    const float* wvo       = (const float*)d_in[21];
    const float* mk        = (const float*)d_in[22];
    const float* mv        = (const float*)d_in[23];
    const float* lng       = (const float*)d_in[24];
    const float* lnb       = (const float*)d_in[25];
    const float* out_w     = (const float*)d_in[26];
    const float* out_b     = (const float*)d_in[27];
    float* out = (float*)d_out;

    float *embed, *cur, *p, *tmp, *gtok, *imp;
    int *cnt, *lists, *maps;
    __nv_bfloat16 *whi, *wlo, *ahi, *alo, *bhi, *blo, *qkvh, *qkvl;
    cudaGetSymbolAddress((void**)&embed, g_embed);
    cudaGetSymbolAddress((void**)&cur,   g_cur);
    cudaGetSymbolAddress((void**)&p,     g_p);
    cudaGetSymbolAddress((void**)&tmp,   g_tmp);
    cudaGetSymbolAddress((void**)&gtok,  g_gtok);
    cudaGetSymbolAddress((void**)&imp,   g_imp);
    cudaGetSymbolAddress((void**)&cnt,   g_cnt);
    cudaGetSymbolAddress((void**)&lists, g_lists);
    cudaGetSymbolAddress((void**)&maps,  g_maps);
    cudaGetSymbolAddress((void**)&whi,   g_whi);
    cudaGetSymbolAddress((void**)&wlo,   g_wlo);
    cudaGetSymbolAddress((void**)&ahi,   g_ahi);
    cudaGetSymbolAddress((void**)&alo,   g_alo);
    cudaGetSymbolAddress((void**)&bhi,   g_bhi);
    cudaGetSymbolAddress((void**)&blo,   g_blo);
    cudaGetSymbolAddress((void**)&qkvh,  g_qkvh);
    cudaGetSymbolAddress((void**)&qkvl,  g_qkvl);

    cudaFuncSetAttribute(attn_mma, cudaFuncAttributeMaxDynamicSharedMemorySize, ATTN_SMEM);
    cudaFuncSetAttribute(tgemm, cudaFuncAttributeMaxDynamicSharedMemorySize, TG_SMEM);

    cudaStream_t s1;
    cudaStreamCreate(&s1);
    cudaEvent_t evF, evJ;
    cudaEventCreateWithFlags(&evF, cudaEventDisableTiming);
    cudaEventCreateWithFlags(&evJ, cudaEventDisableTiming);

    auto TG = [&](unsigned woff, const __nv_bfloat16* Ah, const __nv_bfloat16* Al,
                  float* C, __nv_bfloat16* Ch, __nv_bfloat16* Cl,
                  int M, int N, int K,
                  const float* bias, int relu, const int* ga, const int* sc,
                  const float* rs, const float* res, const int* Md,
                  int E = 1, int sB = 0, int sBias = 0, int sList = 0) {
        dim3 grid(N / 128, (M + 127) / 128, E);
        tgemm<<<grid, 256, TG_SMEM>>>(Ah, Al, whi + woff, wlo + woff, C, Ch, Cl, N, K, M,
                                      bias, relu, ga, sc, rs, res, Md, sB, sBias, sList);
    };
    auto WS = [&](const float* W, unsigned off, int nelem, cudaStream_t st) {
        wsplit<<<nelem / 16 / 256, 256, 0, st>>>(W, whi + off, wlo + off, nelem / 4);
    };

    init_kernel<<<1, 1024>>>();

    // main-stream splits (needed early)
    WS(emb_w2, OFF_EMBW2, 1024 * 512, 0);
    WS(emb_wo, OFF_EMBWO, 512 * 4096, 0);
    WS(f0_w2,  OFF_F0W2, 4 * 1024 * 512, 0);

    // side-stream splits (needed from layer 1 onward) — overlapped with embed chain + layer 0
    cudaEventRecord(evF, 0);
    cudaStreamWaitEvent(s1, evF, 0);
    WS(f_w1, OFF_FW1, 28 * 512 * 1024, s1);
    WS(f_w2, OFF_FW2, 28 * 1024 * 512, s1);
    for (int bi = 0; bi < 2; bi++) {
        WS(wq + (size_t)bi * MAT_SZ, OFF_QKV + bi * 3u * MAT_SZ + 0u * MAT_SZ, MAT_SZ, s1);
        WS(wk + (size_t)bi * MAT_SZ, OFF_QKV + bi * 3u * MAT_SZ + 1u * MAT_SZ, MAT_SZ, s1);
        WS(wv + (size_t)bi * MAT_SZ, OFF_QKV + bi * 3u * MAT_SZ + 2u * MAT_SZ, MAT_SZ, s1);
    }
    WS(wvo,   OFF_WO, 2 * 512 * 512, s1);
    WS(out_w, OFF_OUTW, 512 * 4096, s1);
    cudaEventRecord(evJ, s1);

    // embed sub-network
    gemm128<<<dim3(8, 16, 1), 256>>>(x, emb_w1, bhi, blo, DHID, DIN, NTOK,
                                     emb_b1, 1, 0, 0, 0, 0, 0, 0);
    TG(OFF_EMBW2, bhi, blo, embed, ahi, alo, NTOK, DMODEL, DHID, 0, 0, 0, 0, 0, 0, 0);
    TG(OFF_EMBWO, ahi, alo, out + (size_t)NTOK * DOUT, 0, 0, NTOK, DOUT, DMODEL,
       0, 0, 0, 0, 0, 0, 0);

    router_all<<<dim3(NTOK / 8, NLAYER), 256>>>(embed, f0_router, f_router, seq,
                                                gtok, lists, cnt, imp);

    for (int l = 0; l < NLAYER; l++) {
        int* lst = lists + (size_t)l * NEXP * NTOK;
        float* gt = gtok + (size_t)l * NTOK;
        int* ct = cnt + l * 4;

        if (l == 1) cudaStreamWaitEvent(0, evJ, 0);   // join side-stream weight splits

        if (l == 0) {
            gemm128<<<dim3(8, 16, NEXP), 256>>>(x, f0_w1, bhi, blo, DHID, DIN, NTOK,
                                                f0_b1, 1, lst, lst, ct,
                                                DIN * DHID, DHID, NTOK);
            TG(OFF_F0W2, bhi, blo, p, 0, 0, NTOK, DMODEL, DHID, 0, 0, lst, lst,
               gt, 0, ct, NEXP, DMODEL * DHID, 0, NTOK);
        } else {
            TG(OFF_FW1 + (unsigned)(l - 1) * 4u * DMODEL * DHID, ahi, alo,
               0, bhi, blo, NTOK, DHID, DMODEL,
               f_b1 + (size_t)(l - 1) * NEXP * DHID, 1, lst, lst, 0, 0, ct,
               NEXP, DMODEL * DHID, DHID, NTOK);
            TG(OFF_FW2 + (unsigned)(l - 1) * 4u * DHID * DMODEL, bhi, blo,
               p, 0, 0, NTOK, DMODEL, DHID,
               0, 0, lst, lst, gt, 0, ct,
               NEXP, DHID * DMODEL, 0, NTOK);
        }
        const float* fbL = (l == 0) ? f0_fb : f_fb + (size_t)(l - 1) * 4 * DMODEL;
        const float* faL = (l == 0) ? f0_fa : f_fa + (size_t)(l - 1) * DMODEL;
        fsmn_kernel<<<NTOK * DMODEL / 256, 256>>>(p, fbL, faL,
                                                  (l == 0) ? (const float*)0 : cur, cur,
                                                  l == 3 ? 1 : 0);

        if (l == 3 || l == 7) {
            int bi = l / 4;
            // fused QKV: z=0->q rows (identity), z=1->k rows, z=2->v rows (section offsets in maps)
            TG(OFF_QKV + (unsigned)bi * 3u * MAT_SZ, ahi, alo, 0, qkvh, qkvl,
               NTOK, DMODEL, DMODEL, 0, 0, 0, maps, 0, 0, 0, 3, MAT_SZ, 0, NTOK);
            memrows_kernel<<<BATCH * MMEM * DMODEL / 256, 256>>>(
                mk + (size_t)bi * MMEM * DMODEL, mv + (size_t)bi * MMEM * DMODEL);
            attn_mma<<<dim3(TLEN / 128, NHEAD, BATCH), 256, ATTN_SMEM>>>(
                qkvh, qkvl,
                qkvh + (size_t)NTOK * DMODEL, qkvl + (size_t)NTOK * DMODEL,
                qkvh + (size_t)(NTOK + BSF) * DMODEL, qkvl + (size_t)(NTOK + BSF) * DMODEL,
                seq, bhi, blo);
            TG(OFF_WO + (unsigned)bi * MAT_SZ, bhi, blo, tmp, 0, 0,
               NTOK, DMODEL, DMODEL, 0, 0, 0, 0, 0, cur, 0);
            ln_kernel<<<NTOK, 128>>>(tmp, cur, lng + bi * DMODEL, lnb + bi * DMODEL);
        }
    }

    TG(OFF_OUTW, ahi, alo, out, 0, 0, NTOK, DOUT, DMODEL, out_b, 0, 0, 0, 0, 0, 0);
    aux_kernel<<<1, 1>>>(out + 2 * (size_t)NTOK * DOUT);
}

// round 9
// speedup vs baseline: 4.9005x; 1.0862x over previous
#include <cuda_runtime.h>
#include <cuda_bf16.h>
#include <math.h>
#include <stdint.h>

// ---------------- problem constants ----------------
#define BATCH 4
#define TLEN  512
#define NTOK  (BATCH*TLEN)
#define DIN   80
#define KPAD  96
#define DOUT  4096
#define DMODEL 512
#define DHID  1024
#define NEXP  4
#define NLAYER 8
#define NHEAD 8
#define DH    64
#define MMEM  64
#define SFULL (TLEN+MMEM)
#define BSF   (BATCH*SFULL)
#define QKV_ROWS (NTOK + 2*BSF)

// ---------------- device scratch ----------------
__device__ float g_embed[NTOK*DMODEL];
__device__ float g_cur[NTOK*DMODEL];
__device__ float g_p[NTOK*DMODEL];
__device__ float g_tmp[NTOK*DMODEL];
__device__ float g_gtok[NLAYER*NTOK];
__device__ float g_imp[NLAYER*NEXP];
__device__ int   g_cnt[NLAYER*NEXP];
__device__ int   g_lists[NLAYER*NEXP*NTOK];
__device__ int   g_maps[3*NTOK];

#define WPOOL (40u*1024u*1024u)
__device__ __nv_bfloat16 g_whi[WPOOL];
__device__ __nv_bfloat16 g_wlo[WPOOL];
__device__ __nv_bfloat16 g_ahi[NTOK*DMODEL];
__device__ __nv_bfloat16 g_alo[NTOK*DMODEL];
__device__ __nv_bfloat16 g_bhi[NTOK*DHID];
__device__ __nv_bfloat16 g_blo[NTOK*DHID];
__device__ __nv_bfloat16 g_ehi[NTOK*DMODEL];
__device__ __nv_bfloat16 g_elo[NTOK*DMODEL];
__device__ __nv_bfloat16 g_xhi[NTOK*KPAD];
__device__ __nv_bfloat16 g_xlo[NTOK*KPAD];
__device__ __nv_bfloat16 g_qkvh[QKV_ROWS*DMODEL];
__device__ __nv_bfloat16 g_qkvl[QKV_ROWS*DMODEL];

#define OFF_EMBW2 0u
#define OFF_EMBWO (OFF_EMBW2 + 512u*1024u)
#define OFF_F0W2  (OFF_EMBWO + 4096u*512u)
#define OFF_FW1   (OFF_F0W2 + 4u*512u*1024u)
#define OFF_FW2   (OFF_FW1 + 28u*1024u*512u)
#define OFF_QKV   (OFF_FW2 + 28u*512u*1024u)
#define OFF_WO    (OFF_QKV + 6u*512u*512u)
#define OFF_OUTW  (OFF_WO + 2u*512u*512u)
#define OFF_EMBW1 (OFF_OUTW + 512u*4096u)
#define OFF_F0W1  (OFF_EMBW1 + 96u*1024u)
#define MAT_SZ    (512u*512u)

// ---------------- helpers ----------------
__device__ __forceinline__ uint32_t s2u(const void* p) {
    uint32_t a;
    asm("{ .reg .u64 t; cvta.to.shared.u64 t, %1; cvt.u32.u64 %0, t; }" : "=r"(a) : "l"(p));
    return a;
}
__device__ __forceinline__ void ldsm4(uint32_t* r, uint32_t addr) {
    asm volatile("ldmatrix.sync.aligned.m8n8.x4.shared.b16 {%0,%1,%2,%3}, [%4];"
        : "=r"(r[0]), "=r"(r[1]), "=r"(r[2]), "=r"(r[3]) : "r"(addr));
}
__device__ __forceinline__ void ldsm2(uint32_t* r, uint32_t addr) {
    asm volatile("ldmatrix.sync.aligned.m8n8.x2.shared.b16 {%0,%1}, [%2];"
        : "=r"(r[0]), "=r"(r[1]) : "r"(addr));
}
__device__ __forceinline__ void ldsm2t(uint32_t* r, uint32_t addr) {
    asm volatile("ldmatrix.sync.aligned.m8n8.x2.trans.shared.b16 {%0,%1}, [%2];"
        : "=r"(r[0]), "=r"(r[1]) : "r"(addr));
}
__device__ __forceinline__ void mma_bf16(float* c, const uint32_t* a, const uint32_t* b) {
    asm volatile("mma.sync.aligned.m16n8k16.row.col.f32.bf16.bf16.f32 "
        "{%0,%1,%2,%3}, {%4,%5,%6,%7}, {%8,%9}, {%0,%1,%2,%3};"
        : "+f"(c[0]), "+f"(c[1]), "+f"(c[2]), "+f"(c[3])
        : "r"(a[0]), "r"(a[1]), "r"(a[2]), "r"(a[3]), "r"(b[0]), "r"(b[1]));
}
__device__ __forceinline__ uint32_t packbf(float a, float b) {
    __nv_bfloat162 h = __floats2bfloat162_rn(a, b);
    return *(uint32_t*)&h;
}
__device__ __forceinline__ float bfres(float x) {
    return x - __bfloat162float(__float2bfloat16(x));
}
#define CPA(dst, src, sz) asm volatile("cp.async.ca.shared.global [%0], [%1], 16, %2;" \
    :: "r"(dst), "l"(src), "r"(sz))
#define CPC() asm volatile("cp.async.commit_group;" ::: "memory")
#define CPW() asm volatile("cp.async.wait_group 0;" ::: "memory")

// ---------------- init ----------------
__global__ void init_kernel() {
    int t = threadIdx.x;
    if (t < NLAYER*NEXP) { g_cnt[t] = 0; g_imp[t] = 0.f; }
    for (int i = t; i < NTOK; i += blockDim.x) {
        int kv = (i >> 9) * SFULL + (i & 511);
        g_maps[i] = i;
        g_maps[NTOK + i] = NTOK + kv;
        g_maps[2 * NTOK + i] = NTOK + BSF + kv;
    }
}

// ---------------- streaming weight split ----------------
__global__ void wsplit(const float* __restrict__ W, __nv_bfloat16* __restrict__ hi,
                       __nv_bfloat16* __restrict__ lo, int n4)
{
    int i = blockIdx.x * 256 + threadIdx.x;
    if (i >= n4) return;
    float4 v = ((const float4*)W)[i];
    __nv_bfloat162 h01 = __floats2bfloat162_rn(v.x, v.y);
    __nv_bfloat162 h23 = __floats2bfloat162_rn(v.z, v.w);
    __nv_bfloat162 l01 = __floats2bfloat162_rn(v.x - __bfloat162float(h01.x),
                                               v.y - __bfloat162float(h01.y));
    __nv_bfloat162 l23 = __floats2bfloat162_rn(v.z - __bfloat162float(h23.x),
                                               v.w - __bfloat162float(h23.y));
    uint2 hw, lw;
    hw.x = *(uint32_t*)&h01; hw.y = *(uint32_t*)&h23;
    lw.x = *(uint32_t*)&l01; lw.y = *(uint32_t*)&l23;
    *(uint2*)(hi + (size_t)i * 4) = hw;
    *(uint2*)(lo + (size_t)i * 4) = lw;
}

// ---------------- weight split with K pad 80->96 (input [Z,80,N], output [Z,96,N]) ----------------
__global__ void wsplit_pad(const float* __restrict__ W, __nv_bfloat16* __restrict__ hi,
                           __nv_bfloat16* __restrict__ lo, int N, int total4)
{
    int i = blockIdx.x * 256 + threadIdx.x;
    if (i >= total4) return;
    int elem = i * 4;
    int z = elem / (KPAD * N);
    int rem = elem - z * KPAD * N;
    int k = rem / N, n = rem - k * N;
    float4 v = make_float4(0.f, 0.f, 0.f, 0.f);
    if (k < DIN) v = *(const float4*)(W + (size_t)z * DIN * N + (size_t)k * N + n);
    __nv_bfloat162 h01 = __floats2bfloat162_rn(v.x, v.y);
    __nv_bfloat162 h23 = __floats2bfloat162_rn(v.z, v.w);
    __nv_bfloat162 l01 = __floats2bfloat162_rn(v.x - __bfloat162float(h01.x),
                                               v.y - __bfloat162float(h01.y));
    __nv_bfloat162 l23 = __floats2bfloat162_rn(v.z - __bfloat162float(h23.x),
                                               v.w - __bfloat162float(h23.y));
    uint2 hw, lw;
    hw.x = *(uint32_t*)&h01; hw.y = *(uint32_t*)&h23;
    lw.x = *(uint32_t*)&l01; lw.y = *(uint32_t*)&l23;
    *(uint2*)(hi + (size_t)elem) = hw;
    *(uint2*)(lo + (size_t)elem) = lw;
}

// ---------------- x split with pad 80->96 ----------------
__global__ void xsplit(const float* __restrict__ x)
{
    int i = blockIdx.x * 256 + threadIdx.x;
    if (i >= NTOK * KPAD) return;
    int row = i / KPAD, c = i - row * KPAD;
    float v = (c < DIN) ? x[(size_t)row * DIN + c] : 0.f;
    __nv_bfloat16 h = __float2bfloat16(v);
    g_xhi[i] = h;
    g_xlo[i] = __float2bfloat16(v - __bfloat162float(h));
}

// ---------------- bf16 TC GEMM (A [M,K] row-major, B [K,N] k-major, cp.async 2-stage) ----------------
#define KC 32
#define APITCHB 80
#define BPITCHB 272
#define A_TILE (128*APITCHB)
#define B_TILE (KC*BPITCHB)
#define STG (2*A_TILE + 2*B_TILE)
#define TG_SMEM (2*STG)
__global__ __launch_bounds__(256, 2)
void tgemm(const __nv_bfloat16* __restrict__ Ahi, const __nv_bfloat16* __restrict__ Alo,
           const __nv_bfloat16* __restrict__ Bhi, const __nv_bfloat16* __restrict__ Blo,
           float* __restrict__ C,
           __nv_bfloat16* __restrict__ Chi, __nv_bfloat16* __restrict__ Clo,
           int N, int K, int Mstatic,
           const float* __restrict__ bias, int doRelu,
           const int* __restrict__ gatherA, const int* __restrict__ scatterC,
           const float* __restrict__ rowScale, const float* __restrict__ residual,
           const int* __restrict__ Mdev, int strideB, int strideBias, int strideList)
{
    extern __shared__ char smem[];
    int e = blockIdx.z;
    const __nv_bfloat16* Bhz = Bhi + (size_t)e * strideB;
    const __nv_bfloat16* Blz = Blo + (size_t)e * strideB;
    const float* biasz = bias ? bias + (size_t)e * strideBias : (const float*)0;
    const int* gA = gatherA ? gatherA + (size_t)e * strideList : (const int*)0;
    const int* sC = scatterC ? scatterC + (size_t)e * strideList : (const int*)0;
    int Ml = Mdev ? Mdev[e] : Mstatic;
    int row0 = blockIdx.y * 128;
    if (row0 >= Ml) return;
    int col0 = blockIdx.x * 128;
    int tid = threadIdx.x, wid = tid >> 5, lane = tid & 31;
    uint32_t sb = s2u(smem);

    int arow[2], lr[2], lu[2];
    #pragma unroll
    for (int i = 0; i < 2; i++) {
        int unit = tid + i * 256;
        lr[i] = unit >> 2;
        lu[i] = unit & 3;
        int gr = row0 + lr[i];
        arow[i] = (gr < Ml) ? (gA ? gA[gr] : gr) : -1;
    }

    auto issue = [&](int c, int stage) {
        int k0 = c * KC;
        uint32_t base = sb + stage * STG;
        #pragma unroll
        for (int i = 0; i < 2; i++) {
            uint32_t offA = (uint32_t)(lr[i] * APITCHB + lu[i] * 16);
            int ar = arow[i] >= 0 ? arow[i] : 0;
            uint32_t asz = arow[i] >= 0 ? 16u : 0u;
            CPA(base + offA, (const char*)(Ahi + (size_t)ar * K + k0 + lu[i] * 8), asz);
            CPA(base + A_TILE + offA, (const char*)(Alo + (size_t)ar * K + k0 + lu[i] * 8), asz);
            int unit = tid + i * 256;
            int bk = unit >> 4, bc16 = unit & 15;
            uint32_t offB = (uint32_t)(bk * BPITCHB + bc16 * 16);
            const char* bh = (const char*)(Bhz + (size_t)(k0 + bk) * N + col0 + bc16 * 8);
            const char* bl = (const char*)(Blz + (size_t)(k0 + bk) * N + col0 + bc16 * 8);
            CPA(base + 2u * A_TILE + offB, bh, 16u);
            CPA(base + 2u * A_TILE + B_TILE + offB, bl, 16u);
        }
    };

    float acc[4][4][4] = {};
    int wm = wid >> 2, wn = wid & 3;
    int m_base = wm * 64, n_base = wn * 32;
    int l8 = lane & 7, mat = lane >> 3, bsel = (lane >> 3) & 1;

    int nc = K / KC;
    issue(0, 0); CPC();

    for (int c = 0; c < nc; c++) {
        CPW();
        __syncthreads();
        if (c + 1 < nc) { issue(c + 1, (c + 1) & 1); CPC(); }

        uint32_t base = sb + (c & 1) * STG;
        uint32_t ahB = base, alB = base + A_TILE;
        uint32_t bhB = base + 2u * A_TILE, blB = base + 2u * A_TILE + B_TILE;
        #pragma unroll
        for (int ks = 0; ks < 2; ks++) {
            int kb = ks * 16;
            uint32_t aoff = (uint32_t)(kb + (mat >> 1) * 8) * 2;
            uint32_t af[4][4], bfh[4][2], bfl[4][2];
            #pragma unroll
            for (int mf = 0; mf < 4; mf++)
                ldsm4(af[mf], ahB + (uint32_t)(m_base + mf * 16 + (mat & 1) * 8 + l8) * APITCHB + aoff);
            #pragma unroll
            for (int nf = 0; nf < 4; nf++)
                ldsm2t(bfh[nf], bhB + (uint32_t)(kb + bsel * 8 + l8) * BPITCHB
                                    + (uint32_t)(n_base + nf * 8) * 2);
            #pragma unroll
            for (int mf = 0; mf < 4; mf++)
                #pragma unroll
                for (int nf = 0; nf < 4; nf++)
                    mma_bf16(acc[mf][nf], af[mf], bfh[nf]);
            #pragma unroll
            for (int nf = 0; nf < 4; nf++)
                ldsm2t(bfl[nf], blB + (uint32_t)(kb + bsel * 8 + l8) * BPITCHB
                                    + (uint32_t)(n_base + nf * 8) * 2);
            #pragma unroll
            for (int mf = 0; mf < 4; mf++)
                #pragma unroll
                for (int nf = 0; nf < 4; nf++)
                    mma_bf16(acc[mf][nf], af[mf], bfl[nf]);
            #pragma unroll
            for (int mf = 0; mf < 4; mf++)
                ldsm4(af[mf], alB + (uint32_t)(m_base + mf * 16 + (mat & 1) * 8 + l8) * APITCHB + aoff);
            #pragma unroll
            for (int mf = 0; mf < 4; mf++)
                #pragma unroll
                for (int nf = 0; nf < 4; nf++)
                    mma_bf16(acc[mf][nf], af[mf], bfh[nf]);
        }
    }

    int g = lane >> 2, t2 = (lane & 3) * 2;
    #pragma unroll
    for (int mf = 0; mf < 4; mf++) {
        #pragma unroll
        for (int half = 0; half < 2; half++) {
            int r = row0 + m_base + mf * 16 + g + half * 8;
            if (r >= Ml) continue;
            int orow = sC ? sC[r] : r;
            float sc = rowScale ? rowScale[orow] : 1.f;
            size_t rb = (size_t)orow * N;
            #pragma unroll
            for (int nf = 0; nf < 4; nf++) {
                int cc = col0 + n_base + nf * 8 + t2;
                float v0 = acc[mf][nf][half * 2 + 0] * sc;
                float v1 = acc[mf][nf][half * 2 + 1] * sc;
                if (biasz) { v0 += biasz[cc]; v1 += biasz[cc + 1]; }
                if (residual) { v0 += residual[rb + cc]; v1 += residual[rb + cc + 1]; }
                if (doRelu) { v0 = fmaxf(v0, 0.f); v1 = fmaxf(v1, 0.f); }
                if (C) *(float2*)(C + rb + cc) = make_float2(v0, v1);
                if (Chi) {
                    *(uint32_t*)(Chi + rb + cc) = packbf(v0, v1);
                    *(uint32_t*)(Clo + rb + cc) = packbf(bfres(v0), bfres(v1));
                }
            }
        }
    }
}

// ---------------- fused router (all layers) ----------------
__global__ void router_all(const float* __restrict__ embed, const float* __restrict__ f0r,
                           const float* __restrict__ fr, const int* __restrict__ seqlen,
                           float* __restrict__ gtokA, int* __restrict__ listsA,
                           int* __restrict__ cntA, float* __restrict__ impA)
{
    int l = blockIdx.y;
    const float* R = (l == 0) ? f0r : fr + (size_t)(l - 1) * DMODEL * NEXP;
    float* gtok = gtokA + (size_t)l * NTOK;
    int* lists = listsA + (size_t)l * NEXP * NTOK;
    int* cnt = cntA + l * NEXP;
    float* imp = impA + l * NEXP;

    int gw = (blockIdx.x * blockDim.x + threadIdx.x) >> 5;
    int lane = threadIdx.x & 31;
    if (gw >= NTOK) return;
    const float* xr = embed + (size_t)gw * DMODEL;
    float l0 = 0, l1 = 0, l2 = 0, l3 = 0;
    for (int d = lane; d < DMODEL; d += 32) {
        float v = xr[d];
        const float* rr = R + d * 4;
        l0 += v * rr[0]; l1 += v * rr[1]; l2 += v * rr[2]; l3 += v * rr[3];
    }
    for (int off = 16; off; off >>= 1) {
        l0 += __shfl_xor_sync(0xffffffffu, l0, off);
        l1 += __shfl_xor_sync(0xffffffffu, l1, off);
        l2 += __shfl_xor_sync(0xffffffffu, l2, off);
        l3 += __shfl_xor_sync(0xffffffffu, l3, off);
    }
    if (lane == 0) {
        float mx = fmaxf(fmaxf(l0, l1), fmaxf(l2, l3));
        float e0 = __expf(l0 - mx), e1 = __expf(l1 - mx);
        float e2 = __expf(l2 - mx), e3 = __expf(l3 - mx);
        float inv = 1.f / (e0 + e1 + e2 + e3);
        float s0 = e0 * inv, s1 = e1 * inv, s2 = e2 * inv, s3 = e3 * inv;
        int em = 0; float gm = s0;
        if (s1 > gm) { gm = s1; em = 1; }
        if (s2 > gm) { gm = s2; em = 2; }
        if (s3 > gm) { gm = s3; em = 3; }
        int b = gw >> 9, t = gw & 511;
        if (t < seqlen[b]) {
            atomicAdd(&imp[0], s0); atomicAdd(&imp[1], s1);
            atomicAdd(&imp[2], s2); atomicAdd(&imp[3], s3);
        }
        gtok[gw] = gm;
        int slot = atomicAdd(&cnt[em], 1);
        lists[em * NTOK + slot] = gw;
    }
}

// ---------------- FSMN (+optional PE, emits split(cur)) ----------------
__global__ void fsmn_kernel(const float* __restrict__ P, const float* __restrict__ fb,
                            const float* __restrict__ fa, const float* __restrict__ skipin,
                            float* __restrict__ outp, int doPE)
{
    int idx = blockIdx.x * 256 + threadIdx.x;
    if (idx >= NTOK * DMODEL) return;
    int d = idx & 511;
    int t = (idx >> 9) & 511;
    float v = P[idx];
    #pragma unroll
    for (int k = 0; k < 4; k++) {
        int off = (k + 1) * 2;
        if (t - off >= 0) v += fb[k * DMODEL + d] * P[idx - off * DMODEL];
    }
    if (t + 1 < TLEN) v += fa[d] * P[idx + DMODEL];
    if (skipin) v += skipin[idx];
    if (doPE) {
        int i = d >> 1;
        float div = __expf(-(float)(2 * i) * (9.2103403719761836f / 512.f));
        float a = (float)t * div;
        v += (d & 1) ? cosf(a) : sinf(a);
    }
    outp[idx] = v;
    __nv_bfloat16 h = __float2bfloat16(v);
    g_ahi[idx] = h;
    g_alo[idx] = __float2bfloat16(v - __bfloat162float(h));
}

// ---------------- memory KV rows ----------------
__global__ void memrows_kernel(const float* __restrict__ mk, const float* __restrict__ mv)
{
    int idx = blockIdx.x * 256 + threadIdx.x;
    if (idx >= BATCH * MMEM * DMODEL) return;
    int d = idx & 511;
    int r = idx >> 9;
    int m = r & 63;
    int b = r >> 6;
    size_t krow = (size_t)(NTOK + b * SFULL + TLEN + m);
    size_t vrow = krow + BSF;
    float kv = mk[m * DMODEL + d];
    float vv = mv[m * DMODEL + d];
    __nv_bfloat16 hk = __float2bfloat16(kv);
    g_qkvh[krow * DMODEL + d] = hk;
    g_qkvl[krow * DMODEL + d] = __float2bfloat16(kv - __bfloat162float(hk));
    __nv_bfloat16 hv = __float2bfloat16(vv);
    g_qkvh[vrow * DMODEL + d] = hv;
    g_qkvl[vrow * DMODEL + d] = __float2bfloat16(vv - __bfloat162float(hv));
}

// ---------------- tensor-core flash attention ----------------
#define AT_PITCH 72
#define AT_QH 0
#define AT_QL (128*AT_PITCH)
#define AT_KH (2*128*AT_PITCH)
#define AT_KL (AT_KH + 64*AT_PITCH)
#define AT_VH (AT_KL + 64*AT_PITCH)
#define AT_VL (AT_VH + 64*AT_PITCH)
#define ATTN_SMEM ((AT_VL + 64*AT_PITCH) * 2)
__global__ __launch_bounds__(256, 1)
void attn_mma(const __nv_bfloat16* __restrict__ qh, const __nv_bfloat16* __restrict__ ql,
              const __nv_bfloat16* __restrict__ kh, const __nv_bfloat16* __restrict__ kl,
              const __nv_bfloat16* __restrict__ vh, const __nv_bfloat16* __restrict__ vl,
              const int* __restrict__ seqlen,
              __nv_bfloat16* __restrict__ Ohi, __nv_bfloat16* __restrict__ Olo)
{
    extern __shared__ __nv_bfloat16 sb[];
    int q0 = blockIdx.x * 128, h = blockIdx.y, b = blockIdx.z;
    int tid = threadIdx.x, wid = tid >> 5, lane = tid & 31;
    int slen = seqlen[b];
    int l8 = lane & 7, mat = lane >> 3, g = lane >> 2, t2 = (lane & 3) * 2;
    int mrow = wid * 16;

    #pragma unroll
    for (int i = 0; i < 4; i++) {
        int u = i * 256 + tid;
        int r = u >> 3, c8 = u & 7;
        size_t src = ((size_t)(b * TLEN + q0 + r)) * DMODEL + h * DH + c8 * 8;
        *(uint4*)&sb[AT_QH + r * AT_PITCH + c8 * 8] = *(const uint4*)(qh + src);
        *(uint4*)&sb[AT_QL + r * AT_PITCH + c8 * 8] = *(const uint4*)(ql + src);
    }

    uint32_t QhB = s2u(sb + AT_QH), QlB = s2u(sb + AT_QL);
    uint32_t KhB = s2u(sb + AT_KH), KlB = s2u(sb + AT_KL);
    uint32_t VhB = s2u(sb + AT_VH), VlB = s2u(sb + AT_VL);

    float o[8][4] = {};
    float m0 = -1e30f, m1 = -1e30f, l0 = 0.f, l1 = 0.f;

    for (int s0 = 0; s0 < SFULL; s0 += 64) {
        __syncthreads();
        #pragma unroll
        for (int i = 0; i < 2; i++) {
            int u = i * 256 + tid;
            int r = u >> 3, c8 = u & 7;
            size_t src = ((size_t)(b * SFULL + s0 + r)) * DMODEL + h * DH + c8 * 8;
            uint32_t dst = r * AT_PITCH + c8 * 8;
            *(uint4*)&sb[AT_KH + dst] = *(const uint4*)(kh + src);
            *(uint4*)&sb[AT_KL + dst] = *(const uint4*)(kl + src);
            *(uint4*)&sb[AT_VH + dst] = *(const uint4*)(vh + src);
            *(uint4*)&sb[AT_VL + dst] = *(const uint4*)(vl + src);
        }
        __syncthreads();

        float sc[8][4] = {};
        #pragma unroll
        for (int pass = 0; pass < 3; pass++) {
            uint32_t aB = (pass == 2) ? QlB : QhB;
            uint32_t bB = (pass == 1) ? KlB : KhB;
            #pragma unroll
            for (int kc = 0; kc < 4; kc++) {
                uint32_t af[4];
                ldsm4(af, aB + (uint32_t)((mrow + (mat & 1) * 8 + l8) * AT_PITCH
                                          + kc * 16 + (mat >> 1) * 8) * 2);
                #pragma unroll
                for (int nf = 0; nf < 8; nf++) {
                    uint32_t bf2[2];
                    ldsm2(bf2, bB + (uint32_t)((nf * 8 + l8) * AT_PITCH
                                               + kc * 16 + ((lane >> 3) & 1) * 8) * 2);
                    mma_bf16(sc[nf], af, bf2);
                }
            }
        }

        float rm0 = -1e30f, rm1 = -1e30f;
        #pragma unroll
        for (int nf = 0; nf < 8; nf++) {
            #pragma unroll
            for (int j = 0; j < 4; j++) {
                int sg = s0 + nf * 8 + t2 + (j & 1);
                float v = sc[nf][j] * 0.125f;
                sc[nf][j] = (sg >= slen && sg < TLEN) ? -1e9f : v;
            }
            rm0 = fmaxf(rm0, fmaxf(sc[nf][0], sc[nf][1]));
            rm1 = fmaxf(rm1, fmaxf(sc[nf][2], sc[nf][3]));
        }
        rm0 = fmaxf(rm0, __shfl_xor_sync(0xffffffffu, rm0, 1));
        rm0 = fmaxf(rm0, __shfl_xor_sync(0xffffffffu, rm0, 2));
        rm1 = fmaxf(rm1, __shfl_xor_sync(0xffffffffu, rm1, 1));
        rm1 = fmaxf(rm1, __shfl_xor_sync(0xffffffffu, rm1, 2));
        float mn0 = fmaxf(m0, rm0), mn1 = fmaxf(m1, rm1);
        float e0 = __expf(m0 - mn0), e1 = __expf(m1 - mn1);
        float rs0 = 0.f, rs1 = 0.f;
        #pragma unroll
        for (int nf = 0; nf < 8; nf++) {
            sc[nf][0] = __expf(sc[nf][0] - mn0); rs0 += sc[nf][0];
            sc[nf][1] = __expf(sc[nf][1] - mn0); rs0 += sc[nf][1];
            sc[nf][2] = __expf(sc[nf][2] - mn1); rs1 += sc[nf][2];
            sc[nf][3] = __expf(sc[nf][3] - mn1); rs1 += sc[nf][3];
        }
        rs0 += __shfl_xor_sync(0xffffffffu, rs0, 1);
        rs0 += __shfl_xor_sync(0xffffffffu, rs0, 2);
        rs1 += __shfl_xor_sync(0xffffffffu, rs1, 1);
        rs1 += __shfl_xor_sync(0xffffffffu, rs1, 2);
        l0 = l0 * e0 + rs0; l1 = l1 * e1 + rs1;
        m0 = mn0; m1 = mn1;
        #pragma unroll
        for (int nf = 0; nf < 8; nf++) {
            o[nf][0] *= e0; o[nf][1] *= e0; o[nf][2] *= e1; o[nf][3] *= e1;
        }

        uint32_t phi[4][4], plo[4][4];
        #pragma unroll
        for (int kc = 0; kc < 4; kc++) {
            float* A = sc[2 * kc];
            float* B = sc[2 * kc + 1];
            phi[kc][0] = packbf(A[0], A[1]); phi[kc][1] = packbf(A[2], A[3]);
            phi[kc][2] = packbf(B[0], B[1]); phi[kc][3] = packbf(B[2], B[3]);
            plo[kc][0] = packbf(bfres(A[0]), bfres(A[1]));
            plo[kc][1] = packbf(bfres(A[2]), bfres(A[3]));
            plo[kc][2] = packbf(bfres(B[0]), bfres(B[1]));
            plo[kc][3] = packbf(bfres(B[2]), bfres(B[3]));
        }

        #pragma unroll
        for (int pass = 0; pass < 3; pass++) {
            uint32_t vB = (pass == 1) ? VlB : VhB;
            #pragma unroll
            for (int kc = 0; kc < 4; kc++) {
                const uint32_t* pf = (pass == 2) ? plo[kc] : phi[kc];
                #pragma unroll
                for (int nf = 0; nf < 8; nf++) {
                    uint32_t bf2[2];
                    ldsm2t(bf2, vB + (uint32_t)((kc * 16 + ((lane >> 3) & 1) * 8 + l8) * AT_PITCH
                                                + nf * 8) * 2);
                    mma_bf16(o[nf], pf, bf2);
                }
            }
        }
    }

    float inv0 = 1.f / l0, inv1 = 1.f / l1;
    int r0 = q0 + mrow + g;
    #pragma unroll
    for (int nf = 0; nf < 8; nf++) {
        int cc = h * DH + nf * 8 + t2;
        size_t i0 = ((size_t)(b * TLEN + r0)) * DMODEL + cc;
        size_t i1 = ((size_t)(b * TLEN + r0 + 8)) * DMODEL + cc;
        float v0 = o[nf][0] * inv0, v1 = o[nf][1] * inv0;
        float w0 = o[nf][2] * inv1, w1 = o[nf][3] * inv1;
        *(uint32_t*)(Ohi + i0) = packbf(v0, v1);
        *(uint32_t*)(Olo + i0) = packbf(bfres(v0), bfres(v1));
        *(uint32_t*)(Ohi + i1) = packbf(w0, w1);
        *(uint32_t*)(Olo + i1) = packbf(bfres(w0), bfres(w1));
    }
}

// ---------------- layernorm (emits split(cur)) ----------------
__global__ void ln_kernel(const float* __restrict__ X, float* __restrict__ Y,
                          const float* __restrict__ gw, const float* __restrict__ bw)
{
    __shared__ float red[128];
    int row = blockIdx.x, tid = threadIdx.x;
    const float* xr = X + (size_t)row * DMODEL;
    float v[4]; float s = 0.f;
    #pragma unroll
    for (int i = 0; i < 4; i++) { v[i] = xr[tid + 128 * i]; s += v[i]; }
    red[tid] = s; __syncthreads();
    for (int off = 64; off > 0; off >>= 1) {
        if (tid < off) red[tid] += red[tid + off];
        __syncthreads();
    }
    float mu = red[0] * (1.f / 512.f);
    __syncthreads();
    float s2 = 0.f;
    #pragma unroll
    for (int i = 0; i < 4; i++) { float d = v[i] - mu; s2 += d * d; }
    red[tid] = s2; __syncthreads();
    for (int off = 64; off > 0; off >>= 1) {
        if (tid < off) red[tid] += red[tid + off];
        __syncthreads();
    }
    float inv = rsqrtf(red[0] * (1.f / 512.f) + 1e-5f);
    #pragma unroll
    for (int i = 0; i < 4; i++) {
        int c = tid + 128 * i;
        float y = (v[i] - mu) * inv * gw[c] + bw[c];
        size_t idx = (size_t)row * DMODEL + c;
        Y[idx] = y;
        __nv_bfloat16 h = __float2bfloat16(y);
        g_ahi[idx] = h;
        g_alo[idx] = __float2bfloat16(y - __bfloat162float(h));
    }
}

// ---------------- aux ----------------
__global__ void aux_kernel(float* __restrict__ dst)
{
    float tot = 0.f;
    for (int l = 0; l < NLAYER; l++) {
        float m = 0.f;
        for (int e = 0; e < NEXP; e++) m += g_imp[l * 4 + e];
        m *= 0.25f;
        float var = 0.f;
        for (int e = 0; e < NEXP; e++) { float d = g_imp[l * 4 + e] - m; var += d * d; }
        var *= 0.25f;
        tot += var / (m * m + 1e-9f);
    }
    dst[0] = tot;
}

// ---------------- launcher ----------------
extern "C" void kernel_launch(void* const* d_in, const int* in_sizes, int n_in,
                              void* d_out, int out_size)
{
    const float* x         = (const float*)d_in[0];
    const int*   seq       = (const int*)  d_in[1];
    const float* emb_w1    = (const float*)d_in[2];
    const float* emb_b1    = (const float*)d_in[3];
    const float* emb_w2    = (const float*)d_in[4];
    const float* emb_wo    = (const float*)d_in[5];
    const float* f0_w1     = (const float*)d_in[6];
    const float* f0_b1     = (const float*)d_in[7];
    const float* f0_w2     = (const float*)d_in[8];
    const float* f0_router = (const float*)d_in[9];
    const float* f0_fb     = (const float*)d_in[10];
    const float* f0_fa     = (const float*)d_in[11];
    const float* f_w1      = (const float*)d_in[12];
    const float* f_b1      = (const float*)d_in[13];
    const float* f_w2      = (const float*)d_in[14];
    const float* f_router  = (const float*)d_in[15];
    const float* f_fb      = (const float*)d_in[16];
    const float* f_fa      = (const float*)d_in[17];
    const float* wq        = (const float*)d_in[18];
    const float* wk        = (const float*)d_in[19];
    const float* wv        = (const float*)d_in[20];
    const float* wvo       = (const float*)d_in[21];
    const float* mk        = (const float*)d_in[22];
    const float* mv        = (const float*)d_in[23];
    const float* lng       = (const float*)d_in[24];
    const float* lnb       = (const float*)d_in[25];
    const float* out_w     = (const float*)d_in[26];
    const float* out_b     = (const float*)d_in[27];
    float* out = (float*)d_out;

    float *embed, *cur, *p, *tmp, *gtok, *imp;
    int *cnt, *lists, *maps;
    __nv_bfloat16 *whi, *wlo, *ahi, *alo, *bhi, *blo, *ehi, *elo, *xhi, *xlo, *qkvh, *qkvl;
    cudaGetSymbolAddress((void**)&embed, g_embed);
    cudaGetSymbolAddress((void**)&cur,   g_cur);
    cudaGetSymbolAddress((void**)&p,     g_p);
    cudaGetSymbolAddress((void**)&tmp,   g_tmp);
    cudaGetSymbolAddress((void**)&gtok,  g_gtok);
    cudaGetSymbolAddress((void**)&imp,   g_imp);
    cudaGetSymbolAddress((void**)&cnt,   g_cnt);
    cudaGetSymbolAddress((void**)&lists, g_lists);
    cudaGetSymbolAddress((void**)&maps,  g_maps);
    cudaGetSymbolAddress((void**)&whi,   g_whi);
    cudaGetSymbolAddress((void**)&wlo,   g_wlo);
    cudaGetSymbolAddress((void**)&ahi,   g_ahi);
    cudaGetSymbolAddress((void**)&alo,   g_alo);
    cudaGetSymbolAddress((void**)&bhi,   g_bhi);
    cudaGetSymbolAddress((void**)&blo,   g_blo);
    cudaGetSymbolAddress((void**)&ehi,   g_ehi);
    cudaGetSymbolAddress((void**)&elo,   g_elo);
    cudaGetSymbolAddress((void**)&xhi,   g_xhi);
    cudaGetSymbolAddress((void**)&xlo,   g_xlo);
    cudaGetSymbolAddress((void**)&qkvh,  g_qkvh);
    cudaGetSymbolAddress((void**)&qkvl,  g_qkvl);

    cudaFuncSetAttribute(attn_mma, cudaFuncAttributeMaxDynamicSharedMemorySize, ATTN_SMEM);
    cudaFuncSetAttribute(tgemm, cudaFuncAttributeMaxDynamicSharedMemorySize, TG_SMEM);

    cudaStream_t s1;
    cudaStreamCreate(&s1);
    cudaEvent_t evF, evJ, evE0, evE1;
    cudaEventCreateWithFlags(&evF, cudaEventDisableTiming);
    cudaEventCreateWithFlags(&evJ, cudaEventDisableTiming);
    cudaEventCreateWithFlags(&evE0, cudaEventDisableTiming);
    cudaEventCreateWithFlags(&evE1, cudaEventDisableTiming);

    auto TG = [&](unsigned woff, const __nv_bfloat16* Ah, const __nv_bfloat16* Al,
                  float* C, __nv_bfloat16* Ch, __nv_bfloat16* Cl,
                  int M, int N, int K,
                  const float* bias, int relu, const int* ga, const int* sc,
                  const float* rs, const float* res, const int* Md,
                  int E = 1, int sB = 0, int sBias = 0, int sList = 0,
                  cudaStream_t st = 0) {
        dim3 grid(N / 128, (M + 127) / 128, E);
        tgemm<<<grid, 256, TG_SMEM, st>>>(Ah, Al, whi + woff, wlo + woff, C, Ch, Cl,
                                          N, K, M, bias, relu, ga, sc, rs, res, Md,
                                          sB, sBias, sList);
    };
    auto WS = [&](const float* W, unsigned off, int nelem, cudaStream_t st) {
        wsplit<<<(nelem / 4 + 255) / 256, 256, 0, st>>>(W, whi + off, wlo + off, nelem / 4);
    };

    init_kernel<<<1, 1024>>>();

    // main-stream prep (needed early)
    xsplit<<<(NTOK * KPAD + 255) / 256, 256>>>(x);
    wsplit_pad<<<(KPAD * 1024 / 4 + 255) / 256, 256>>>(emb_w1, whi + OFF_EMBW1,
                                                       wlo + OFF_EMBW1, 1024, KPAD * 1024 / 4);
    wsplit_pad<<<(NEXP * KPAD * 1024 / 4 + 255) / 256, 256>>>(f0_w1, whi + OFF_F0W1,
                                                              wlo + OFF_F0W1, 1024,
                                                              NEXP * KPAD * 1024 / 4);
    WS(emb_w2, OFF_EMBW2, 1024 * 512, 0);
    WS(f0_w2,  OFF_F0W2, 4 * 1024 * 512, 0);

    // side-stream weight splits (needed from layer 1 / attention / output)
    cudaEventRecord(evF, 0);
    cudaStreamWaitEvent(s1, evF, 0);
    WS(emb_wo, OFF_EMBWO, 512 * 4096, s1);
    WS(f_w1, OFF_FW1, 28 * 512 * 1024, s1);
    WS(f_w2, OFF_FW2, 28 * 1024 * 512, s1);
    for (int bi = 0; bi < 2; bi++) {
        WS(wq + (size_t)bi * MAT_SZ, OFF_QKV + bi * 3u * MAT_SZ + 0u * MAT_SZ, MAT_SZ, s1);
        WS(wk + (size_t)bi * MAT_SZ, OFF_QKV + bi * 3u * MAT_SZ + 1u * MAT_SZ, MAT_SZ, s1);
        WS(wv + (size_t)bi * MAT_SZ, OFF_QKV + bi * 3u * MAT_SZ + 2u * MAT_SZ, MAT_SZ, s1);
    }
    WS(wvo,   OFF_WO, 2 * 512 * 512, s1);
    WS(out_w, OFF_OUTW, 512 * 4096, s1);
    cudaEventRecord(evJ, s1);

    // embed sub-network (all tensor-core now)
    TG(OFF_EMBW1, xhi, xlo, 0, bhi, blo, NTOK, DHID, KPAD, emb_b1, 1, 0, 0, 0, 0, 0);
    TG(OFF_EMBW2, bhi, blo, embed, ehi, elo, NTOK, DMODEL, DHID, 0, 0, 0, 0, 0, 0, 0);
    cudaEventRecord(evE0, 0);

    // embed_out overlapped on side stream (reads ehi/elo + emb_wo split)
    cudaStreamWaitEvent(s1, evE0, 0);
    TG(OFF_EMBWO, ehi, elo, out + (size_t)NTOK * DOUT, 0, 0, NTOK, DOUT, DMODEL,
       0, 0, 0, 0, 0, 0, 0, 1, 0, 0, 0, s1);
    cudaEventRecord(evE1, s1);

    router_all<<<dim3(NTOK / 8, NLAYER), 256>>>(embed, f0_router, f_router, seq,
                                                gtok, lists, cnt, imp);

    for (int l = 0; l < NLAYER; l++) {
        int* lst = lists + (size_t)l * NEXP * NTOK;
        float* gt = gtok + (size_t)l * NTOK;
        int* ct = cnt + l * 4;

        if (l == 1) cudaStreamWaitEvent(0, evJ, 0);

        if (l == 0) {
            TG(OFF_F0W1, xhi, xlo, 0, bhi, blo, NTOK, DHID, KPAD,
               f0_b1, 1, lst, lst, 0, 0, ct, NEXP, KPAD * DHID, DHID, NTOK);
            TG(OFF_F0W2, bhi, blo, p, 0, 0, NTOK, DMODEL, DHID, 0, 0, lst, lst,
               gt, 0, ct, NEXP, DMODEL * DHID, 0, NTOK);
        } else {
            TG(OFF_FW1 + (unsigned)(l - 1) * 4u * DMODEL * DHID, ahi, alo,
               0, bhi, blo, NTOK, DHID, DMODEL,
               f_b1 + (size_t)(l - 1) * NEXP * DHID, 1, lst, lst, 0, 0, ct,
               NEXP, DMODEL * DHID, DHID, NTOK);
            TG(OFF_FW2 + (unsigned)(l - 1) * 4u * DHID * DMODEL, bhi, blo,
               p, 0, 0, NTOK, DMODEL, DHID,
               0, 0, lst, lst, gt, 0, ct,
               NEXP, DHID * DMODEL, 0, NTOK);
        }
        const float* fbL = (l == 0) ? f0_fb : f_fb + (size_t)(l - 1) * 4 * DMODEL;
        const float* faL = (l == 0) ? f0_fa : f_fa + (size_t)(l - 1) * DMODEL;
        fsmn_kernel<<<NTOK * DMODEL / 256, 256>>>(p, fbL, faL,
                                                  (l == 0) ? (const float*)0 : cur, cur,
                                                  l == 3 ? 1 : 0);

        if (l == 3 || l == 7) {
            int bi = l / 4;
            TG(OFF_QKV + (unsigned)bi * 3u * MAT_SZ, ahi, alo, 0, qkvh, qkvl,
               NTOK, DMODEL, DMODEL, 0, 0, 0, maps, 0, 0, 0, 3, MAT_SZ, 0, NTOK);
            memrows_kernel<<<BATCH * MMEM * DMODEL / 256, 256>>>(
                mk + (size_t)bi * MMEM * DMODEL, mv + (size_t)bi * MMEM * DMODEL);
            attn_mma<<<dim3(TLEN / 128, NHEAD, BATCH), 256, ATTN_SMEM>>>(
                qkvh, qkvl,
                qkvh + (size_t)NTOK * DMODEL, qkvl + (size_t)NTOK * DMODEL,
                qkvh + (size_t)(NTOK + BSF) * DMODEL, qkvl + (size_t)(NTOK + BSF) * DMODEL,
                seq, bhi, blo);
            TG(OFF_WO + (unsigned)bi * MAT_SZ, bhi, blo, tmp, 0, 0,
               NTOK, DMODEL, DMODEL, 0, 0, 0, 0, 0, cur, 0);
            ln_kernel<<<NTOK, 128>>>(tmp, cur, lng + bi * DMODEL, lnb + bi * DMODEL);
        }
    }

    TG(OFF_OUTW, ahi, alo, out, 0, 0, NTOK, DOUT, DMODEL, out_b, 0, 0, 0, 0, 0, 0);
    cudaStreamWaitEvent(0, evE1, 0);
    aux_kernel<<<1, 1>>>(out + 2 * (size_t)NTOK * DOUT);
}